// round 5
// baseline (speedup 1.0000x reference)
#include <cuda_runtime.h>
#include <cuda_bf16.h>
#include <cstdint>

#define Bn 32
#define Nn 577
#define Cn 768
#define Hn 12
#define Dn 64
#define Mn (Bn*Nn)          // 18464
#define QKV_N (3*Cn)        // 2304
#define BHD ((size_t)Bn*Hn*Nn*Dn)   // 14,180,352

// Scratch (__device__ globals: allocation-free rule) — all bf16 hi/lo pairs
__device__ __align__(16) __nv_bfloat16 g_qh[BHD], g_ql[BHD];
__device__ __align__(16) __nv_bfloat16 g_kh[BHD], g_kl[BHD];
__device__ __align__(16) __nv_bfloat16 g_vh[BHD], g_vl[BHD];
__device__ __align__(16) __nv_bfloat16 g_aoh[(size_t)Mn*Cn], g_aol[(size_t)Mn*Cn];

// ---------------------------------------------------------------------------
// helpers
// ---------------------------------------------------------------------------
__device__ __forceinline__ uint32_t smem_u32(const void* p){
    uint32_t a;
    asm("{ .reg .u64 t; cvta.to.shared.u64 t, %1; cvt.u32.u64 %0, t; }"
        : "=r"(a) : "l"(p));
    return a;
}
__device__ __forceinline__ void ldsm4(uint32_t (&r)[4], uint32_t a){
    asm volatile("ldmatrix.sync.aligned.m8n8.x4.shared.b16 {%0,%1,%2,%3}, [%4];"
        : "=r"(r[0]),"=r"(r[1]),"=r"(r[2]),"=r"(r[3]) : "r"(a));
}
__device__ __forceinline__ void ldsm4t(uint32_t (&r)[4], uint32_t a){
    asm volatile("ldmatrix.sync.aligned.m8n8.x4.trans.shared.b16 {%0,%1,%2,%3}, [%4];"
        : "=r"(r[0]),"=r"(r[1]),"=r"(r[2]),"=r"(r[3]) : "r"(a));
}
__device__ __forceinline__ void mma16816(float* c, const uint32_t* a,
                                         uint32_t b0, uint32_t b1){
    asm volatile("mma.sync.aligned.m16n8k16.row.col.f32.bf16.bf16.f32 "
        "{%0,%1,%2,%3}, {%4,%5,%6,%7}, {%8,%9}, {%0,%1,%2,%3};"
        : "+f"(c[0]),"+f"(c[1]),"+f"(c[2]),"+f"(c[3])
        : "r"(a[0]),"r"(a[1]),"r"(a[2]),"r"(a[3]), "r"(b0),"r"(b1));
}
__device__ __forceinline__ uint32_t packbf(float x, float y){
    __nv_bfloat162 t = __floats2bfloat162_rn(x, y);
    return *reinterpret_cast<uint32_t*>(&t);
}
// 8 fp32 -> 4 b32 hi-bf16 pairs + 4 b32 lo-bf16 pairs (hi + lo ≈ fp32)
__device__ __forceinline__ void cvt8_split(float4 a, float4 b, uint32_t* h, uint32_t* l){
    float f[8] = {a.x,a.y,a.z,a.w,b.x,b.y,b.z,b.w};
    float hf[8];
#pragma unroll
    for (int i=0;i<8;i++) hf[i] = __bfloat162float(__float2bfloat16(f[i]));
#pragma unroll
    for (int i=0;i<4;i++){
        h[i] = packbf(f[2*i], f[2*i+1]);
        l[i] = packbf(f[2*i]-hf[2*i], f[2*i+1]-hf[2*i+1]);
    }
}
__device__ __forceinline__ void store_pair(__nv_bfloat16* dh, __nv_bfloat16* dl,
                                           size_t idx, float v1, float v2){
    const __nv_bfloat16 h1 = __float2bfloat16(v1), h2 = __float2bfloat16(v2);
    uint32_t hp; { __nv_bfloat162 t; t.x=h1; t.y=h2; hp=*reinterpret_cast<uint32_t*>(&t); }
    *reinterpret_cast<uint32_t*>(dh + idx) = hp;
    *reinterpret_cast<uint32_t*>(dl + idx) =
        packbf(v1 - __bfloat162float(h1), v2 - __bfloat162float(h2));
}

// ---------------------------------------------------------------------------
// HMMA bf16x3 GEMM: D[128x128] = A[M,768] @ B[N,768]^T (fp32 accum)
// EPI==0: A = x (fp32, split in-kernel); epilogue RoPE+scale -> bf16 q/k/v
// EPI==1: A = g_aoh/g_aol (bf16 direct); epilogue +bias -> fp32 Out
// ---------------------------------------------------------------------------
#define KT 32
#define NKT (Cn/KT)          // 24
#define TILE_B 10240
#define STAGE_B 40960
#define SMEM_DYN (2*STAGE_B)

template<int EPI>
__global__ __launch_bounds__(256) void gemm_tc(
    const float* __restrict__ Ain, const float* __restrict__ Bw,
    const float* __restrict__ cosb, const float* __restrict__ sinb,
    const float* __restrict__ bias, float* __restrict__ Out)
{
    extern __shared__ char sm[];

    const int tid  = threadIdx.x;
    const int wid  = tid >> 5;
    const int lane = tid & 31;
    const int m0 = blockIdx.y * 128;
    const int n0 = blockIdx.x * 128;

    const int row  = tid >> 1;          // 0..127
    const int half = tid & 1;           // 0..1
    const bool mok = (m0 + row) < Mn;
    const float* pa = Ain + (size_t)(m0+row)*Cn + half*16;
    const __nv_bfloat16* pah = g_aoh + (size_t)(m0+row)*Cn + half*16;
    const __nv_bfloat16* pal = g_aol + (size_t)(m0+row)*Cn + half*16;
    const float* pb = Bw + (size_t)(n0+row)*Cn + half*16;
    const uint32_t sts_off = (uint32_t)row*80 + (uint32_t)half*32;

    const uint32_t smb = smem_u32(sm);

    const int wm = wid & 3;
    const int wn = wid >> 2;
    const uint32_t a_lane = (uint32_t)((wm*32 + (lane&15))*80 + (lane>>4)*16);
    const uint32_t b_lane = (uint32_t)((wn*64 + (lane&7) + ((lane>>4)<<3))*80
                                       + ((lane>>3)&1)*16);

    float acc[2][8][4];
#pragma unroll
    for (int im=0;im<2;im++)
#pragma unroll
        for (int j=0;j<8;j++)
#pragma unroll
            for (int q=0;q<4;q++) acc[im][j][q] = 0.f;

    float4 a4[4], b4[4];
    uint4 abh[2], abl[2];

#define LDG_STAGE(s_) do{ \
    const float* qb = pb + (s_)*KT; \
    if (EPI==0){ \
        const float* qa = pa + (s_)*KT; \
        if (mok){ a4[0]=*(const float4*)qa;     a4[1]=*(const float4*)(qa+4); \
                  a4[2]=*(const float4*)(qa+8); a4[3]=*(const float4*)(qa+12);} \
        else { a4[0]=a4[1]=a4[2]=a4[3]=make_float4(0.f,0.f,0.f,0.f); } \
    } else { \
        if (mok){ abh[0]=*(const uint4*)(pah + (s_)*KT); abh[1]=*(const uint4*)(pah + (s_)*KT + 8); \
                  abl[0]=*(const uint4*)(pal + (s_)*KT); abl[1]=*(const uint4*)(pal + (s_)*KT + 8);} \
        else { abh[0]=abh[1]=abl[0]=abl[1]=make_uint4(0,0,0,0); } \
    } \
    b4[0]=*(const float4*)qb;     b4[1]=*(const float4*)(qb+4); \
    b4[2]=*(const float4*)(qb+8); b4[3]=*(const float4*)(qb+12); }while(0)

#define STS_STAGE(s_) do{ \
    char* sp = sm + (size_t)((s_)&1)*STAGE_B; \
    uint32_t h[4], l[4]; \
    if (EPI==0){ \
        cvt8_split(a4[0],a4[1],h,l); \
        *(uint4*)(sp + sts_off)              = make_uint4(h[0],h[1],h[2],h[3]); \
        *(uint4*)(sp + TILE_B + sts_off)     = make_uint4(l[0],l[1],l[2],l[3]); \
        cvt8_split(a4[2],a4[3],h,l); \
        *(uint4*)(sp + sts_off + 16)         = make_uint4(h[0],h[1],h[2],h[3]); \
        *(uint4*)(sp + TILE_B + sts_off + 16)= make_uint4(l[0],l[1],l[2],l[3]); \
    } else { \
        *(uint4*)(sp + sts_off)              = abh[0]; \
        *(uint4*)(sp + sts_off + 16)         = abh[1]; \
        *(uint4*)(sp + TILE_B + sts_off)     = abl[0]; \
        *(uint4*)(sp + TILE_B + sts_off + 16)= abl[1]; \
    } \
    cvt8_split(b4[0],b4[1],h,l); \
    *(uint4*)(sp + 2*TILE_B + sts_off)   = make_uint4(h[0],h[1],h[2],h[3]); \
    *(uint4*)(sp + 3*TILE_B + sts_off)   = make_uint4(l[0],l[1],l[2],l[3]); \
    cvt8_split(b4[2],b4[3],h,l); \
    *(uint4*)(sp + 2*TILE_B + sts_off+16)= make_uint4(h[0],h[1],h[2],h[3]); \
    *(uint4*)(sp + 3*TILE_B + sts_off+16)= make_uint4(l[0],l[1],l[2],l[3]); }while(0)

    LDG_STAGE(0);
    STS_STAGE(0);
    __syncthreads();

    for (int s = 0; s < NKT; s++){
        if (s+1 < NKT) LDG_STAGE(s+1);

        const uint32_t sb = smb + (uint32_t)(s&1)*STAGE_B;
#pragma unroll
        for (int kk = 0; kk < 2; kk++){
            uint32_t ah[2][4], al[2][4];
            ldsm4(ah[0], sb + a_lane + kk*32);
            ldsm4(ah[1], sb + a_lane + 16*80 + kk*32);
            ldsm4(al[0], sb + TILE_B + a_lane + kk*32);
            ldsm4(al[1], sb + TILE_B + a_lane + 16*80 + kk*32);
            uint32_t bh[4][4], bl[4][4];
#pragma unroll
            for (int t2 = 0; t2 < 4; t2++){
                ldsm4(bh[t2], sb + 2*TILE_B + b_lane + t2*16*80 + kk*32);
                ldsm4(bl[t2], sb + 3*TILE_B + b_lane + t2*16*80 + kk*32);
            }
            // term 1: Ah*Bh  (RAW distance 16 across accumulators)
#pragma unroll
            for (int im = 0; im < 2; im++)
#pragma unroll
                for (int j = 0; j < 8; j++)
                    mma16816(acc[im][j], ah[im],
                             bh[j>>1][(j&1)*2], bh[j>>1][(j&1)*2+1]);
            // term 2: Al*Bh
#pragma unroll
            for (int im = 0; im < 2; im++)
#pragma unroll
                for (int j = 0; j < 8; j++)
                    mma16816(acc[im][j], al[im],
                             bh[j>>1][(j&1)*2], bh[j>>1][(j&1)*2+1]);
            // term 3: Ah*Bl
#pragma unroll
            for (int im = 0; im < 2; im++)
#pragma unroll
                for (int j = 0; j < 8; j++)
                    mma16816(acc[im][j], ah[im],
                             bl[j>>1][(j&1)*2], bl[j>>1][(j&1)*2+1]);
        }

        if (s+1 < NKT) STS_STAGE(s+1);
        __syncthreads();
    }
#undef LDG_STAGE
#undef STS_STAGE

    // ---------------- epilogue
    if (EPI == 0){
        // RoPE + q-scale, write bf16 hi/lo q/k/v in [B,H,N,D]
#pragma unroll
        for (int im = 0; im < 2; im++){
#pragma unroll
            for (int j = 0; j < 8; j++){
                const int cl = wn*64 + j*8 + (lane&3)*2;
#pragma unroll
                for (int rr = 0; rr < 2; rr++){
                    const int r = wm*32 + im*16 + (lane>>2) + rr*8;
                    const int m = m0 + r;
                    if (m >= Mn) continue;
                    float v1 = acc[im][j][rr*2+0];
                    float v2 = acc[im][j][rr*2+1];
                    const int gc  = n0 + cl;
                    const int sec = gc / Cn;
                    const int rem = gc - sec*Cn;
                    const int hh  = rem >> 6;
                    const int d   = rem & 63;
                    const int bb  = m / Nn;
                    const int n   = m - bb*Nn;
                    if (sec < 2 && n > 0){
                        const float cs = cosb[(n-1)*(Dn/2) + (d>>1)];
                        const float sn = sinb[(n-1)*(Dn/2) + (d>>1)];
                        const float r1 = v1*cs - v2*sn;
                        const float r2 = v1*sn + v2*cs;
                        v1 = r1; v2 = r2;
                    }
                    if (sec == 0){ v1 *= 0.125f; v2 *= 0.125f; }
                    const size_t idx = ((size_t)(bb*Hn + hh)*Nn + n)*Dn + d;
                    if (sec == 0)      store_pair(g_qh, g_ql, idx, v1, v2);
                    else if (sec == 1) store_pair(g_kh, g_kl, idx, v1, v2);
                    else               store_pair(g_vh, g_vl, idx, v1, v2);
                }
            }
        }
    } else {
        float* Ds = (float*)sm;            // 128 x 132 staging
#pragma unroll
        for (int im = 0; im < 2; im++){
#pragma unroll
            for (int j = 0; j < 8; j++){
                const int cl = wn*64 + j*8 + (lane&3)*2;
#pragma unroll
                for (int rr = 0; rr < 2; rr++){
                    const int r = wm*32 + im*16 + (lane>>2) + rr*8;
                    float v1 = acc[im][j][rr*2+0];
                    float v2 = acc[im][j][rr*2+1];
                    const int gc = n0 + cl;
                    v1 += bias[gc]; v2 += bias[gc+1];
                    Ds[r*132 + cl]   = v1;
                    Ds[r*132 + cl+1] = v2;
                }
            }
        }
        __syncthreads();
        const int m = m0 + row;
        if (m < Mn){
            float* dst = Out + (size_t)m*Cn + n0 + half*64;
            const float* src = &Ds[row*132 + half*64];
#pragma unroll
            for (int j = 0; j < 64; j += 4)
                *(float4*)&dst[j] = *(const float4*)&src[j];
        }
    }
}

// ---------------------------------------------------------------------------
// HMMA flash attention: CTA = 128 q-rows x (b,h). 8 warps x m16.
// Smem: K/V hi/lo tiles 64x64 bf16, pitch 144B, double buffered.
// ---------------------------------------------------------------------------
#define AT_PITCH 144
#define AT_TILE  (64*AT_PITCH)       // 9216
#define AT_STAGE (4*AT_TILE)         // 36864
#define AT_SMEM  (2*AT_STAGE)        // 73728
#define NTkv ((Nn+63)/64)            // 10

__global__ __launch_bounds__(256) void attn_tc()
{
    extern __shared__ char sm[];
    const uint32_t smb = smem_u32(sm);
    const int tid  = threadIdx.x;
    const int wid  = tid >> 5;
    const int lane = tid & 31;
    const int qt   = blockIdx.x;          // 0..4
    const int bh   = blockIdx.y;          // 0..383
    const int bb   = bh / Hn;
    const int h    = bh - bb*Hn;

    const __nv_bfloat16* Qh = g_qh + (size_t)bh*Nn*Dn;
    const __nv_bfloat16* Ql = g_ql + (size_t)bh*Nn*Dn;
    const __nv_bfloat16* Kh = g_kh + (size_t)bh*Nn*Dn;
    const __nv_bfloat16* Kl = g_kl + (size_t)bh*Nn*Dn;
    const __nv_bfloat16* Vh = g_vh + (size_t)bh*Nn*Dn;
    const __nv_bfloat16* Vl = g_vl + (size_t)bh*Nn*Dn;

    // ---- stage Q (128 rows x 64) hi at 0, lo at 18432; then ldsm to frags
    {
#pragma unroll
        for (int i = 0; i < 4; i++){
            const int idx = tid + i*256;      // 0..1023
            const int r   = idx >> 3;
            const int j   = idx & 7;
            const int gr  = qt*128 + r;
            uint4 vh = make_uint4(0,0,0,0), vl = vh;
            if (gr < Nn){
                vh = *(const uint4*)(Qh + (size_t)gr*Dn + j*8);
                vl = *(const uint4*)(Ql + (size_t)gr*Dn + j*8);
            }
            *(uint4*)(sm + r*AT_PITCH + j*16)         = vh;
            *(uint4*)(sm + 18432 + r*AT_PITCH + j*16) = vl;
        }
    }
    __syncthreads();
    uint32_t qfh[4][4], qfl[4][4];
    {
        const uint32_t qa = smb + (uint32_t)((wid*16 + (lane&15))*AT_PITCH + (lane>>4)*16);
#pragma unroll
        for (int kk = 0; kk < 4; kk++){
            ldsm4(qfh[kk], qa + kk*32);
            ldsm4(qfl[kk], qa + 18432 + kk*32);
        }
    }
    __syncthreads();

#define LOADKV(t_, buf_) do{ \
    const int kv0 = (t_)*64; \
    char* bp = sm + (size_t)(buf_)*AT_STAGE; \
    _Pragma("unroll") \
    for (int i_ = 0; i_ < 8; i_++){ \
        const int idx = tid + i_*256;            /* 0..2047 */ \
        const int ts  = idx >> 9;                /* 0..3 */ \
        const int rem = idx & 511; \
        const int r_  = rem >> 3; \
        const int j_  = rem & 7; \
        const int gr  = kv0 + r_; \
        const __nv_bfloat16* src = (ts==0)?Kh:(ts==1)?Kl:(ts==2)?Vh:Vl; \
        uint4 v = make_uint4(0,0,0,0); \
        if (gr < Nn) v = *(const uint4*)(src + (size_t)gr*Dn + j_*8); \
        *(uint4*)(bp + ts*AT_TILE + r_*AT_PITCH + j_*16) = v; \
    } }while(0)

    LOADKV(0, 0);
    __syncthreads();

    float m0r = -1e30f, m1r = -1e30f, l0r = 0.f, l1r = 0.f;
    float o[8][4];
#pragma unroll
    for (int j=0;j<8;j++)
#pragma unroll
        for (int q=0;q<4;q++) o[j][q] = 0.f;

    for (int t = 0; t < NTkv; t++){
        if (t+1 < NTkv) LOADKV(t+1, (t+1)&1);

        const uint32_t sb = smb + (uint32_t)(t&1)*AT_STAGE;

        // ---- S = Q K^T (3 terms, term-major to break acc RAW chains)
        float s[8][4];
#pragma unroll
        for (int j=0;j<8;j++)
#pragma unroll
            for (int q=0;q<4;q++) s[j][q] = 0.f;

#pragma unroll
        for (int kk = 0; kk < 4; kk++){
            uint32_t kh[4][4], kl[4][4];
#pragma unroll
            for (int g = 0; g < 4; g++){
                const uint32_t ka = sb
                    + (uint32_t)((g*16 + (lane&7) + ((lane>>4)<<3))*AT_PITCH
                                 + ((lane>>3)&1)*16 + kk*32);
                ldsm4(kh[g], ka);
                ldsm4(kl[g], ka + AT_TILE);
            }
#pragma unroll
            for (int j = 0; j < 8; j++)
                mma16816(s[j], qfh[kk], kh[j>>1][(j&1)*2], kh[j>>1][(j&1)*2+1]);
#pragma unroll
            for (int j = 0; j < 8; j++)
                mma16816(s[j], qfl[kk], kh[j>>1][(j&1)*2], kh[j>>1][(j&1)*2+1]);
#pragma unroll
            for (int j = 0; j < 8; j++)
                mma16816(s[j], qfh[kk], kl[j>>1][(j&1)*2], kl[j>>1][(j&1)*2+1]);
        }

        // ---- mask + online softmax (rows: lane>>2 and +8)
        if (t == NTkv-1){
#pragma unroll
            for (int j = 0; j < 8; j++){
                const int c0 = t*64 + j*8 + (lane&3)*2;
                if (c0   >= Nn){ s[j][0] = -1e30f; s[j][2] = -1e30f; }
                if (c0+1 >= Nn){ s[j][1] = -1e30f; s[j][3] = -1e30f; }
            }
        }
        float mx0 = -1e30f, mx1 = -1e30f;
#pragma unroll
        for (int j = 0; j < 8; j++){
            mx0 = fmaxf(mx0, fmaxf(s[j][0], s[j][1]));
            mx1 = fmaxf(mx1, fmaxf(s[j][2], s[j][3]));
        }
        mx0 = fmaxf(mx0, __shfl_xor_sync(0xffffffffu, mx0, 1));
        mx0 = fmaxf(mx0, __shfl_xor_sync(0xffffffffu, mx0, 2));
        mx1 = fmaxf(mx1, __shfl_xor_sync(0xffffffffu, mx1, 1));
        mx1 = fmaxf(mx1, __shfl_xor_sync(0xffffffffu, mx1, 2));
        const float mn0 = fmaxf(m0r, mx0), mn1 = fmaxf(m1r, mx1);
        const float al0 = __expf(m0r - mn0), al1 = __expf(m1r - mn1);
        float rs0 = 0.f, rs1 = 0.f;
#pragma unroll
        for (int j = 0; j < 8; j++){
            s[j][0] = __expf(s[j][0]-mn0); s[j][1] = __expf(s[j][1]-mn0);
            s[j][2] = __expf(s[j][2]-mn1); s[j][3] = __expf(s[j][3]-mn1);
            rs0 += s[j][0] + s[j][1];
            rs1 += s[j][2] + s[j][3];
        }
        rs0 += __shfl_xor_sync(0xffffffffu, rs0, 1);
        rs0 += __shfl_xor_sync(0xffffffffu, rs0, 2);
        rs1 += __shfl_xor_sync(0xffffffffu, rs1, 1);
        rs1 += __shfl_xor_sync(0xffffffffu, rs1, 2);
        l0r = l0r*al0 + rs0;  m0r = mn0;
        l1r = l1r*al1 + rs1;  m1r = mn1;
#pragma unroll
        for (int j = 0; j < 8; j++){
            o[j][0] *= al0; o[j][1] *= al0;
            o[j][2] *= al1; o[j][3] *= al1;
        }

        // ---- O += P V (3 terms, term-major), P repacked in registers
#pragma unroll
        for (int kk = 0; kk < 4; kk++){
            uint32_t pha[4], pla[4];
            {
                const int j0 = 2*kk, j1 = 2*kk+1;
                float h0, h1;
                h0 = __bfloat162float(__float2bfloat16(s[j0][0]));
                h1 = __bfloat162float(__float2bfloat16(s[j0][1]));
                pha[0] = packbf(s[j0][0], s[j0][1]);
                pla[0] = packbf(s[j0][0]-h0, s[j0][1]-h1);
                h0 = __bfloat162float(__float2bfloat16(s[j0][2]));
                h1 = __bfloat162float(__float2bfloat16(s[j0][3]));
                pha[1] = packbf(s[j0][2], s[j0][3]);
                pla[1] = packbf(s[j0][2]-h0, s[j0][3]-h1);
                h0 = __bfloat162float(__float2bfloat16(s[j1][0]));
                h1 = __bfloat162float(__float2bfloat16(s[j1][1]));
                pha[2] = packbf(s[j1][0], s[j1][1]);
                pla[2] = packbf(s[j1][0]-h0, s[j1][1]-h1);
                h0 = __bfloat162float(__float2bfloat16(s[j1][2]));
                h1 = __bfloat162float(__float2bfloat16(s[j1][3]));
                pha[3] = packbf(s[j1][2], s[j1][3]);
                pla[3] = packbf(s[j1][2]-h0, s[j1][3]-h1);
            }
            uint32_t vh[4][4], vl[4][4];
#pragma unroll
            for (int g = 0; g < 4; g++){
                const uint32_t va = sb + 2*AT_TILE
                    + (uint32_t)((kk*16 + (lane&7) + ((lane>>3)&1)*8)*AT_PITCH
                                 + ((lane>>4)*8 + g*16)*2);
                ldsm4t(vh[g], va);
                ldsm4t(vl[g], va + AT_TILE);
            }
#pragma unroll
            for (int j = 0; j < 8; j++)
                mma16816(o[j], pha, vh[j>>1][(j&1)*2], vh[j>>1][(j&1)*2+1]);
#pragma unroll
            for (int j = 0; j < 8; j++)
                mma16816(o[j], pla, vh[j>>1][(j&1)*2], vh[j>>1][(j&1)*2+1]);
#pragma unroll
            for (int j = 0; j < 8; j++)
                mma16816(o[j], pha, vl[j>>1][(j&1)*2], vl[j>>1][(j&1)*2+1]);
        }
        __syncthreads();
    }
#undef LOADKV

    // ---- normalize + store AO bf16 hi/lo ([B*N, C] at col h*64+d)
    const float inv0 = 1.f / l0r, inv1 = 1.f / l1r;
    const int r0 = qt*128 + wid*16 + (lane>>2);
    const int r1 = r0 + 8;
#pragma unroll
    for (int j = 0; j < 8; j++){
        const int col = h*Dn + j*8 + (lane&3)*2;
        if (r0 < Nn)
            store_pair(g_aoh, g_aol, (size_t)(bb*Nn + r0)*Cn + col,
                       o[j][0]*inv0, o[j][1]*inv0);
        if (r1 < Nn)
            store_pair(g_aoh, g_aol, (size_t)(bb*Nn + r1)*Cn + col,
                       o[j][2]*inv1, o[j][3]*inv1);
    }
}

// ---------------------------------------------------------------------------
extern "C" void kernel_launch(void* const* d_in, const int* in_sizes, int n_in,
                              void* d_out, int out_size)
{
    (void)in_sizes; (void)n_in; (void)out_size;
    const float* x      = (const float*)d_in[0];
    const float* w_qkv  = (const float*)d_in[1];
    const float* w_proj = (const float*)d_in[2];
    const float* b_proj = (const float*)d_in[3];
    const float* cosb   = (const float*)d_in[4];
    const float* sinb   = (const float*)d_in[5];
    float* out = (float*)d_out;

    cudaFuncSetAttribute(gemm_tc<0>, cudaFuncAttributeMaxDynamicSharedMemorySize, SMEM_DYN);
    cudaFuncSetAttribute(gemm_tc<1>, cudaFuncAttributeMaxDynamicSharedMemorySize, SMEM_DYN);
    cudaFuncSetAttribute(attn_tc,    cudaFuncAttributeMaxDynamicSharedMemorySize, AT_SMEM);

    const int MT = (Mn + 127) / 128;   // 145
    gemm_tc<0><<<dim3(QKV_N/128, MT), 256, SMEM_DYN>>>(x, w_qkv, cosb, sinb, nullptr, nullptr);
    attn_tc<<<dim3((Nn+127)/128, Bn*Hn), 256, AT_SMEM>>>();
    gemm_tc<1><<<dim3(Cn/128, MT), 256, SMEM_DYN>>>(nullptr, w_proj, nullptr, nullptr, b_proj, out);
}

// round 6
// speedup vs baseline: 1.2272x; 1.2272x over previous
#include <cuda_runtime.h>
#include <cuda_bf16.h>
#include <cstdint>

#define Bn 32
#define Nn 577
#define Cn 768
#define Hn 12
#define Dn 64
#define Mn (Bn*Nn)          // 18464
#define QKV_N (3*Cn)        // 2304
#define BHD ((size_t)Bn*Hn*Nn*Dn)   // 14,180,352

// Scratch (__device__ globals) — bf16 hi/lo pairs everywhere
__device__ __align__(16) __nv_bfloat16 g_xh[(size_t)Mn*Cn],  g_xl[(size_t)Mn*Cn];
__device__ __align__(16) __nv_bfloat16 g_wqh[(size_t)QKV_N*Cn], g_wql[(size_t)QKV_N*Cn];
__device__ __align__(16) __nv_bfloat16 g_wph[(size_t)Cn*Cn], g_wpl[(size_t)Cn*Cn];
__device__ __align__(16) __nv_bfloat16 g_qh[BHD], g_ql[BHD];
__device__ __align__(16) __nv_bfloat16 g_kh[BHD], g_kl[BHD];
__device__ __align__(16) __nv_bfloat16 g_vh[BHD], g_vl[BHD];
__device__ __align__(16) __nv_bfloat16 g_aoh[(size_t)Mn*Cn], g_aol[(size_t)Mn*Cn];

// ---------------------------------------------------------------------------
// helpers
// ---------------------------------------------------------------------------
__device__ __forceinline__ uint32_t smem_u32(const void* p){
    uint32_t a;
    asm("{ .reg .u64 t; cvta.to.shared.u64 t, %1; cvt.u32.u64 %0, t; }"
        : "=r"(a) : "l"(p));
    return a;
}
__device__ __forceinline__ void ldsm4(uint32_t (&r)[4], uint32_t a){
    asm volatile("ldmatrix.sync.aligned.m8n8.x4.shared.b16 {%0,%1,%2,%3}, [%4];"
        : "=r"(r[0]),"=r"(r[1]),"=r"(r[2]),"=r"(r[3]) : "r"(a));
}
__device__ __forceinline__ void ldsm4t(uint32_t (&r)[4], uint32_t a){
    asm volatile("ldmatrix.sync.aligned.m8n8.x4.trans.shared.b16 {%0,%1,%2,%3}, [%4];"
        : "=r"(r[0]),"=r"(r[1]),"=r"(r[2]),"=r"(r[3]) : "r"(a));
}
__device__ __forceinline__ void mma16816(float* c, const uint32_t* a,
                                         uint32_t b0, uint32_t b1){
    asm volatile("mma.sync.aligned.m16n8k16.row.col.f32.bf16.bf16.f32 "
        "{%0,%1,%2,%3}, {%4,%5,%6,%7}, {%8,%9}, {%0,%1,%2,%3};"
        : "+f"(c[0]),"+f"(c[1]),"+f"(c[2]),"+f"(c[3])
        : "r"(a[0]),"r"(a[1]),"r"(a[2]),"r"(a[3]), "r"(b0),"r"(b1));
}
__device__ __forceinline__ void cpa(uint32_t s, const void* g, uint32_t n){
    asm volatile("cp.async.cg.shared.global [%0], [%1], 16, %2;"
                 :: "r"(s), "l"(g), "r"(n) : "memory");
}
__device__ __forceinline__ uint32_t packbf(float x, float y){
    __nv_bfloat162 t = __floats2bfloat162_rn(x, y);
    return *reinterpret_cast<uint32_t*>(&t);
}
__device__ __forceinline__ void store_pair(__nv_bfloat16* dh, __nv_bfloat16* dl,
                                           size_t idx, float v1, float v2){
    const __nv_bfloat16 h1 = __float2bfloat16(v1), h2 = __float2bfloat16(v2);
    uint32_t hp; { __nv_bfloat162 t; t.x=h1; t.y=h2; hp=*reinterpret_cast<uint32_t*>(&t); }
    *reinterpret_cast<uint32_t*>(dh + idx) = hp;
    *reinterpret_cast<uint32_t*>(dl + idx) =
        packbf(v1 - __bfloat162float(h1), v2 - __bfloat162float(h2));
}

// ---------------------------------------------------------------------------
// split: fp32 -> bf16 hi + bf16 lo (residual)
// ---------------------------------------------------------------------------
__global__ __launch_bounds__(256) void split_k(
    const float* __restrict__ s, __nv_bfloat16* __restrict__ dh,
    __nv_bfloat16* __restrict__ dl, int n)
{
    const int i = (blockIdx.x*256 + threadIdx.x)*4;
    if (i < n){
        float4 v = *(const float4*)(s + i);
        const float hx = __bfloat162float(__float2bfloat16(v.x));
        const float hy = __bfloat162float(__float2bfloat16(v.y));
        const float hz = __bfloat162float(__float2bfloat16(v.z));
        const float hw = __bfloat162float(__float2bfloat16(v.w));
        *(uint2*)(dh + i) = make_uint2(packbf(v.x, v.y), packbf(v.z, v.w));
        *(uint2*)(dl + i) = make_uint2(packbf(v.x-hx, v.y-hy), packbf(v.z-hz, v.w-hw));
    }
}

// ---------------------------------------------------------------------------
// HMMA bf16x3 GEMM, cp.async pipeline, SW128 128B-row tiles, k-stage 64.
// D[128x128] = A[M,768] @ B[N,768]^T (fp32 accum), 3 split terms.
// EPI==0: epilogue RoPE + q-scale -> bf16 q/k/v.  EPI==1: +bias -> fp32 Out.
// ---------------------------------------------------------------------------
#define KS 64
#define NSTG (Cn/KS)         // 12
#define TILE16K 16384
#define STG_B (4*TILE16K)    // 65536 : Ah|Al|Bh|Bl
#define NPIPE 3
#define SMEM_G (NPIPE*STG_B) // 196608

template<int EPI>
__global__ __launch_bounds__(256) void gemm_bb(
    const __nv_bfloat16* __restrict__ Ah, const __nv_bfloat16* __restrict__ Al,
    const __nv_bfloat16* __restrict__ Bh, const __nv_bfloat16* __restrict__ Bl,
    const float* __restrict__ cosb, const float* __restrict__ sinb,
    const float* __restrict__ bias, float* __restrict__ Out)
{
    extern __shared__ char sm[];
    const uint32_t smb = smem_u32(sm);

    const int tid  = threadIdx.x;
    const int wid  = tid >> 5;
    const int lane = tid & 31;
    const int m0 = blockIdx.y * 128;
    const int n0 = blockIdx.x * 128;

    const int wm = wid & 3;
    const int wn = wid >> 2;

    float acc[2][8][4];
#pragma unroll
    for (int im=0;im<2;im++)
#pragma unroll
        for (int j=0;j<8;j++)
#pragma unroll
            for (int q=0;q<4;q++) acc[im][j][q] = 0.f;

    // producer: 16 cp.async per thread per stage (4 rounds x 4 tensors)
#define ISSUE(s_, b_) do{ \
    const uint32_t bb_ = smb + (uint32_t)(b_)*STG_B; \
    const int kt_ = (s_)*KS; \
    _Pragma("unroll") \
    for (int r_ = 0; r_ < 4; r_++){ \
        const int idx_ = tid + r_*256; \
        const uint32_t row_ = (uint32_t)(idx_ >> 3); \
        const uint32_t grp_ = (uint32_t)(idx_ & 7); \
        const uint32_t dst_ = bb_ + row_*128 + ((grp_ ^ (row_ & 7)) << 4); \
        const uint32_t an_  = ((int)(m0 + row_) < Mn) ? 16u : 0u; \
        const size_t aoff_ = (size_t)(m0 + row_)*Cn + kt_ + grp_*8; \
        const size_t boff_ = (size_t)(n0 + row_)*Cn + kt_ + grp_*8; \
        cpa(dst_,             Ah + aoff_, an_); \
        cpa(dst_ + TILE16K,   Al + aoff_, an_); \
        cpa(dst_ + 2*TILE16K, Bh + boff_, 16u); \
        cpa(dst_ + 3*TILE16K, Bl + boff_, 16u); \
    } \
    asm volatile("cp.async.commit_group;":::"memory"); \
}while(0)

    ISSUE(0, 0);
    ISSUE(1, 1);
    ISSUE(2, 2);

    const uint32_t ar0 = (uint32_t)(wm*32 + (lane & 15));
    const uint32_t ar1 = ar0 + 16;
    const uint32_t brb = (uint32_t)(wn*64 + (lane & 7) + ((lane >> 4) << 3));

    for (int s = 0; s < NSTG; s++){
        asm volatile("cp.async.wait_group 2;":::"memory");
        __syncthreads();

        const uint32_t sb = smb + (uint32_t)(s % NPIPE)*STG_B;
#pragma unroll
        for (int kk = 0; kk < 4; kk++){
            const uint32_t gA = (uint32_t)(kk*2 + (lane >> 4));
            const uint32_t gB = (uint32_t)(kk*2 + ((lane >> 3) & 1));
            uint32_t ah[2][4], al[2][4], bhf[4][4], blf[4][4];
            ldsm4(ah[0], sb + ar0*128 + ((gA ^ (ar0 & 7)) << 4));
            ldsm4(ah[1], sb + ar1*128 + ((gA ^ (ar1 & 7)) << 4));
            ldsm4(al[0], sb + TILE16K + ar0*128 + ((gA ^ (ar0 & 7)) << 4));
            ldsm4(al[1], sb + TILE16K + ar1*128 + ((gA ^ (ar1 & 7)) << 4));
#pragma unroll
            for (int t2 = 0; t2 < 4; t2++){
                const uint32_t br = brb + (uint32_t)(t2*16);
                ldsm4(bhf[t2], sb + 2*TILE16K + br*128 + ((gB ^ (br & 7)) << 4));
                ldsm4(blf[t2], sb + 3*TILE16K + br*128 + ((gB ^ (br & 7)) << 4));
            }
#pragma unroll
            for (int im = 0; im < 2; im++)
#pragma unroll
                for (int j = 0; j < 8; j++)
                    mma16816(acc[im][j], ah[im],
                             bhf[j>>1][(j&1)*2], bhf[j>>1][(j&1)*2+1]);
#pragma unroll
            for (int im = 0; im < 2; im++)
#pragma unroll
                for (int j = 0; j < 8; j++)
                    mma16816(acc[im][j], al[im],
                             bhf[j>>1][(j&1)*2], bhf[j>>1][(j&1)*2+1]);
#pragma unroll
            for (int im = 0; im < 2; im++)
#pragma unroll
                for (int j = 0; j < 8; j++)
                    mma16816(acc[im][j], ah[im],
                             blf[j>>1][(j&1)*2], blf[j>>1][(j&1)*2+1]);
        }
        __syncthreads();
        if (s + NPIPE < NSTG) ISSUE(s + NPIPE, s % NPIPE);
    }
#undef ISSUE

    // ---------------- epilogue
    if (EPI == 0){
        // RoPE + q-scale, write bf16 hi/lo q/k/v in [B,H,N,D]
#pragma unroll
        for (int im = 0; im < 2; im++){
#pragma unroll
            for (int j = 0; j < 8; j++){
                const int cl = wn*64 + j*8 + (lane&3)*2;
#pragma unroll
                for (int rr = 0; rr < 2; rr++){
                    const int r = wm*32 + im*16 + (lane>>2) + rr*8;
                    const int m = m0 + r;
                    if (m >= Mn) continue;
                    float v1 = acc[im][j][rr*2+0];
                    float v2 = acc[im][j][rr*2+1];
                    const int gc  = n0 + cl;
                    const int sec = gc / Cn;
                    const int rem = gc - sec*Cn;
                    const int hh  = rem >> 6;
                    const int d   = rem & 63;
                    const int bb  = m / Nn;
                    const int n   = m - bb*Nn;
                    if (sec < 2 && n > 0){
                        const float cs = cosb[(n-1)*(Dn/2) + (d>>1)];
                        const float sn = sinb[(n-1)*(Dn/2) + (d>>1)];
                        const float r1 = v1*cs - v2*sn;
                        const float r2 = v1*sn + v2*cs;
                        v1 = r1; v2 = r2;
                    }
                    if (sec == 0){ v1 *= 0.125f; v2 *= 0.125f; }
                    const size_t idx = ((size_t)(bb*Hn + hh)*Nn + n)*Dn + d;
                    if (sec == 0)      store_pair(g_qh, g_ql, idx, v1, v2);
                    else if (sec == 1) store_pair(g_kh, g_kl, idx, v1, v2);
                    else               store_pair(g_vh, g_vl, idx, v1, v2);
                }
            }
        }
    } else {
        float* Ds = (float*)sm;            // 128 x 132 staging
#pragma unroll
        for (int im = 0; im < 2; im++){
#pragma unroll
            for (int j = 0; j < 8; j++){
                const int cl = wn*64 + j*8 + (lane&3)*2;
#pragma unroll
                for (int rr = 0; rr < 2; rr++){
                    const int r = wm*32 + im*16 + (lane>>2) + rr*8;
                    float v1 = acc[im][j][rr*2+0];
                    float v2 = acc[im][j][rr*2+1];
                    const int gc = n0 + cl;
                    v1 += bias[gc]; v2 += bias[gc+1];
                    Ds[r*132 + cl]   = v1;
                    Ds[r*132 + cl+1] = v2;
                }
            }
        }
        __syncthreads();
        const int row  = tid >> 1;
        const int half = tid & 1;
        const int m = m0 + row;
        if (m < Mn){
            float* dst = Out + (size_t)m*Cn + n0 + half*64;
            const float* src = &Ds[row*132 + half*64];
#pragma unroll
            for (int j = 0; j < 64; j += 4)
                *(float4*)&dst[j] = *(const float4*)&src[j];
        }
    }
}

// ---------------------------------------------------------------------------
// HMMA flash attention (unchanged from round 4/5)
// ---------------------------------------------------------------------------
#define AT_PITCH 144
#define AT_TILE  (64*AT_PITCH)       // 9216
#define AT_STAGE (4*AT_TILE)         // 36864
#define AT_SMEM  (2*AT_STAGE)        // 73728
#define NTkv ((Nn+63)/64)            // 10

__global__ __launch_bounds__(256) void attn_tc()
{
    extern __shared__ char sm[];
    const uint32_t smb = smem_u32(sm);
    const int tid  = threadIdx.x;
    const int wid  = tid >> 5;
    const int lane = tid & 31;
    const int qt   = blockIdx.x;
    const int bh   = blockIdx.y;
    const int bb   = bh / Hn;
    const int h    = bh - bb*Hn;

    const __nv_bfloat16* Qh = g_qh + (size_t)bh*Nn*Dn;
    const __nv_bfloat16* Ql = g_ql + (size_t)bh*Nn*Dn;
    const __nv_bfloat16* Kh = g_kh + (size_t)bh*Nn*Dn;
    const __nv_bfloat16* Kl = g_kl + (size_t)bh*Nn*Dn;
    const __nv_bfloat16* Vh = g_vh + (size_t)bh*Nn*Dn;
    const __nv_bfloat16* Vl = g_vl + (size_t)bh*Nn*Dn;

    {
#pragma unroll
        for (int i = 0; i < 4; i++){
            const int idx = tid + i*256;
            const int r   = idx >> 3;
            const int j   = idx & 7;
            const int gr  = qt*128 + r;
            uint4 vh = make_uint4(0,0,0,0), vl = vh;
            if (gr < Nn){
                vh = *(const uint4*)(Qh + (size_t)gr*Dn + j*8);
                vl = *(const uint4*)(Ql + (size_t)gr*Dn + j*8);
            }
            *(uint4*)(sm + r*AT_PITCH + j*16)         = vh;
            *(uint4*)(sm + 18432 + r*AT_PITCH + j*16) = vl;
        }
    }
    __syncthreads();
    uint32_t qfh[4][4], qfl[4][4];
    {
        const uint32_t qa = smb + (uint32_t)((wid*16 + (lane&15))*AT_PITCH + (lane>>4)*16);
#pragma unroll
        for (int kk = 0; kk < 4; kk++){
            ldsm4(qfh[kk], qa + kk*32);
            ldsm4(qfl[kk], qa + 18432 + kk*32);
        }
    }
    __syncthreads();

#define LOADKV(t_, buf_) do{ \
    const int kv0 = (t_)*64; \
    char* bp = sm + (size_t)(buf_)*AT_STAGE; \
    _Pragma("unroll") \
    for (int i_ = 0; i_ < 8; i_++){ \
        const int idx = tid + i_*256; \
        const int ts  = idx >> 9; \
        const int rem = idx & 511; \
        const int r_  = rem >> 3; \
        const int j_  = rem & 7; \
        const int gr  = kv0 + r_; \
        const __nv_bfloat16* src = (ts==0)?Kh:(ts==1)?Kl:(ts==2)?Vh:Vl; \
        uint4 v = make_uint4(0,0,0,0); \
        if (gr < Nn) v = *(const uint4*)(src + (size_t)gr*Dn + j_*8); \
        *(uint4*)(bp + ts*AT_TILE + r_*AT_PITCH + j_*16) = v; \
    } }while(0)

    LOADKV(0, 0);
    __syncthreads();

    float m0r = -1e30f, m1r = -1e30f, l0r = 0.f, l1r = 0.f;
    float o[8][4];
#pragma unroll
    for (int j=0;j<8;j++)
#pragma unroll
        for (int q=0;q<4;q++) o[j][q] = 0.f;

    for (int t = 0; t < NTkv; t++){
        if (t+1 < NTkv) LOADKV(t+1, (t+1)&1);

        const uint32_t sb = smb + (uint32_t)(t&1)*AT_STAGE;

        float s[8][4];
#pragma unroll
        for (int j=0;j<8;j++)
#pragma unroll
            for (int q=0;q<4;q++) s[j][q] = 0.f;

#pragma unroll
        for (int kk = 0; kk < 4; kk++){
            uint32_t kh[4][4], kl[4][4];
#pragma unroll
            for (int g = 0; g < 4; g++){
                const uint32_t ka = sb
                    + (uint32_t)((g*16 + (lane&7) + ((lane>>4)<<3))*AT_PITCH
                                 + ((lane>>3)&1)*16 + kk*32);
                ldsm4(kh[g], ka);
                ldsm4(kl[g], ka + AT_TILE);
            }
#pragma unroll
            for (int j = 0; j < 8; j++)
                mma16816(s[j], qfh[kk], kh[j>>1][(j&1)*2], kh[j>>1][(j&1)*2+1]);
#pragma unroll
            for (int j = 0; j < 8; j++)
                mma16816(s[j], qfl[kk], kh[j>>1][(j&1)*2], kh[j>>1][(j&1)*2+1]);
#pragma unroll
            for (int j = 0; j < 8; j++)
                mma16816(s[j], qfh[kk], kl[j>>1][(j&1)*2], kl[j>>1][(j&1)*2+1]);
        }

        if (t == NTkv-1){
#pragma unroll
            for (int j = 0; j < 8; j++){
                const int c0 = t*64 + j*8 + (lane&3)*2;
                if (c0   >= Nn){ s[j][0] = -1e30f; s[j][2] = -1e30f; }
                if (c0+1 >= Nn){ s[j][1] = -1e30f; s[j][3] = -1e30f; }
            }
        }
        float mx0 = -1e30f, mx1 = -1e30f;
#pragma unroll
        for (int j = 0; j < 8; j++){
            mx0 = fmaxf(mx0, fmaxf(s[j][0], s[j][1]));
            mx1 = fmaxf(mx1, fmaxf(s[j][2], s[j][3]));
        }
        mx0 = fmaxf(mx0, __shfl_xor_sync(0xffffffffu, mx0, 1));
        mx0 = fmaxf(mx0, __shfl_xor_sync(0xffffffffu, mx0, 2));
        mx1 = fmaxf(mx1, __shfl_xor_sync(0xffffffffu, mx1, 1));
        mx1 = fmaxf(mx1, __shfl_xor_sync(0xffffffffu, mx1, 2));
        const float mn0 = fmaxf(m0r, mx0), mn1 = fmaxf(m1r, mx1);
        const float al0 = __expf(m0r - mn0), al1 = __expf(m1r - mn1);
        float rs0 = 0.f, rs1 = 0.f;
#pragma unroll
        for (int j = 0; j < 8; j++){
            s[j][0] = __expf(s[j][0]-mn0); s[j][1] = __expf(s[j][1]-mn0);
            s[j][2] = __expf(s[j][2]-mn1); s[j][3] = __expf(s[j][3]-mn1);
            rs0 += s[j][0] + s[j][1];
            rs1 += s[j][2] + s[j][3];
        }
        rs0 += __shfl_xor_sync(0xffffffffu, rs0, 1);
        rs0 += __shfl_xor_sync(0xffffffffu, rs0, 2);
        rs1 += __shfl_xor_sync(0xffffffffu, rs1, 1);
        rs1 += __shfl_xor_sync(0xffffffffu, rs1, 2);
        l0r = l0r*al0 + rs0;  m0r = mn0;
        l1r = l1r*al1 + rs1;  m1r = mn1;
#pragma unroll
        for (int j = 0; j < 8; j++){
            o[j][0] *= al0; o[j][1] *= al0;
            o[j][2] *= al1; o[j][3] *= al1;
        }

#pragma unroll
        for (int kk = 0; kk < 4; kk++){
            uint32_t pha[4], pla[4];
            {
                const int j0 = 2*kk, j1 = 2*kk+1;
                float h0, h1;
                h0 = __bfloat162float(__float2bfloat16(s[j0][0]));
                h1 = __bfloat162float(__float2bfloat16(s[j0][1]));
                pha[0] = packbf(s[j0][0], s[j0][1]);
                pla[0] = packbf(s[j0][0]-h0, s[j0][1]-h1);
                h0 = __bfloat162float(__float2bfloat16(s[j0][2]));
                h1 = __bfloat162float(__float2bfloat16(s[j0][3]));
                pha[1] = packbf(s[j0][2], s[j0][3]);
                pla[1] = packbf(s[j0][2]-h0, s[j0][3]-h1);
                h0 = __bfloat162float(__float2bfloat16(s[j1][0]));
                h1 = __bfloat162float(__float2bfloat16(s[j1][1]));
                pha[2] = packbf(s[j1][0], s[j1][1]);
                pla[2] = packbf(s[j1][0]-h0, s[j1][1]-h1);
                h0 = __bfloat162float(__float2bfloat16(s[j1][2]));
                h1 = __bfloat162float(__float2bfloat16(s[j1][3]));
                pha[3] = packbf(s[j1][2], s[j1][3]);
                pla[3] = packbf(s[j1][2]-h0, s[j1][3]-h1);
            }
            uint32_t vh[4][4], vl[4][4];
#pragma unroll
            for (int g = 0; g < 4; g++){
                const uint32_t va = sb + 2*AT_TILE
                    + (uint32_t)((kk*16 + (lane&7) + ((lane>>3)&1)*8)*AT_PITCH
                                 + ((lane>>4)*8 + g*16)*2);
                ldsm4t(vh[g], va);
                ldsm4t(vl[g], va + AT_TILE);
            }
#pragma unroll
            for (int j = 0; j < 8; j++)
                mma16816(o[j], pha, vh[j>>1][(j&1)*2], vh[j>>1][(j&1)*2+1]);
#pragma unroll
            for (int j = 0; j < 8; j++)
                mma16816(o[j], pla, vh[j>>1][(j&1)*2], vh[j>>1][(j&1)*2+1]);
#pragma unroll
            for (int j = 0; j < 8; j++)
                mma16816(o[j], pha, vl[j>>1][(j&1)*2], vl[j>>1][(j&1)*2+1]);
        }
        __syncthreads();
    }
#undef LOADKV

    const float inv0 = 1.f / l0r, inv1 = 1.f / l1r;
    const int r0 = qt*128 + wid*16 + (lane>>2);
    const int r1 = r0 + 8;
#pragma unroll
    for (int j = 0; j < 8; j++){
        const int col = h*Dn + j*8 + (lane&3)*2;
        if (r0 < Nn)
            store_pair(g_aoh, g_aol, (size_t)(bb*Nn + r0)*Cn + col,
                       o[j][0]*inv0, o[j][1]*inv0);
        if (r1 < Nn)
            store_pair(g_aoh, g_aol, (size_t)(bb*Nn + r1)*Cn + col,
                       o[j][2]*inv1, o[j][3]*inv1);
    }
}

// ---------------------------------------------------------------------------
extern "C" void kernel_launch(void* const* d_in, const int* in_sizes, int n_in,
                              void* d_out, int out_size)
{
    (void)in_sizes; (void)n_in; (void)out_size;
    const float* x      = (const float*)d_in[0];
    const float* w_qkv  = (const float*)d_in[1];
    const float* w_proj = (const float*)d_in[2];
    const float* b_proj = (const float*)d_in[3];
    const float* cosb   = (const float*)d_in[4];
    const float* sinb   = (const float*)d_in[5];
    float* out = (float*)d_out;

    cudaFuncSetAttribute(gemm_bb<0>, cudaFuncAttributeMaxDynamicSharedMemorySize, SMEM_G);
    cudaFuncSetAttribute(gemm_bb<1>, cudaFuncAttributeMaxDynamicSharedMemorySize, SMEM_G);
    cudaFuncSetAttribute(attn_tc,    cudaFuncAttributeMaxDynamicSharedMemorySize, AT_SMEM);

    __nv_bfloat16 *xh, *xl, *wqh, *wql, *wph, *wpl, *aoh, *aol;
    cudaGetSymbolAddress((void**)&xh,  g_xh);  cudaGetSymbolAddress((void**)&xl,  g_xl);
    cudaGetSymbolAddress((void**)&wqh, g_wqh); cudaGetSymbolAddress((void**)&wql, g_wql);
    cudaGetSymbolAddress((void**)&wph, g_wph); cudaGetSymbolAddress((void**)&wpl, g_wpl);
    cudaGetSymbolAddress((void**)&aoh, g_aoh); cudaGetSymbolAddress((void**)&aol, g_aol);

    const int nx = Mn*Cn, nwq = QKV_N*Cn, nwp = Cn*Cn;
    split_k<<<(nx/4 + 255)/256, 256>>>(x, xh, xl, nx);
    split_k<<<(nwq/4 + 255)/256, 256>>>(w_qkv, wqh, wql, nwq);
    split_k<<<(nwp/4 + 255)/256, 256>>>(w_proj, wph, wpl, nwp);

    const int MT = (Mn + 127) / 128;   // 145
    gemm_bb<0><<<dim3(QKV_N/128, MT), 256, SMEM_G>>>(xh, xl, wqh, wql,
                                                     cosb, sinb, nullptr, nullptr);
    attn_tc<<<dim3((Nn+127)/128, Bn*Hn), 256, AT_SMEM>>>();
    gemm_bb<1><<<dim3(Cn/128, MT), 256, SMEM_G>>>(aoh, aol, wph, wpl,
                                                  nullptr, nullptr, b_proj, out);
}

// round 7
// speedup vs baseline: 1.4161x; 1.1539x over previous
#include <cuda_runtime.h>
#include <cuda_bf16.h>
#include <cstdint>

#define Bn 32
#define Nn 577
#define Cn 768
#define Hn 12
#define Dn 64
#define Mn (Bn*Nn)          // 18464
#define QKV_N (3*Cn)        // 2304
#define BHD ((size_t)Bn*Hn*Nn*Dn)   // 14,180,352

// Scratch (__device__ globals) — bf16 hi/lo pairs everywhere
__device__ __align__(16) __nv_bfloat16 g_xh[(size_t)Mn*Cn],  g_xl[(size_t)Mn*Cn];
__device__ __align__(16) __nv_bfloat16 g_wqh[(size_t)QKV_N*Cn], g_wql[(size_t)QKV_N*Cn];
__device__ __align__(16) __nv_bfloat16 g_wph[(size_t)Cn*Cn], g_wpl[(size_t)Cn*Cn];
__device__ __align__(16) __nv_bfloat16 g_qh[BHD], g_ql[BHD];
__device__ __align__(16) __nv_bfloat16 g_kh[BHD], g_kl[BHD];
__device__ __align__(16) __nv_bfloat16 g_vh[BHD], g_vl[BHD];
__device__ __align__(16) __nv_bfloat16 g_aoh[(size_t)Mn*Cn], g_aol[(size_t)Mn*Cn];

// ---------------------------------------------------------------------------
// helpers
// ---------------------------------------------------------------------------
__device__ __forceinline__ uint32_t smem_u32(const void* p){
    uint32_t a;
    asm("{ .reg .u64 t; cvta.to.shared.u64 t, %1; cvt.u32.u64 %0, t; }"
        : "=r"(a) : "l"(p));
    return a;
}
__device__ __forceinline__ void ldsm4(uint32_t (&r)[4], uint32_t a){
    asm volatile("ldmatrix.sync.aligned.m8n8.x4.shared.b16 {%0,%1,%2,%3}, [%4];"
        : "=r"(r[0]),"=r"(r[1]),"=r"(r[2]),"=r"(r[3]) : "r"(a));
}
__device__ __forceinline__ void ldsm4t(uint32_t (&r)[4], uint32_t a){
    asm volatile("ldmatrix.sync.aligned.m8n8.x4.trans.shared.b16 {%0,%1,%2,%3}, [%4];"
        : "=r"(r[0]),"=r"(r[1]),"=r"(r[2]),"=r"(r[3]) : "r"(a));
}
__device__ __forceinline__ void mma16816(float* c, const uint32_t* a,
                                         uint32_t b0, uint32_t b1){
    asm volatile("mma.sync.aligned.m16n8k16.row.col.f32.bf16.bf16.f32 "
        "{%0,%1,%2,%3}, {%4,%5,%6,%7}, {%8,%9}, {%0,%1,%2,%3};"
        : "+f"(c[0]),"+f"(c[1]),"+f"(c[2]),"+f"(c[3])
        : "r"(a[0]),"r"(a[1]),"r"(a[2]),"r"(a[3]), "r"(b0),"r"(b1));
}
__device__ __forceinline__ void cpa(uint32_t s, const void* g, uint32_t n){
    asm volatile("cp.async.cg.shared.global [%0], [%1], 16, %2;"
                 :: "r"(s), "l"(g), "r"(n) : "memory");
}
__device__ __forceinline__ uint32_t packbf(float x, float y){
    __nv_bfloat162 t = __floats2bfloat162_rn(x, y);
    return *reinterpret_cast<uint32_t*>(&t);
}
__device__ __forceinline__ void store_pair(__nv_bfloat16* dh, __nv_bfloat16* dl,
                                           size_t idx, float v1, float v2){
    const __nv_bfloat16 h1 = __float2bfloat16(v1), h2 = __float2bfloat16(v2);
    uint32_t hp; { __nv_bfloat162 t; t.x=h1; t.y=h2; hp=*reinterpret_cast<uint32_t*>(&t); }
    *reinterpret_cast<uint32_t*>(dh + idx) = hp;
    *reinterpret_cast<uint32_t*>(dl + idx) =
        packbf(v1 - __bfloat162float(h1), v2 - __bfloat162float(h2));
}

// ---------------------------------------------------------------------------
// split: fp32 -> bf16 hi + bf16 lo (residual)
// ---------------------------------------------------------------------------
__global__ __launch_bounds__(256) void split_k(
    const float* __restrict__ s, __nv_bfloat16* __restrict__ dh,
    __nv_bfloat16* __restrict__ dl, int n)
{
    const int i = (blockIdx.x*256 + threadIdx.x)*4;
    if (i < n){
        float4 v = *(const float4*)(s + i);
        const float hx = __bfloat162float(__float2bfloat16(v.x));
        const float hy = __bfloat162float(__float2bfloat16(v.y));
        const float hz = __bfloat162float(__float2bfloat16(v.z));
        const float hw = __bfloat162float(__float2bfloat16(v.w));
        *(uint2*)(dh + i) = make_uint2(packbf(v.x, v.y), packbf(v.z, v.w));
        *(uint2*)(dl + i) = make_uint2(packbf(v.x-hx, v.y-hy), packbf(v.z-hz, v.w-hw));
    }
}

// ---------------------------------------------------------------------------
// HMMA bf16x3 GEMM, cp.async pipeline, 64B-row swizzled tiles, k-stage 32.
// 96KB smem/CTA -> 2 CTAs/SM. D[128x128] = A[M,768] @ B[N,768]^T, 3 terms.
// EPI==0: epilogue RoPE + q-scale -> bf16 q/k/v.  EPI==1: +bias -> fp32 Out.
// ---------------------------------------------------------------------------
#define KS 32
#define NSTG (Cn/KS)         // 24
#define TILE8K 8192
#define STG_B (4*TILE8K)     // 32768 : Ah|Al|Bh|Bl
#define NPIPE 3
#define SMEM_G (NPIPE*STG_B) // 98304

// swizzled byte offset within a 128x(32bf16) tile
#define SWZ(row_, grp_) ((uint32_t)(row_)*64u + ((((uint32_t)(grp_)) ^ (((uint32_t)(row_)>>1)&3u))<<4))

template<int EPI>
__global__ __launch_bounds__(256,2) void gemm_bb(
    const __nv_bfloat16* __restrict__ Ah, const __nv_bfloat16* __restrict__ Al,
    const __nv_bfloat16* __restrict__ Bh, const __nv_bfloat16* __restrict__ Bl,
    const float* __restrict__ cosb, const float* __restrict__ sinb,
    const float* __restrict__ bias, float* __restrict__ Out)
{
    extern __shared__ char sm[];
    const uint32_t smb = smem_u32(sm);

    const int tid  = threadIdx.x;
    const int wid  = tid >> 5;
    const int lane = tid & 31;
    const int m0 = blockIdx.y * 128;
    const int n0 = blockIdx.x * 128;

    const int wm = wid & 3;
    const int wn = wid >> 2;

    float acc[2][8][4];
#pragma unroll
    for (int im=0;im<2;im++)
#pragma unroll
        for (int j=0;j<8;j++)
#pragma unroll
            for (int q=0;q<4;q++) acc[im][j][q] = 0.f;

    // producer: 8 cp.async per thread per stage (2 rounds x 4 tensors)
#define ISSUE(s_, b_) do{ \
    const uint32_t bb_ = smb + (uint32_t)(b_)*STG_B; \
    const int kt_ = (s_)*KS; \
    _Pragma("unroll") \
    for (int r_ = 0; r_ < 2; r_++){ \
        const int idx_ = tid + r_*256; \
        const uint32_t row_ = (uint32_t)(idx_ >> 2); \
        const uint32_t grp_ = (uint32_t)(idx_ & 3); \
        const uint32_t dst_ = bb_ + SWZ(row_, grp_); \
        const uint32_t an_  = ((int)(m0 + row_) < Mn) ? 16u : 0u; \
        const size_t aoff_ = (size_t)(m0 + row_)*Cn + kt_ + grp_*8; \
        const size_t boff_ = (size_t)(n0 + row_)*Cn + kt_ + grp_*8; \
        cpa(dst_,            Ah + aoff_, an_); \
        cpa(dst_ + TILE8K,   Al + aoff_, an_); \
        cpa(dst_ + 2*TILE8K, Bh + boff_, 16u); \
        cpa(dst_ + 3*TILE8K, Bl + boff_, 16u); \
    } \
    asm volatile("cp.async.commit_group;":::"memory"); \
}while(0)

    ISSUE(0, 0);
    ISSUE(1, 1);
    ISSUE(2, 2);

    const uint32_t ar0 = (uint32_t)(wm*32 + (lane & 15));
    const uint32_t ar1 = ar0 + 16;
    const uint32_t brb = (uint32_t)(wn*64 + (lane & 7) + ((lane >> 4) << 3));

    for (int s = 0; s < NSTG; s++){
        asm volatile("cp.async.wait_group 2;":::"memory");
        __syncthreads();

        const uint32_t sb = smb + (uint32_t)(s % NPIPE)*STG_B;
#pragma unroll
        for (int kk = 0; kk < 2; kk++){
            const uint32_t gA = (uint32_t)(kk*2 + (lane >> 4));
            const uint32_t gB = (uint32_t)(kk*2 + ((lane >> 3) & 1));
            uint32_t ah[2][4], al[2][4], bhf[4][4], blf[4][4];
            ldsm4(ah[0], sb + SWZ(ar0, gA));
            ldsm4(ah[1], sb + SWZ(ar1, gA));
            ldsm4(al[0], sb + TILE8K + SWZ(ar0, gA));
            ldsm4(al[1], sb + TILE8K + SWZ(ar1, gA));
#pragma unroll
            for (int t2 = 0; t2 < 4; t2++){
                const uint32_t br = brb + (uint32_t)(t2*16);
                ldsm4(bhf[t2], sb + 2*TILE8K + SWZ(br, gB));
                ldsm4(blf[t2], sb + 3*TILE8K + SWZ(br, gB));
            }
#pragma unroll
            for (int im = 0; im < 2; im++)
#pragma unroll
                for (int j = 0; j < 8; j++)
                    mma16816(acc[im][j], ah[im],
                             bhf[j>>1][(j&1)*2], bhf[j>>1][(j&1)*2+1]);
#pragma unroll
            for (int im = 0; im < 2; im++)
#pragma unroll
                for (int j = 0; j < 8; j++)
                    mma16816(acc[im][j], al[im],
                             bhf[j>>1][(j&1)*2], bhf[j>>1][(j&1)*2+1]);
#pragma unroll
            for (int im = 0; im < 2; im++)
#pragma unroll
                for (int j = 0; j < 8; j++)
                    mma16816(acc[im][j], ah[im],
                             blf[j>>1][(j&1)*2], blf[j>>1][(j&1)*2+1]);
        }
        __syncthreads();
        if (s + NPIPE < NSTG) ISSUE(s + NPIPE, s % NPIPE);
    }
#undef ISSUE

    // ---------------- epilogue
    if (EPI == 0){
        // RoPE + q-scale, write bf16 hi/lo q/k/v in [B,H,N,D]
#pragma unroll
        for (int im = 0; im < 2; im++){
#pragma unroll
            for (int j = 0; j < 8; j++){
                const int cl = wn*64 + j*8 + (lane&3)*2;
#pragma unroll
                for (int rr = 0; rr < 2; rr++){
                    const int r = wm*32 + im*16 + (lane>>2) + rr*8;
                    const int m = m0 + r;
                    if (m >= Mn) continue;
                    float v1 = acc[im][j][rr*2+0];
                    float v2 = acc[im][j][rr*2+1];
                    const int gc  = n0 + cl;
                    const int sec = gc / Cn;
                    const int rem = gc - sec*Cn;
                    const int hh  = rem >> 6;
                    const int d   = rem & 63;
                    const int bb  = m / Nn;
                    const int n   = m - bb*Nn;
                    if (sec < 2 && n > 0){
                        const float cs = cosb[(n-1)*(Dn/2) + (d>>1)];
                        const float sn = sinb[(n-1)*(Dn/2) + (d>>1)];
                        const float r1 = v1*cs - v2*sn;
                        const float r2 = v1*sn + v2*cs;
                        v1 = r1; v2 = r2;
                    }
                    if (sec == 0){ v1 *= 0.125f; v2 *= 0.125f; }
                    const size_t idx = ((size_t)(bb*Hn + hh)*Nn + n)*Dn + d;
                    if (sec == 0)      store_pair(g_qh, g_ql, idx, v1, v2);
                    else if (sec == 1) store_pair(g_kh, g_kl, idx, v1, v2);
                    else               store_pair(g_vh, g_vl, idx, v1, v2);
                }
            }
        }
    } else {
        // bias + coalesced fp32 store via smem staging (96KB is enough: use 64 rows x2)
        float* Ds = (float*)sm;            // 128 x 132 floats = 67584 B <= 98304
#pragma unroll
        for (int im = 0; im < 2; im++){
#pragma unroll
            for (int j = 0; j < 8; j++){
                const int cl = wn*64 + j*8 + (lane&3)*2;
#pragma unroll
                for (int rr = 0; rr < 2; rr++){
                    const int r = wm*32 + im*16 + (lane>>2) + rr*8;
                    float v1 = acc[im][j][rr*2+0];
                    float v2 = acc[im][j][rr*2+1];
                    const int gc = n0 + cl;
                    v1 += bias[gc]; v2 += bias[gc+1];
                    Ds[r*132 + cl]   = v1;
                    Ds[r*132 + cl+1] = v2;
                }
            }
        }
        __syncthreads();
        const int row  = tid >> 1;
        const int half = tid & 1;
        const int m = m0 + row;
        if (m < Mn){
            float* dst = Out + (size_t)m*Cn + n0 + half*64;
            const float* src = &Ds[row*132 + half*64];
#pragma unroll
            for (int j = 0; j < 64; j += 4)
                *(float4*)&dst[j] = *(const float4*)&src[j];
        }
    }
}

// ---------------------------------------------------------------------------
// HMMA flash attention (same algorithm; allow 2 CTAs/SM)
// ---------------------------------------------------------------------------
#define AT_PITCH 144
#define AT_TILE  (64*AT_PITCH)       // 9216
#define AT_STAGE (4*AT_TILE)         // 36864
#define AT_SMEM  (2*AT_STAGE)        // 73728
#define NTkv ((Nn+63)/64)            // 10

__global__ __launch_bounds__(256,2) void attn_tc()
{
    extern __shared__ char sm[];
    const uint32_t smb = smem_u32(sm);
    const int tid  = threadIdx.x;
    const int wid  = tid >> 5;
    const int lane = tid & 31;
    const int qt   = blockIdx.x;
    const int bh   = blockIdx.y;
    const int bb   = bh / Hn;
    const int h    = bh - bb*Hn;

    const __nv_bfloat16* Qh = g_qh + (size_t)bh*Nn*Dn;
    const __nv_bfloat16* Ql = g_ql + (size_t)bh*Nn*Dn;
    const __nv_bfloat16* Kh = g_kh + (size_t)bh*Nn*Dn;
    const __nv_bfloat16* Kl = g_kl + (size_t)bh*Nn*Dn;
    const __nv_bfloat16* Vh = g_vh + (size_t)bh*Nn*Dn;
    const __nv_bfloat16* Vl = g_vl + (size_t)bh*Nn*Dn;

    {
#pragma unroll
        for (int i = 0; i < 4; i++){
            const int idx = tid + i*256;
            const int r   = idx >> 3;
            const int j   = idx & 7;
            const int gr  = qt*128 + r;
            uint4 vh = make_uint4(0,0,0,0), vl = vh;
            if (gr < Nn){
                vh = *(const uint4*)(Qh + (size_t)gr*Dn + j*8);
                vl = *(const uint4*)(Ql + (size_t)gr*Dn + j*8);
            }
            *(uint4*)(sm + r*AT_PITCH + j*16)         = vh;
            *(uint4*)(sm + 18432 + r*AT_PITCH + j*16) = vl;
        }
    }
    __syncthreads();
    uint32_t qfh[4][4], qfl[4][4];
    {
        const uint32_t qa = smb + (uint32_t)((wid*16 + (lane&15))*AT_PITCH + (lane>>4)*16);
#pragma unroll
        for (int kk = 0; kk < 4; kk++){
            ldsm4(qfh[kk], qa + kk*32);
            ldsm4(qfl[kk], qa + 18432 + kk*32);
        }
    }
    __syncthreads();

#define LOADKV(t_, buf_) do{ \
    const int kv0 = (t_)*64; \
    char* bp = sm + (size_t)(buf_)*AT_STAGE; \
    _Pragma("unroll") \
    for (int i_ = 0; i_ < 8; i_++){ \
        const int idx = tid + i_*256; \
        const int ts  = idx >> 9; \
        const int rem = idx & 511; \
        const int r_  = rem >> 3; \
        const int j_  = rem & 7; \
        const int gr  = kv0 + r_; \
        const __nv_bfloat16* src = (ts==0)?Kh:(ts==1)?Kl:(ts==2)?Vh:Vl; \
        uint4 v = make_uint4(0,0,0,0); \
        if (gr < Nn) v = *(const uint4*)(src + (size_t)gr*Dn + j_*8); \
        *(uint4*)(bp + ts*AT_TILE + r_*AT_PITCH + j_*16) = v; \
    } }while(0)

    LOADKV(0, 0);
    __syncthreads();

    float m0r = -1e30f, m1r = -1e30f, l0r = 0.f, l1r = 0.f;
    float o[8][4];
#pragma unroll
    for (int j=0;j<8;j++)
#pragma unroll
        for (int q=0;q<4;q++) o[j][q] = 0.f;

    for (int t = 0; t < NTkv; t++){
        if (t+1 < NTkv) LOADKV(t+1, (t+1)&1);

        const uint32_t sb = smb + (uint32_t)(t&1)*AT_STAGE;

        float s[8][4];
#pragma unroll
        for (int j=0;j<8;j++)
#pragma unroll
            for (int q=0;q<4;q++) s[j][q] = 0.f;

#pragma unroll
        for (int kk = 0; kk < 4; kk++){
            uint32_t kh[4][4], kl[4][4];
#pragma unroll
            for (int g = 0; g < 4; g++){
                const uint32_t ka = sb
                    + (uint32_t)((g*16 + (lane&7) + ((lane>>4)<<3))*AT_PITCH
                                 + ((lane>>3)&1)*16 + kk*32);
                ldsm4(kh[g], ka);
                ldsm4(kl[g], ka + AT_TILE);
            }
#pragma unroll
            for (int j = 0; j < 8; j++)
                mma16816(s[j], qfh[kk], kh[j>>1][(j&1)*2], kh[j>>1][(j&1)*2+1]);
#pragma unroll
            for (int j = 0; j < 8; j++)
                mma16816(s[j], qfl[kk], kh[j>>1][(j&1)*2], kh[j>>1][(j&1)*2+1]);
#pragma unroll
            for (int j = 0; j < 8; j++)
                mma16816(s[j], qfh[kk], kl[j>>1][(j&1)*2], kl[j>>1][(j&1)*2+1]);
        }

        if (t == NTkv-1){
#pragma unroll
            for (int j = 0; j < 8; j++){
                const int c0 = t*64 + j*8 + (lane&3)*2;
                if (c0   >= Nn){ s[j][0] = -1e30f; s[j][2] = -1e30f; }
                if (c0+1 >= Nn){ s[j][1] = -1e30f; s[j][3] = -1e30f; }
            }
        }
        float mx0 = -1e30f, mx1 = -1e30f;
#pragma unroll
        for (int j = 0; j < 8; j++){
            mx0 = fmaxf(mx0, fmaxf(s[j][0], s[j][1]));
            mx1 = fmaxf(mx1, fmaxf(s[j][2], s[j][3]));
        }
        mx0 = fmaxf(mx0, __shfl_xor_sync(0xffffffffu, mx0, 1));
        mx0 = fmaxf(mx0, __shfl_xor_sync(0xffffffffu, mx0, 2));
        mx1 = fmaxf(mx1, __shfl_xor_sync(0xffffffffu, mx1, 1));
        mx1 = fmaxf(mx1, __shfl_xor_sync(0xffffffffu, mx1, 2));
        const float mn0 = fmaxf(m0r, mx0), mn1 = fmaxf(m1r, mx1);
        const float al0 = __expf(m0r - mn0), al1 = __expf(m1r - mn1);
        float rs0 = 0.f, rs1 = 0.f;
#pragma unroll
        for (int j = 0; j < 8; j++){
            s[j][0] = __expf(s[j][0]-mn0); s[j][1] = __expf(s[j][1]-mn0);
            s[j][2] = __expf(s[j][2]-mn1); s[j][3] = __expf(s[j][3]-mn1);
            rs0 += s[j][0] + s[j][1];
            rs1 += s[j][2] + s[j][3];
        }
        rs0 += __shfl_xor_sync(0xffffffffu, rs0, 1);
        rs0 += __shfl_xor_sync(0xffffffffu, rs0, 2);
        rs1 += __shfl_xor_sync(0xffffffffu, rs1, 1);
        rs1 += __shfl_xor_sync(0xffffffffu, rs1, 2);
        l0r = l0r*al0 + rs0;  m0r = mn0;
        l1r = l1r*al1 + rs1;  m1r = mn1;
#pragma unroll
        for (int j = 0; j < 8; j++){
            o[j][0] *= al0; o[j][1] *= al0;
            o[j][2] *= al1; o[j][3] *= al1;
        }

#pragma unroll
        for (int kk = 0; kk < 4; kk++){
            uint32_t pha[4], pla[4];
            {
                const int j0 = 2*kk, j1 = 2*kk+1;
                float h0, h1;
                h0 = __bfloat162float(__float2bfloat16(s[j0][0]));
                h1 = __bfloat162float(__float2bfloat16(s[j0][1]));
                pha[0] = packbf(s[j0][0], s[j0][1]);
                pla[0] = packbf(s[j0][0]-h0, s[j0][1]-h1);
                h0 = __bfloat162float(__float2bfloat16(s[j0][2]));
                h1 = __bfloat162float(__float2bfloat16(s[j0][3]));
                pha[1] = packbf(s[j0][2], s[j0][3]);
                pla[1] = packbf(s[j0][2]-h0, s[j0][3]-h1);
                h0 = __bfloat162float(__float2bfloat16(s[j1][0]));
                h1 = __bfloat162float(__float2bfloat16(s[j1][1]));
                pha[2] = packbf(s[j1][0], s[j1][1]);
                pla[2] = packbf(s[j1][0]-h0, s[j1][1]-h1);
                h0 = __bfloat162float(__float2bfloat16(s[j1][2]));
                h1 = __bfloat162float(__float2bfloat16(s[j1][3]));
                pha[3] = packbf(s[j1][2], s[j1][3]);
                pla[3] = packbf(s[j1][2]-h0, s[j1][3]-h1);
            }
            uint32_t vh[4][4], vl[4][4];
#pragma unroll
            for (int g = 0; g < 4; g++){
                const uint32_t va = sb + 2*AT_TILE
                    + (uint32_t)((kk*16 + (lane&7) + ((lane>>3)&1)*8)*AT_PITCH
                                 + ((lane>>4)*8 + g*16)*2);
                ldsm4t(vh[g], va);
                ldsm4t(vl[g], va + AT_TILE);
            }
#pragma unroll
            for (int j = 0; j < 8; j++)
                mma16816(o[j], pha, vh[j>>1][(j&1)*2], vh[j>>1][(j&1)*2+1]);
#pragma unroll
            for (int j = 0; j < 8; j++)
                mma16816(o[j], pla, vh[j>>1][(j&1)*2], vh[j>>1][(j&1)*2+1]);
#pragma unroll
            for (int j = 0; j < 8; j++)
                mma16816(o[j], pha, vl[j>>1][(j&1)*2], vl[j>>1][(j&1)*2+1]);
        }
        __syncthreads();
    }
#undef LOADKV

    const float inv0 = 1.f / l0r, inv1 = 1.f / l1r;
    const int r0 = qt*128 + wid*16 + (lane>>2);
    const int r1 = r0 + 8;
#pragma unroll
    for (int j = 0; j < 8; j++){
        const int col = h*Dn + j*8 + (lane&3)*2;
        if (r0 < Nn)
            store_pair(g_aoh, g_aol, (size_t)(bb*Nn + r0)*Cn + col,
                       o[j][0]*inv0, o[j][1]*inv0);
        if (r1 < Nn)
            store_pair(g_aoh, g_aol, (size_t)(bb*Nn + r1)*Cn + col,
                       o[j][2]*inv1, o[j][3]*inv1);
    }
}

// ---------------------------------------------------------------------------
extern "C" void kernel_launch(void* const* d_in, const int* in_sizes, int n_in,
                              void* d_out, int out_size)
{
    (void)in_sizes; (void)n_in; (void)out_size;
    const float* x      = (const float*)d_in[0];
    const float* w_qkv  = (const float*)d_in[1];
    const float* w_proj = (const float*)d_in[2];
    const float* b_proj = (const float*)d_in[3];
    const float* cosb   = (const float*)d_in[4];
    const float* sinb   = (const float*)d_in[5];
    float* out = (float*)d_out;

    cudaFuncSetAttribute(gemm_bb<0>, cudaFuncAttributeMaxDynamicSharedMemorySize, SMEM_G);
    cudaFuncSetAttribute(gemm_bb<1>, cudaFuncAttributeMaxDynamicSharedMemorySize, SMEM_G);
    cudaFuncSetAttribute(attn_tc,    cudaFuncAttributeMaxDynamicSharedMemorySize, AT_SMEM);

    __nv_bfloat16 *xh, *xl, *wqh, *wql, *wph, *wpl, *aoh, *aol;
    cudaGetSymbolAddress((void**)&xh,  g_xh);  cudaGetSymbolAddress((void**)&xl,  g_xl);
    cudaGetSymbolAddress((void**)&wqh, g_wqh); cudaGetSymbolAddress((void**)&wql, g_wql);
    cudaGetSymbolAddress((void**)&wph, g_wph); cudaGetSymbolAddress((void**)&wpl, g_wpl);
    cudaGetSymbolAddress((void**)&aoh, g_aoh); cudaGetSymbolAddress((void**)&aol, g_aol);

    const int nx = Mn*Cn, nwq = QKV_N*Cn, nwp = Cn*Cn;
    split_k<<<(nx/4 + 255)/256, 256>>>(x, xh, xl, nx);
    split_k<<<(nwq/4 + 255)/256, 256>>>(w_qkv, wqh, wql, nwq);
    split_k<<<(nwp/4 + 255)/256, 256>>>(w_proj, wph, wpl, nwp);

    const int MT = (Mn + 127) / 128;   // 145
    gemm_bb<0><<<dim3(QKV_N/128, MT), 256, SMEM_G>>>(xh, xl, wqh, wql,
                                                     cosb, sinb, nullptr, nullptr);
    attn_tc<<<dim3((Nn+127)/128, Bn*Hn), 256, AT_SMEM>>>();
    gemm_bb<1><<<dim3(Cn/128, MT), 256, SMEM_G>>>(aoh, aol, wph, wpl,
                                                  nullptr, nullptr, b_proj, out);
}

// round 8
// speedup vs baseline: 1.6305x; 1.1514x over previous
#include <cuda_runtime.h>
#include <cuda_bf16.h>
#include <cuda_fp16.h>
#include <cstdint>

#define Bn 32
#define Nn 577
#define Cn 768
#define Hn 12
#define Dn 64
#define Mn (Bn*Nn)          // 18464
#define QKV_N (3*Cn)        // 2304
#define BHD ((size_t)Bn*Hn*Nn*Dn)   // 14,180,352

// Scratch (__device__ globals)
__device__ __align__(16) __half g_xh[(size_t)Mn*Cn], g_xl[(size_t)Mn*Cn];   // x split fp16
__device__ __align__(16) __half g_wq[(size_t)QKV_N*Cn];                      // w_qkv fp16
__device__ __align__(16) __nv_bfloat16 g_wph[(size_t)Cn*Cn], g_wpl[(size_t)Cn*Cn];
__device__ __align__(16) __nv_bfloat16 g_qh[BHD], g_ql[BHD];
__device__ __align__(16) __nv_bfloat16 g_kh[BHD], g_kl[BHD];
__device__ __align__(16) __nv_bfloat16 g_vh[BHD], g_vl[BHD];
__device__ __align__(16) __nv_bfloat16 g_aoh[(size_t)Mn*Cn], g_aol[(size_t)Mn*Cn];

// ---------------------------------------------------------------------------
// helpers
// ---------------------------------------------------------------------------
__device__ __forceinline__ uint32_t smem_u32(const void* p){
    uint32_t a;
    asm("{ .reg .u64 t; cvta.to.shared.u64 t, %1; cvt.u32.u64 %0, t; }"
        : "=r"(a) : "l"(p));
    return a;
}
__device__ __forceinline__ void ldsm4(uint32_t (&r)[4], uint32_t a){
    asm volatile("ldmatrix.sync.aligned.m8n8.x4.shared.b16 {%0,%1,%2,%3}, [%4];"
        : "=r"(r[0]),"=r"(r[1]),"=r"(r[2]),"=r"(r[3]) : "r"(a));
}
__device__ __forceinline__ void ldsm4t(uint32_t (&r)[4], uint32_t a){
    asm volatile("ldmatrix.sync.aligned.m8n8.x4.trans.shared.b16 {%0,%1,%2,%3}, [%4];"
        : "=r"(r[0]),"=r"(r[1]),"=r"(r[2]),"=r"(r[3]) : "r"(a));
}
__device__ __forceinline__ void mma16816(float* c, const uint32_t* a,
                                         uint32_t b0, uint32_t b1){
    asm volatile("mma.sync.aligned.m16n8k16.row.col.f32.bf16.bf16.f32 "
        "{%0,%1,%2,%3}, {%4,%5,%6,%7}, {%8,%9}, {%0,%1,%2,%3};"
        : "+f"(c[0]),"+f"(c[1]),"+f"(c[2]),"+f"(c[3])
        : "r"(a[0]),"r"(a[1]),"r"(a[2]),"r"(a[3]), "r"(b0),"r"(b1));
}
__device__ __forceinline__ void mma16816h(float* c, const uint32_t* a,
                                          uint32_t b0, uint32_t b1){
    asm volatile("mma.sync.aligned.m16n8k16.row.col.f32.f16.f16.f32 "
        "{%0,%1,%2,%3}, {%4,%5,%6,%7}, {%8,%9}, {%0,%1,%2,%3};"
        : "+f"(c[0]),"+f"(c[1]),"+f"(c[2]),"+f"(c[3])
        : "r"(a[0]),"r"(a[1]),"r"(a[2]),"r"(a[3]), "r"(b0),"r"(b1));
}
__device__ __forceinline__ void cpa(uint32_t s, const void* g, uint32_t n){
    asm volatile("cp.async.cg.shared.global [%0], [%1], 16, %2;"
                 :: "r"(s), "l"(g), "r"(n) : "memory");
}
__device__ __forceinline__ uint32_t packbf(float x, float y){
    __nv_bfloat162 t = __floats2bfloat162_rn(x, y);
    return *reinterpret_cast<uint32_t*>(&t);
}
__device__ __forceinline__ uint32_t packh(float x, float y){
    __half2 t = __floats2half2_rn(x, y);
    return *reinterpret_cast<uint32_t*>(&t);
}
__device__ __forceinline__ void store_pair(__nv_bfloat16* dh, __nv_bfloat16* dl,
                                           size_t idx, float v1, float v2){
    const __nv_bfloat16 h1 = __float2bfloat16(v1), h2 = __float2bfloat16(v2);
    uint32_t hp; { __nv_bfloat162 t; t.x=h1; t.y=h2; hp=*reinterpret_cast<uint32_t*>(&t); }
    *reinterpret_cast<uint32_t*>(dh + idx) = hp;
    *reinterpret_cast<uint32_t*>(dl + idx) =
        packbf(v1 - __bfloat162float(h1), v2 - __bfloat162float(h2));
}

// ---------------------------------------------------------------------------
// conversion kernels
// ---------------------------------------------------------------------------
__global__ __launch_bounds__(256) void split_bf(
    const float* __restrict__ s, __nv_bfloat16* __restrict__ dh,
    __nv_bfloat16* __restrict__ dl, int n)
{
    const int i = (blockIdx.x*256 + threadIdx.x)*4;
    if (i < n){
        float4 v = *(const float4*)(s + i);
        const float hx = __bfloat162float(__float2bfloat16(v.x));
        const float hy = __bfloat162float(__float2bfloat16(v.y));
        const float hz = __bfloat162float(__float2bfloat16(v.z));
        const float hw = __bfloat162float(__float2bfloat16(v.w));
        *(uint2*)(dh + i) = make_uint2(packbf(v.x, v.y), packbf(v.z, v.w));
        *(uint2*)(dl + i) = make_uint2(packbf(v.x-hx, v.y-hy), packbf(v.z-hz, v.w-hw));
    }
}
__global__ __launch_bounds__(256) void split_h(
    const float* __restrict__ s, __half* __restrict__ dh,
    __half* __restrict__ dl, int n)
{
    const int i = (blockIdx.x*256 + threadIdx.x)*4;
    if (i < n){
        float4 v = *(const float4*)(s + i);
        const float hx = __half2float(__float2half_rn(v.x));
        const float hy = __half2float(__float2half_rn(v.y));
        const float hz = __half2float(__float2half_rn(v.z));
        const float hw = __half2float(__float2half_rn(v.w));
        *(uint2*)(dh + i) = make_uint2(packh(v.x, v.y), packh(v.z, v.w));
        *(uint2*)(dl + i) = make_uint2(packh(v.x-hx, v.y-hy), packh(v.z-hz, v.w-hw));
    }
}
__global__ __launch_bounds__(256) void cvt_h(
    const float* __restrict__ s, __half* __restrict__ d, int n)
{
    const int i = (blockIdx.x*256 + threadIdx.x)*4;
    if (i < n){
        float4 v = *(const float4*)(s + i);
        *(uint2*)(d + i) = make_uint2(packh(v.x, v.y), packh(v.z, v.w));
    }
}

// swizzled byte offset within a 128x(32x2B) tile
#define SWZ(row_, grp_) ((uint32_t)(row_)*64u + ((((uint32_t)(grp_)) ^ (((uint32_t)(row_)>>1)&3u))<<4))

#define KS 32
#define NSTG (Cn/KS)         // 24
#define TILE8K 8192

// ---------------------------------------------------------------------------
// QKV GEMM: fp16 2-term (Ah·B + Al·B), 4-deep cp.async pipe, 2 CTAs/SM.
// Epilogue: RoPE + q-scale -> bf16 hi/lo q/k/v in [B,H,N,D].
// ---------------------------------------------------------------------------
#define QSTG_B (3*TILE8K)     // 24576 : Ah|Al|Bh
#define QNPIPE 4
#define SMEM_Q (QNPIPE*QSTG_B) // 98304

__global__ __launch_bounds__(256,2) void gemm_qkv(
    const __half* __restrict__ Ah, const __half* __restrict__ Al,
    const __half* __restrict__ Bh,
    const float* __restrict__ cosb, const float* __restrict__ sinb)
{
    extern __shared__ char sm[];
    const uint32_t smb = smem_u32(sm);

    const int tid  = threadIdx.x;
    const int wid  = tid >> 5;
    const int lane = tid & 31;
    const int m0 = blockIdx.y * 128;
    const int n0 = blockIdx.x * 128;
    const int wm = wid & 3;
    const int wn = wid >> 2;

    float acc[2][8][4];
#pragma unroll
    for (int im=0;im<2;im++)
#pragma unroll
        for (int j=0;j<8;j++)
#pragma unroll
            for (int q=0;q<4;q++) acc[im][j][q] = 0.f;

#define QISSUE(s_, b_) do{ \
    const uint32_t bb_ = smb + (uint32_t)(b_)*QSTG_B; \
    const int kt_ = (s_)*KS; \
    _Pragma("unroll") \
    for (int r_ = 0; r_ < 2; r_++){ \
        const int idx_ = tid + r_*256; \
        const uint32_t row_ = (uint32_t)(idx_ >> 2); \
        const uint32_t grp_ = (uint32_t)(idx_ & 3); \
        const uint32_t dst_ = bb_ + SWZ(row_, grp_); \
        const uint32_t an_  = ((int)(m0 + row_) < Mn) ? 16u : 0u; \
        const size_t aoff_ = (size_t)(m0 + row_)*Cn + kt_ + grp_*8; \
        const size_t boff_ = (size_t)(n0 + row_)*Cn + kt_ + grp_*8; \
        cpa(dst_,            Ah + aoff_, an_); \
        cpa(dst_ + TILE8K,   Al + aoff_, an_); \
        cpa(dst_ + 2*TILE8K, Bh + boff_, 16u); \
    } \
    asm volatile("cp.async.commit_group;":::"memory"); \
}while(0)

    QISSUE(0, 0);
    QISSUE(1, 1);
    QISSUE(2, 2);

    const uint32_t ar0 = (uint32_t)(wm*32 + (lane & 15));
    const uint32_t ar1 = ar0 + 16;
    const uint32_t brb = (uint32_t)(wn*64 + (lane & 7) + ((lane >> 4) << 3));

    for (int s = 0; s < NSTG; s++){
        asm volatile("cp.async.wait_group 2;":::"memory");
        __syncthreads();

        const uint32_t sb = smb + (uint32_t)(s % QNPIPE)*QSTG_B;
#pragma unroll
        for (int kk = 0; kk < 2; kk++){
            const uint32_t gA = (uint32_t)(kk*2 + (lane >> 4));
            const uint32_t gB = (uint32_t)(kk*2 + ((lane >> 3) & 1));
            uint32_t ah[2][4], al[2][4], bhf[4][4];
            ldsm4(ah[0], sb + SWZ(ar0, gA));
            ldsm4(ah[1], sb + SWZ(ar1, gA));
            ldsm4(al[0], sb + TILE8K + SWZ(ar0, gA));
            ldsm4(al[1], sb + TILE8K + SWZ(ar1, gA));
#pragma unroll
            for (int t2 = 0; t2 < 4; t2++){
                const uint32_t br = brb + (uint32_t)(t2*16);
                ldsm4(bhf[t2], sb + 2*TILE8K + SWZ(br, gB));
            }
#pragma unroll
            for (int im = 0; im < 2; im++)
#pragma unroll
                for (int j = 0; j < 8; j++)
                    mma16816h(acc[im][j], ah[im],
                              bhf[j>>1][(j&1)*2], bhf[j>>1][(j&1)*2+1]);
#pragma unroll
            for (int im = 0; im < 2; im++)
#pragma unroll
                for (int j = 0; j < 8; j++)
                    mma16816h(acc[im][j], al[im],
                              bhf[j>>1][(j&1)*2], bhf[j>>1][(j&1)*2+1]);
        }
        __syncthreads();
        if (s + 3 < NSTG) QISSUE(s + 3, (s + 3) % QNPIPE);
    }
#undef QISSUE

    // epilogue: RoPE + q-scale, write bf16 hi/lo q/k/v in [B,H,N,D]
#pragma unroll
    for (int im = 0; im < 2; im++){
#pragma unroll
        for (int j = 0; j < 8; j++){
            const int cl = wn*64 + j*8 + (lane&3)*2;
#pragma unroll
            for (int rr = 0; rr < 2; rr++){
                const int r = wm*32 + im*16 + (lane>>2) + rr*8;
                const int m = m0 + r;
                if (m >= Mn) continue;
                float v1 = acc[im][j][rr*2+0];
                float v2 = acc[im][j][rr*2+1];
                const int gc  = n0 + cl;
                const int sec = gc / Cn;
                const int rem = gc - sec*Cn;
                const int hh  = rem >> 6;
                const int d   = rem & 63;
                const int bb  = m / Nn;
                const int n   = m - bb*Nn;
                if (sec < 2 && n > 0){
                    const float cs = cosb[(n-1)*(Dn/2) + (d>>1)];
                    const float sn = sinb[(n-1)*(Dn/2) + (d>>1)];
                    const float r1 = v1*cs - v2*sn;
                    const float r2 = v1*sn + v2*cs;
                    v1 = r1; v2 = r2;
                }
                if (sec == 0){ v1 *= 0.125f; v2 *= 0.125f; }
                const size_t idx = ((size_t)(bb*Hn + hh)*Nn + n)*Dn + d;
                if (sec == 0)      store_pair(g_qh, g_ql, idx, v1, v2);
                else if (sec == 1) store_pair(g_kh, g_kl, idx, v1, v2);
                else               store_pair(g_vh, g_vl, idx, v1, v2);
            }
        }
    }
}

// ---------------------------------------------------------------------------
// Proj GEMM: bf16 3-term (unchanged numerics), k-stage 32, 2 CTAs/SM.
// ---------------------------------------------------------------------------
#define STG_B (4*TILE8K)     // 32768 : Ah|Al|Bh|Bl
#define NPIPE 3
#define SMEM_G (NPIPE*STG_B) // 98304

__global__ __launch_bounds__(256,2) void gemm_proj(
    const __nv_bfloat16* __restrict__ Ah, const __nv_bfloat16* __restrict__ Al,
    const __nv_bfloat16* __restrict__ Bh, const __nv_bfloat16* __restrict__ Bl,
    const float* __restrict__ bias, float* __restrict__ Out)
{
    extern __shared__ char sm[];
    const uint32_t smb = smem_u32(sm);

    const int tid  = threadIdx.x;
    const int wid  = tid >> 5;
    const int lane = tid & 31;
    const int m0 = blockIdx.y * 128;
    const int n0 = blockIdx.x * 128;
    const int wm = wid & 3;
    const int wn = wid >> 2;

    float acc[2][8][4];
#pragma unroll
    for (int im=0;im<2;im++)
#pragma unroll
        for (int j=0;j<8;j++)
#pragma unroll
            for (int q=0;q<4;q++) acc[im][j][q] = 0.f;

#define PISSUE(s_, b_) do{ \
    const uint32_t bb_ = smb + (uint32_t)(b_)*STG_B; \
    const int kt_ = (s_)*KS; \
    _Pragma("unroll") \
    for (int r_ = 0; r_ < 2; r_++){ \
        const int idx_ = tid + r_*256; \
        const uint32_t row_ = (uint32_t)(idx_ >> 2); \
        const uint32_t grp_ = (uint32_t)(idx_ & 3); \
        const uint32_t dst_ = bb_ + SWZ(row_, grp_); \
        const uint32_t an_  = ((int)(m0 + row_) < Mn) ? 16u : 0u; \
        const size_t aoff_ = (size_t)(m0 + row_)*Cn + kt_ + grp_*8; \
        const size_t boff_ = (size_t)(n0 + row_)*Cn + kt_ + grp_*8; \
        cpa(dst_,            Ah + aoff_, an_); \
        cpa(dst_ + TILE8K,   Al + aoff_, an_); \
        cpa(dst_ + 2*TILE8K, Bh + boff_, 16u); \
        cpa(dst_ + 3*TILE8K, Bl + boff_, 16u); \
    } \
    asm volatile("cp.async.commit_group;":::"memory"); \
}while(0)

    PISSUE(0, 0);
    PISSUE(1, 1);
    PISSUE(2, 2);

    const uint32_t ar0 = (uint32_t)(wm*32 + (lane & 15));
    const uint32_t ar1 = ar0 + 16;
    const uint32_t brb = (uint32_t)(wn*64 + (lane & 7) + ((lane >> 4) << 3));

    for (int s = 0; s < NSTG; s++){
        asm volatile("cp.async.wait_group 2;":::"memory");
        __syncthreads();

        const uint32_t sb = smb + (uint32_t)(s % NPIPE)*STG_B;
#pragma unroll
        for (int kk = 0; kk < 2; kk++){
            const uint32_t gA = (uint32_t)(kk*2 + (lane >> 4));
            const uint32_t gB = (uint32_t)(kk*2 + ((lane >> 3) & 1));
            uint32_t ah[2][4], al[2][4], bhf[4][4], blf[4][4];
            ldsm4(ah[0], sb + SWZ(ar0, gA));
            ldsm4(ah[1], sb + SWZ(ar1, gA));
            ldsm4(al[0], sb + TILE8K + SWZ(ar0, gA));
            ldsm4(al[1], sb + TILE8K + SWZ(ar1, gA));
#pragma unroll
            for (int t2 = 0; t2 < 4; t2++){
                const uint32_t br = brb + (uint32_t)(t2*16);
                ldsm4(bhf[t2], sb + 2*TILE8K + SWZ(br, gB));
                ldsm4(blf[t2], sb + 3*TILE8K + SWZ(br, gB));
            }
#pragma unroll
            for (int im = 0; im < 2; im++)
#pragma unroll
                for (int j = 0; j < 8; j++)
                    mma16816(acc[im][j], ah[im],
                             bhf[j>>1][(j&1)*2], bhf[j>>1][(j&1)*2+1]);
#pragma unroll
            for (int im = 0; im < 2; im++)
#pragma unroll
                for (int j = 0; j < 8; j++)
                    mma16816(acc[im][j], al[im],
                             bhf[j>>1][(j&1)*2], bhf[j>>1][(j&1)*2+1]);
#pragma unroll
            for (int im = 0; im < 2; im++)
#pragma unroll
                for (int j = 0; j < 8; j++)
                    mma16816(acc[im][j], ah[im],
                             blf[j>>1][(j&1)*2], blf[j>>1][(j&1)*2+1]);
        }
        __syncthreads();
        if (s + NPIPE < NSTG) PISSUE(s + NPIPE, s % NPIPE);
    }
#undef PISSUE

    float* Ds = (float*)sm;
#pragma unroll
    for (int im = 0; im < 2; im++){
#pragma unroll
        for (int j = 0; j < 8; j++){
            const int cl = wn*64 + j*8 + (lane&3)*2;
#pragma unroll
            for (int rr = 0; rr < 2; rr++){
                const int r = wm*32 + im*16 + (lane>>2) + rr*8;
                float v1 = acc[im][j][rr*2+0];
                float v2 = acc[im][j][rr*2+1];
                const int gc = n0 + cl;
                v1 += bias[gc]; v2 += bias[gc+1];
                Ds[r*132 + cl]   = v1;
                Ds[r*132 + cl+1] = v2;
            }
        }
    }
    __syncthreads();
    const int row  = tid >> 1;
    const int half = tid & 1;
    const int m = m0 + row;
    if (m < Mn){
        float* dst = Out + (size_t)m*Cn + n0 + half*64;
        const float* src = &Ds[row*132 + half*64];
#pragma unroll
        for (int j = 0; j < 64; j += 4)
            *(float4*)&dst[j] = *(const float4*)&src[j];
    }
}

// ---------------------------------------------------------------------------
// HMMA flash attention (unchanged, bf16x3)
// ---------------------------------------------------------------------------
#define AT_PITCH 144
#define AT_TILE  (64*AT_PITCH)
#define AT_STAGE (4*AT_TILE)
#define AT_SMEM  (2*AT_STAGE)
#define NTkv ((Nn+63)/64)

__global__ __launch_bounds__(256,2) void attn_tc()
{
    extern __shared__ char sm[];
    const uint32_t smb = smem_u32(sm);
    const int tid  = threadIdx.x;
    const int wid  = tid >> 5;
    const int lane = tid & 31;
    const int qt   = blockIdx.x;
    const int bh   = blockIdx.y;
    const int bb   = bh / Hn;
    const int h    = bh - bb*Hn;

    const __nv_bfloat16* Qh = g_qh + (size_t)bh*Nn*Dn;
    const __nv_bfloat16* Ql = g_ql + (size_t)bh*Nn*Dn;
    const __nv_bfloat16* Kh = g_kh + (size_t)bh*Nn*Dn;
    const __nv_bfloat16* Kl = g_kl + (size_t)bh*Nn*Dn;
    const __nv_bfloat16* Vh = g_vh + (size_t)bh*Nn*Dn;
    const __nv_bfloat16* Vl = g_vl + (size_t)bh*Nn*Dn;

    {
#pragma unroll
        for (int i = 0; i < 4; i++){
            const int idx = tid + i*256;
            const int r   = idx >> 3;
            const int j   = idx & 7;
            const int gr  = qt*128 + r;
            uint4 vh = make_uint4(0,0,0,0), vl = vh;
            if (gr < Nn){
                vh = *(const uint4*)(Qh + (size_t)gr*Dn + j*8);
                vl = *(const uint4*)(Ql + (size_t)gr*Dn + j*8);
            }
            *(uint4*)(sm + r*AT_PITCH + j*16)         = vh;
            *(uint4*)(sm + 18432 + r*AT_PITCH + j*16) = vl;
        }
    }
    __syncthreads();
    uint32_t qfh[4][4], qfl[4][4];
    {
        const uint32_t qa = smb + (uint32_t)((wid*16 + (lane&15))*AT_PITCH + (lane>>4)*16);
#pragma unroll
        for (int kk = 0; kk < 4; kk++){
            ldsm4(qfh[kk], qa + kk*32);
            ldsm4(qfl[kk], qa + 18432 + kk*32);
        }
    }
    __syncthreads();

#define LOADKV(t_, buf_) do{ \
    const int kv0 = (t_)*64; \
    char* bp = sm + (size_t)(buf_)*AT_STAGE; \
    _Pragma("unroll") \
    for (int i_ = 0; i_ < 8; i_++){ \
        const int idx = tid + i_*256; \
        const int ts  = idx >> 9; \
        const int rem = idx & 511; \
        const int r_  = rem >> 3; \
        const int j_  = rem & 7; \
        const int gr  = kv0 + r_; \
        const __nv_bfloat16* src = (ts==0)?Kh:(ts==1)?Kl:(ts==2)?Vh:Vl; \
        uint4 v = make_uint4(0,0,0,0); \
        if (gr < Nn) v = *(const uint4*)(src + (size_t)gr*Dn + j_*8); \
        *(uint4*)(bp + ts*AT_TILE + r_*AT_PITCH + j_*16) = v; \
    } }while(0)

    LOADKV(0, 0);
    __syncthreads();

    float m0r = -1e30f, m1r = -1e30f, l0r = 0.f, l1r = 0.f;
    float o[8][4];
#pragma unroll
    for (int j=0;j<8;j++)
#pragma unroll
        for (int q=0;q<4;q++) o[j][q] = 0.f;

    for (int t = 0; t < NTkv; t++){
        if (t+1 < NTkv) LOADKV(t+1, (t+1)&1);

        const uint32_t sb = smb + (uint32_t)(t&1)*AT_STAGE;

        float s[8][4];
#pragma unroll
        for (int j=0;j<8;j++)
#pragma unroll
            for (int q=0;q<4;q++) s[j][q] = 0.f;

#pragma unroll
        for (int kk = 0; kk < 4; kk++){
            uint32_t kh[4][4], kl[4][4];
#pragma unroll
            for (int g = 0; g < 4; g++){
                const uint32_t ka = sb
                    + (uint32_t)((g*16 + (lane&7) + ((lane>>4)<<3))*AT_PITCH
                                 + ((lane>>3)&1)*16 + kk*32);
                ldsm4(kh[g], ka);
                ldsm4(kl[g], ka + AT_TILE);
            }
#pragma unroll
            for (int j = 0; j < 8; j++)
                mma16816(s[j], qfh[kk], kh[j>>1][(j&1)*2], kh[j>>1][(j&1)*2+1]);
#pragma unroll
            for (int j = 0; j < 8; j++)
                mma16816(s[j], qfl[kk], kh[j>>1][(j&1)*2], kh[j>>1][(j&1)*2+1]);
#pragma unroll
            for (int j = 0; j < 8; j++)
                mma16816(s[j], qfh[kk], kl[j>>1][(j&1)*2], kl[j>>1][(j&1)*2+1]);
        }

        if (t == NTkv-1){
#pragma unroll
            for (int j = 0; j < 8; j++){
                const int c0 = t*64 + j*8 + (lane&3)*2;
                if (c0   >= Nn){ s[j][0] = -1e30f; s[j][2] = -1e30f; }
                if (c0+1 >= Nn){ s[j][1] = -1e30f; s[j][3] = -1e30f; }
            }
        }
        float mx0 = -1e30f, mx1 = -1e30f;
#pragma unroll
        for (int j = 0; j < 8; j++){
            mx0 = fmaxf(mx0, fmaxf(s[j][0], s[j][1]));
            mx1 = fmaxf(mx1, fmaxf(s[j][2], s[j][3]));
        }
        mx0 = fmaxf(mx0, __shfl_xor_sync(0xffffffffu, mx0, 1));
        mx0 = fmaxf(mx0, __shfl_xor_sync(0xffffffffu, mx0, 2));
        mx1 = fmaxf(mx1, __shfl_xor_sync(0xffffffffu, mx1, 1));
        mx1 = fmaxf(mx1, __shfl_xor_sync(0xffffffffu, mx1, 2));
        const float mn0 = fmaxf(m0r, mx0), mn1 = fmaxf(m1r, mx1);
        const float al0 = __expf(m0r - mn0), al1 = __expf(m1r - mn1);
        float rs0 = 0.f, rs1 = 0.f;
#pragma unroll
        for (int j = 0; j < 8; j++){
            s[j][0] = __expf(s[j][0]-mn0); s[j][1] = __expf(s[j][1]-mn0);
            s[j][2] = __expf(s[j][2]-mn1); s[j][3] = __expf(s[j][3]-mn1);
            rs0 += s[j][0] + s[j][1];
            rs1 += s[j][2] + s[j][3];
        }
        rs0 += __shfl_xor_sync(0xffffffffu, rs0, 1);
        rs0 += __shfl_xor_sync(0xffffffffu, rs0, 2);
        rs1 += __shfl_xor_sync(0xffffffffu, rs1, 1);
        rs1 += __shfl_xor_sync(0xffffffffu, rs1, 2);
        l0r = l0r*al0 + rs0;  m0r = mn0;
        l1r = l1r*al1 + rs1;  m1r = mn1;
#pragma unroll
        for (int j = 0; j < 8; j++){
            o[j][0] *= al0; o[j][1] *= al0;
            o[j][2] *= al1; o[j][3] *= al1;
        }

#pragma unroll
        for (int kk = 0; kk < 4; kk++){
            uint32_t pha[4], pla[4];
            {
                const int j0 = 2*kk, j1 = 2*kk+1;
                float h0, h1;
                h0 = __bfloat162float(__float2bfloat16(s[j0][0]));
                h1 = __bfloat162float(__float2bfloat16(s[j0][1]));
                pha[0] = packbf(s[j0][0], s[j0][1]);
                pla[0] = packbf(s[j0][0]-h0, s[j0][1]-h1);
                h0 = __bfloat162float(__float2bfloat16(s[j0][2]));
                h1 = __bfloat162float(__float2bfloat16(s[j0][3]));
                pha[1] = packbf(s[j0][2], s[j0][3]);
                pla[1] = packbf(s[j0][2]-h0, s[j0][3]-h1);
                h0 = __bfloat162float(__float2bfloat16(s[j1][0]));
                h1 = __bfloat162float(__float2bfloat16(s[j1][1]));
                pha[2] = packbf(s[j1][0], s[j1][1]);
                pla[2] = packbf(s[j1][0]-h0, s[j1][1]-h1);
                h0 = __bfloat162float(__float2bfloat16(s[j1][2]));
                h1 = __bfloat162float(__float2bfloat16(s[j1][3]));
                pha[3] = packbf(s[j1][2], s[j1][3]);
                pla[3] = packbf(s[j1][2]-h0, s[j1][3]-h1);
            }
            uint32_t vh[4][4], vl[4][4];
#pragma unroll
            for (int g = 0; g < 4; g++){
                const uint32_t va = sb + 2*AT_TILE
                    + (uint32_t)((kk*16 + (lane&7) + ((lane>>3)&1)*8)*AT_PITCH
                                 + ((lane>>4)*8 + g*16)*2);
                ldsm4t(vh[g], va);
                ldsm4t(vl[g], va + AT_TILE);
            }
#pragma unroll
            for (int j = 0; j < 8; j++)
                mma16816(o[j], pha, vh[j>>1][(j&1)*2], vh[j>>1][(j&1)*2+1]);
#pragma unroll
            for (int j = 0; j < 8; j++)
                mma16816(o[j], pla, vh[j>>1][(j&1)*2], vh[j>>1][(j&1)*2+1]);
#pragma unroll
            for (int j = 0; j < 8; j++)
                mma16816(o[j], pha, vl[j>>1][(j&1)*2], vl[j>>1][(j&1)*2+1]);
        }
        __syncthreads();
    }
#undef LOADKV

    const float inv0 = 1.f / l0r, inv1 = 1.f / l1r;
    const int r0 = qt*128 + wid*16 + (lane>>2);
    const int r1 = r0 + 8;
#pragma unroll
    for (int j = 0; j < 8; j++){
        const int col = h*Dn + j*8 + (lane&3)*2;
        if (r0 < Nn)
            store_pair(g_aoh, g_aol, (size_t)(bb*Nn + r0)*Cn + col,
                       o[j][0]*inv0, o[j][1]*inv0);
        if (r1 < Nn)
            store_pair(g_aoh, g_aol, (size_t)(bb*Nn + r1)*Cn + col,
                       o[j][2]*inv1, o[j][3]*inv1);
    }
}

// ---------------------------------------------------------------------------
extern "C" void kernel_launch(void* const* d_in, const int* in_sizes, int n_in,
                              void* d_out, int out_size)
{
    (void)in_sizes; (void)n_in; (void)out_size;
    const float* x      = (const float*)d_in[0];
    const float* w_qkv  = (const float*)d_in[1];
    const float* w_proj = (const float*)d_in[2];
    const float* b_proj = (const float*)d_in[3];
    const float* cosb   = (const float*)d_in[4];
    const float* sinb   = (const float*)d_in[5];
    float* out = (float*)d_out;

    cudaFuncSetAttribute(gemm_qkv,  cudaFuncAttributeMaxDynamicSharedMemorySize, SMEM_Q);
    cudaFuncSetAttribute(gemm_proj, cudaFuncAttributeMaxDynamicSharedMemorySize, SMEM_G);
    cudaFuncSetAttribute(attn_tc,   cudaFuncAttributeMaxDynamicSharedMemorySize, AT_SMEM);

    __half *xh, *xl, *wq;
    __nv_bfloat16 *wph, *wpl, *aoh, *aol;
    cudaGetSymbolAddress((void**)&xh,  g_xh);  cudaGetSymbolAddress((void**)&xl,  g_xl);
    cudaGetSymbolAddress((void**)&wq,  g_wq);
    cudaGetSymbolAddress((void**)&wph, g_wph); cudaGetSymbolAddress((void**)&wpl, g_wpl);
    cudaGetSymbolAddress((void**)&aoh, g_aoh); cudaGetSymbolAddress((void**)&aol, g_aol);

    const int nx = Mn*Cn, nwq = QKV_N*Cn, nwp = Cn*Cn;
    split_h<<<(nx/4 + 255)/256, 256>>>(x, xh, xl, nx);
    cvt_h<<<(nwq/4 + 255)/256, 256>>>(w_qkv, wq, nwq);
    split_bf<<<(nwp/4 + 255)/256, 256>>>(w_proj, wph, wpl, nwp);

    const int MT = (Mn + 127) / 128;   // 145
    gemm_qkv<<<dim3(QKV_N/128, MT), 256, SMEM_Q>>>(xh, xl, wq, cosb, sinb);
    attn_tc<<<dim3((Nn+127)/128, Bn*Hn), 256, AT_SMEM>>>();
    gemm_proj<<<dim3(Cn/128, MT), 256, SMEM_G>>>(aoh, aol, wph, wpl, b_proj, out);
}

// round 9
// speedup vs baseline: 1.8754x; 1.1502x over previous
#include <cuda_runtime.h>
#include <cuda_bf16.h>
#include <cuda_fp16.h>
#include <cstdint>

#define Bn 32
#define Nn 577
#define Cn 768
#define Hn 12
#define Dn 64
#define Mn (Bn*Nn)          // 18464
#define QKV_N (3*Cn)        // 2304
#define BHD ((size_t)Bn*Hn*Nn*Dn)   // 14,180,352

// Scratch (__device__ globals)
__device__ __align__(16) __half g_xh[(size_t)Mn*Cn], g_xl[(size_t)Mn*Cn];   // x split fp16
__device__ __align__(16) __half g_wq[(size_t)QKV_N*Cn];                      // w_qkv fp16
__device__ __align__(16) __nv_bfloat16 g_wph[(size_t)Cn*Cn], g_wpl[(size_t)Cn*Cn];
__device__ __align__(16) __half g_qh[BHD], g_ql[BHD];                        // Q fp16 hi/lo
__device__ __align__(16) __half g_k[BHD], g_v[BHD];                          // K,V fp16
__device__ __align__(16) __nv_bfloat16 g_aoh[(size_t)Mn*Cn], g_aol[(size_t)Mn*Cn];

// ---------------------------------------------------------------------------
// helpers
// ---------------------------------------------------------------------------
__device__ __forceinline__ uint32_t smem_u32(const void* p){
    uint32_t a;
    asm("{ .reg .u64 t; cvta.to.shared.u64 t, %1; cvt.u32.u64 %0, t; }"
        : "=r"(a) : "l"(p));
    return a;
}
__device__ __forceinline__ void ldsm4(uint32_t (&r)[4], uint32_t a){
    asm volatile("ldmatrix.sync.aligned.m8n8.x4.shared.b16 {%0,%1,%2,%3}, [%4];"
        : "=r"(r[0]),"=r"(r[1]),"=r"(r[2]),"=r"(r[3]) : "r"(a));
}
__device__ __forceinline__ void ldsm4t(uint32_t (&r)[4], uint32_t a){
    asm volatile("ldmatrix.sync.aligned.m8n8.x4.trans.shared.b16 {%0,%1,%2,%3}, [%4];"
        : "=r"(r[0]),"=r"(r[1]),"=r"(r[2]),"=r"(r[3]) : "r"(a));
}
__device__ __forceinline__ void mma16816(float* c, const uint32_t* a,
                                         uint32_t b0, uint32_t b1){
    asm volatile("mma.sync.aligned.m16n8k16.row.col.f32.bf16.bf16.f32 "
        "{%0,%1,%2,%3}, {%4,%5,%6,%7}, {%8,%9}, {%0,%1,%2,%3};"
        : "+f"(c[0]),"+f"(c[1]),"+f"(c[2]),"+f"(c[3])
        : "r"(a[0]),"r"(a[1]),"r"(a[2]),"r"(a[3]), "r"(b0),"r"(b1));
}
__device__ __forceinline__ void mma16816h(float* c, const uint32_t* a,
                                          uint32_t b0, uint32_t b1){
    asm volatile("mma.sync.aligned.m16n8k16.row.col.f32.f16.f16.f32 "
        "{%0,%1,%2,%3}, {%4,%5,%6,%7}, {%8,%9}, {%0,%1,%2,%3};"
        : "+f"(c[0]),"+f"(c[1]),"+f"(c[2]),"+f"(c[3])
        : "r"(a[0]),"r"(a[1]),"r"(a[2]),"r"(a[3]), "r"(b0),"r"(b1));
}
__device__ __forceinline__ void cpa(uint32_t s, const void* g, uint32_t n){
    asm volatile("cp.async.cg.shared.global [%0], [%1], 16, %2;"
                 :: "r"(s), "l"(g), "r"(n) : "memory");
}
__device__ __forceinline__ uint32_t packbf(float x, float y){
    __nv_bfloat162 t = __floats2bfloat162_rn(x, y);
    return *reinterpret_cast<uint32_t*>(&t);
}
__device__ __forceinline__ uint32_t packh(float x, float y){
    __half2 t = __floats2half2_rn(x, y);
    return *reinterpret_cast<uint32_t*>(&t);
}
__device__ __forceinline__ void store_pair(__nv_bfloat16* dh, __nv_bfloat16* dl,
                                           size_t idx, float v1, float v2){
    const __nv_bfloat16 h1 = __float2bfloat16(v1), h2 = __float2bfloat16(v2);
    uint32_t hp; { __nv_bfloat162 t; t.x=h1; t.y=h2; hp=*reinterpret_cast<uint32_t*>(&t); }
    *reinterpret_cast<uint32_t*>(dh + idx) = hp;
    *reinterpret_cast<uint32_t*>(dl + idx) =
        packbf(v1 - __bfloat162float(h1), v2 - __bfloat162float(h2));
}
__device__ __forceinline__ void store_pairh(__half* dh, __half* dl,
                                            size_t idx, float v1, float v2){
    const __half h1 = __float2half_rn(v1), h2 = __float2half_rn(v2);
    uint32_t hp; { __half2 t; t.x=h1; t.y=h2; hp=*reinterpret_cast<uint32_t*>(&t); }
    *reinterpret_cast<uint32_t*>(dh + idx) = hp;
    *reinterpret_cast<uint32_t*>(dl + idx) =
        packh(v1 - __half2float(h1), v2 - __half2float(h2));
}

// ---------------------------------------------------------------------------
// conversion kernels
// ---------------------------------------------------------------------------
__global__ __launch_bounds__(256) void split_bf(
    const float* __restrict__ s, __nv_bfloat16* __restrict__ dh,
    __nv_bfloat16* __restrict__ dl, int n)
{
    const int i = (blockIdx.x*256 + threadIdx.x)*4;
    if (i < n){
        float4 v = *(const float4*)(s + i);
        const float hx = __bfloat162float(__float2bfloat16(v.x));
        const float hy = __bfloat162float(__float2bfloat16(v.y));
        const float hz = __bfloat162float(__float2bfloat16(v.z));
        const float hw = __bfloat162float(__float2bfloat16(v.w));
        *(uint2*)(dh + i) = make_uint2(packbf(v.x, v.y), packbf(v.z, v.w));
        *(uint2*)(dl + i) = make_uint2(packbf(v.x-hx, v.y-hy), packbf(v.z-hz, v.w-hw));
    }
}
__global__ __launch_bounds__(256) void split_h(
    const float* __restrict__ s, __half* __restrict__ dh,
    __half* __restrict__ dl, int n)
{
    const int i = (blockIdx.x*256 + threadIdx.x)*4;
    if (i < n){
        float4 v = *(const float4*)(s + i);
        const float hx = __half2float(__float2half_rn(v.x));
        const float hy = __half2float(__float2half_rn(v.y));
        const float hz = __half2float(__float2half_rn(v.z));
        const float hw = __half2float(__float2half_rn(v.w));
        *(uint2*)(dh + i) = make_uint2(packh(v.x, v.y), packh(v.z, v.w));
        *(uint2*)(dl + i) = make_uint2(packh(v.x-hx, v.y-hy), packh(v.z-hz, v.w-hw));
    }
}
__global__ __launch_bounds__(256) void cvt_h(
    const float* __restrict__ s, __half* __restrict__ d, int n)
{
    const int i = (blockIdx.x*256 + threadIdx.x)*4;
    if (i < n){
        float4 v = *(const float4*)(s + i);
        *(uint2*)(d + i) = make_uint2(packh(v.x, v.y), packh(v.z, v.w));
    }
}

// swizzled byte offset within a 128x(32x2B) tile
#define SWZ(row_, grp_) ((uint32_t)(row_)*64u + ((((uint32_t)(grp_)) ^ (((uint32_t)(row_)>>1)&3u))<<4))

#define KS 32
#define NSTG (Cn/KS)         // 24
#define TILE8K 8192

// ---------------------------------------------------------------------------
// QKV GEMM: fp16 2-term (Ah·B + Al·B), 4-deep cp.async pipe, 2 CTAs/SM.
// Epilogue: RoPE + q-scale -> fp16 (q hi/lo; k,v single) in [B,H,N,D].
// ---------------------------------------------------------------------------
#define QSTG_B (3*TILE8K)     // 24576 : Ah|Al|Bh
#define QNPIPE 4
#define SMEM_Q (QNPIPE*QSTG_B) // 98304

__global__ __launch_bounds__(256,2) void gemm_qkv(
    const __half* __restrict__ Ah, const __half* __restrict__ Al,
    const __half* __restrict__ Bh,
    const float* __restrict__ cosb, const float* __restrict__ sinb)
{
    extern __shared__ char sm[];
    const uint32_t smb = smem_u32(sm);

    const int tid  = threadIdx.x;
    const int wid  = tid >> 5;
    const int lane = tid & 31;
    const int m0 = blockIdx.y * 128;
    const int n0 = blockIdx.x * 128;
    const int wm = wid & 3;
    const int wn = wid >> 2;

    float acc[2][8][4];
#pragma unroll
    for (int im=0;im<2;im++)
#pragma unroll
        for (int j=0;j<8;j++)
#pragma unroll
            for (int q=0;q<4;q++) acc[im][j][q] = 0.f;

#define QISSUE(s_, b_) do{ \
    const uint32_t bb_ = smb + (uint32_t)(b_)*QSTG_B; \
    const int kt_ = (s_)*KS; \
    _Pragma("unroll") \
    for (int r_ = 0; r_ < 2; r_++){ \
        const int idx_ = tid + r_*256; \
        const uint32_t row_ = (uint32_t)(idx_ >> 2); \
        const uint32_t grp_ = (uint32_t)(idx_ & 3); \
        const uint32_t dst_ = bb_ + SWZ(row_, grp_); \
        const uint32_t an_  = ((int)(m0 + row_) < Mn) ? 16u : 0u; \
        const size_t aoff_ = (size_t)(m0 + row_)*Cn + kt_ + grp_*8; \
        const size_t boff_ = (size_t)(n0 + row_)*Cn + kt_ + grp_*8; \
        cpa(dst_,            Ah + aoff_, an_); \
        cpa(dst_ + TILE8K,   Al + aoff_, an_); \
        cpa(dst_ + 2*TILE8K, Bh + boff_, 16u); \
    } \
    asm volatile("cp.async.commit_group;":::"memory"); \
}while(0)

    QISSUE(0, 0);
    QISSUE(1, 1);
    QISSUE(2, 2);

    const uint32_t ar0 = (uint32_t)(wm*32 + (lane & 15));
    const uint32_t ar1 = ar0 + 16;
    const uint32_t brb = (uint32_t)(wn*64 + (lane & 7) + ((lane >> 4) << 3));

    for (int s = 0; s < NSTG; s++){
        asm volatile("cp.async.wait_group 2;":::"memory");
        __syncthreads();

        const uint32_t sb = smb + (uint32_t)(s % QNPIPE)*QSTG_B;
#pragma unroll
        for (int kk = 0; kk < 2; kk++){
            const uint32_t gA = (uint32_t)(kk*2 + (lane >> 4));
            const uint32_t gB = (uint32_t)(kk*2 + ((lane >> 3) & 1));
            uint32_t ah[2][4], al[2][4], bhf[4][4];
            ldsm4(ah[0], sb + SWZ(ar0, gA));
            ldsm4(ah[1], sb + SWZ(ar1, gA));
            ldsm4(al[0], sb + TILE8K + SWZ(ar0, gA));
            ldsm4(al[1], sb + TILE8K + SWZ(ar1, gA));
#pragma unroll
            for (int t2 = 0; t2 < 4; t2++){
                const uint32_t br = brb + (uint32_t)(t2*16);
                ldsm4(bhf[t2], sb + 2*TILE8K + SWZ(br, gB));
            }
#pragma unroll
            for (int im = 0; im < 2; im++)
#pragma unroll
                for (int j = 0; j < 8; j++)
                    mma16816h(acc[im][j], ah[im],
                              bhf[j>>1][(j&1)*2], bhf[j>>1][(j&1)*2+1]);
#pragma unroll
            for (int im = 0; im < 2; im++)
#pragma unroll
                for (int j = 0; j < 8; j++)
                    mma16816h(acc[im][j], al[im],
                              bhf[j>>1][(j&1)*2], bhf[j>>1][(j&1)*2+1]);
        }
        __syncthreads();
        if (s + 3 < NSTG) QISSUE(s + 3, (s + 3) % QNPIPE);
    }
#undef QISSUE

    // epilogue: RoPE + q-scale -> fp16 q hi/lo, k/v single fp16, [B,H,N,D]
#pragma unroll
    for (int im = 0; im < 2; im++){
#pragma unroll
        for (int j = 0; j < 8; j++){
            const int cl = wn*64 + j*8 + (lane&3)*2;
#pragma unroll
            for (int rr = 0; rr < 2; rr++){
                const int r = wm*32 + im*16 + (lane>>2) + rr*8;
                const int m = m0 + r;
                if (m >= Mn) continue;
                float v1 = acc[im][j][rr*2+0];
                float v2 = acc[im][j][rr*2+1];
                const int gc  = n0 + cl;
                const int sec = gc / Cn;
                const int rem = gc - sec*Cn;
                const int hh  = rem >> 6;
                const int d   = rem & 63;
                const int bb  = m / Nn;
                const int n   = m - bb*Nn;
                if (sec < 2 && n > 0){
                    const float cs = cosb[(n-1)*(Dn/2) + (d>>1)];
                    const float sn = sinb[(n-1)*(Dn/2) + (d>>1)];
                    const float r1 = v1*cs - v2*sn;
                    const float r2 = v1*sn + v2*cs;
                    v1 = r1; v2 = r2;
                }
                if (sec == 0){ v1 *= 0.125f; v2 *= 0.125f; }
                const size_t idx = ((size_t)(bb*Hn + hh)*Nn + n)*Dn + d;
                if (sec == 0)      store_pairh(g_qh, g_ql, idx, v1, v2);
                else if (sec == 1) *reinterpret_cast<uint32_t*>(g_k + idx) = packh(v1, v2);
                else               *reinterpret_cast<uint32_t*>(g_v + idx) = packh(v1, v2);
            }
        }
    }
}

// ---------------------------------------------------------------------------
// Proj GEMM: bf16 3-term (unchanged numerics), k-stage 32, 2 CTAs/SM.
// ---------------------------------------------------------------------------
#define STG_B (4*TILE8K)     // 32768 : Ah|Al|Bh|Bl
#define NPIPE 3
#define SMEM_G (NPIPE*STG_B) // 98304

__global__ __launch_bounds__(256,2) void gemm_proj(
    const __nv_bfloat16* __restrict__ Ah, const __nv_bfloat16* __restrict__ Al,
    const __nv_bfloat16* __restrict__ Bh, const __nv_bfloat16* __restrict__ Bl,
    const float* __restrict__ bias, float* __restrict__ Out)
{
    extern __shared__ char sm[];
    const uint32_t smb = smem_u32(sm);

    const int tid  = threadIdx.x;
    const int wid  = tid >> 5;
    const int lane = tid & 31;
    const int m0 = blockIdx.y * 128;
    const int n0 = blockIdx.x * 128;
    const int wm = wid & 3;
    const int wn = wid >> 2;

    float acc[2][8][4];
#pragma unroll
    for (int im=0;im<2;im++)
#pragma unroll
        for (int j=0;j<8;j++)
#pragma unroll
            for (int q=0;q<4;q++) acc[im][j][q] = 0.f;

#define PISSUE(s_, b_) do{ \
    const uint32_t bb_ = smb + (uint32_t)(b_)*STG_B; \
    const int kt_ = (s_)*KS; \
    _Pragma("unroll") \
    for (int r_ = 0; r_ < 2; r_++){ \
        const int idx_ = tid + r_*256; \
        const uint32_t row_ = (uint32_t)(idx_ >> 2); \
        const uint32_t grp_ = (uint32_t)(idx_ & 3); \
        const uint32_t dst_ = bb_ + SWZ(row_, grp_); \
        const uint32_t an_  = ((int)(m0 + row_) < Mn) ? 16u : 0u; \
        const size_t aoff_ = (size_t)(m0 + row_)*Cn + kt_ + grp_*8; \
        const size_t boff_ = (size_t)(n0 + row_)*Cn + kt_ + grp_*8; \
        cpa(dst_,            Ah + aoff_, an_); \
        cpa(dst_ + TILE8K,   Al + aoff_, an_); \
        cpa(dst_ + 2*TILE8K, Bh + boff_, 16u); \
        cpa(dst_ + 3*TILE8K, Bl + boff_, 16u); \
    } \
    asm volatile("cp.async.commit_group;":::"memory"); \
}while(0)

    PISSUE(0, 0);
    PISSUE(1, 1);
    PISSUE(2, 2);

    const uint32_t ar0 = (uint32_t)(wm*32 + (lane & 15));
    const uint32_t ar1 = ar0 + 16;
    const uint32_t brb = (uint32_t)(wn*64 + (lane & 7) + ((lane >> 4) << 3));

    for (int s = 0; s < NSTG; s++){
        asm volatile("cp.async.wait_group 2;":::"memory");
        __syncthreads();

        const uint32_t sb = smb + (uint32_t)(s % NPIPE)*STG_B;
#pragma unroll
        for (int kk = 0; kk < 2; kk++){
            const uint32_t gA = (uint32_t)(kk*2 + (lane >> 4));
            const uint32_t gB = (uint32_t)(kk*2 + ((lane >> 3) & 1));
            uint32_t ah[2][4], al[2][4], bhf[4][4], blf[4][4];
            ldsm4(ah[0], sb + SWZ(ar0, gA));
            ldsm4(ah[1], sb + SWZ(ar1, gA));
            ldsm4(al[0], sb + TILE8K + SWZ(ar0, gA));
            ldsm4(al[1], sb + TILE8K + SWZ(ar1, gA));
#pragma unroll
            for (int t2 = 0; t2 < 4; t2++){
                const uint32_t br = brb + (uint32_t)(t2*16);
                ldsm4(bhf[t2], sb + 2*TILE8K + SWZ(br, gB));
                ldsm4(blf[t2], sb + 3*TILE8K + SWZ(br, gB));
            }
#pragma unroll
            for (int im = 0; im < 2; im++)
#pragma unroll
                for (int j = 0; j < 8; j++)
                    mma16816(acc[im][j], ah[im],
                             bhf[j>>1][(j&1)*2], bhf[j>>1][(j&1)*2+1]);
#pragma unroll
            for (int im = 0; im < 2; im++)
#pragma unroll
                for (int j = 0; j < 8; j++)
                    mma16816(acc[im][j], al[im],
                             bhf[j>>1][(j&1)*2], bhf[j>>1][(j&1)*2+1]);
#pragma unroll
            for (int im = 0; im < 2; im++)
#pragma unroll
                for (int j = 0; j < 8; j++)
                    mma16816(acc[im][j], ah[im],
                             blf[j>>1][(j&1)*2], blf[j>>1][(j&1)*2+1]);
        }
        __syncthreads();
        if (s + NPIPE < NSTG) PISSUE(s + NPIPE, s % NPIPE);
    }
#undef PISSUE

    float* Ds = (float*)sm;
#pragma unroll
    for (int im = 0; im < 2; im++){
#pragma unroll
        for (int j = 0; j < 8; j++){
            const int cl = wn*64 + j*8 + (lane&3)*2;
#pragma unroll
            for (int rr = 0; rr < 2; rr++){
                const int r = wm*32 + im*16 + (lane>>2) + rr*8;
                float v1 = acc[im][j][rr*2+0];
                float v2 = acc[im][j][rr*2+1];
                const int gc = n0 + cl;
                v1 += bias[gc]; v2 += bias[gc+1];
                Ds[r*132 + cl]   = v1;
                Ds[r*132 + cl+1] = v2;
            }
        }
    }
    __syncthreads();
    const int row  = tid >> 1;
    const int half = tid & 1;
    const int m = m0 + row;
    if (m < Mn){
        float* dst = Out + (size_t)m*Cn + n0 + half*64;
        const float* src = &Ds[row*132 + half*64];
#pragma unroll
        for (int j = 0; j < 64; j += 4)
            *(float4*)&dst[j] = *(const float4*)&src[j];
    }
}

// ---------------------------------------------------------------------------
// HMMA flash attention, fp16 2-term: S=(Qh+Ql)K, O+=(Ph+Pl)V.
// KV staged via cp.async double buffer (K and V single tiles, 18KB/stage).
// Q staged at sm[0,36864); KV buffers at sm[36864 + buf*18432).
// ---------------------------------------------------------------------------
#define AT_PITCH 144
#define AT_TILE  (64*AT_PITCH)       // 9216
#define KV_STAGE (2*AT_TILE)         // 18432 : K | V
#define AT_SMEM  (36864 + 2*KV_STAGE) // 73728
#define NTkv ((Nn+63)/64)            // 10

__global__ __launch_bounds__(256,2) void attn_tc()
{
    extern __shared__ char sm[];
    const uint32_t smb = smem_u32(sm);
    const int tid  = threadIdx.x;
    const int wid  = tid >> 5;
    const int lane = tid & 31;
    const int qt   = blockIdx.x;
    const int bh   = blockIdx.y;
    const int bb   = bh / Hn;
    const int h    = bh - bb*Hn;

    const __half* Qh = g_qh + (size_t)bh*Nn*Dn;
    const __half* Ql = g_ql + (size_t)bh*Nn*Dn;
    const __half* Kp = g_k  + (size_t)bh*Nn*Dn;
    const __half* Vp = g_v  + (size_t)bh*Nn*Dn;

    // ---- stage Q (128 rows x 64 fp16) hi at 0, lo at 18432
    {
#pragma unroll
        for (int i = 0; i < 4; i++){
            const int idx = tid + i*256;
            const int r   = idx >> 3;
            const int j   = idx & 7;
            const int gr  = qt*128 + r;
            uint4 vh = make_uint4(0,0,0,0), vl = vh;
            if (gr < Nn){
                vh = *(const uint4*)(Qh + (size_t)gr*Dn + j*8);
                vl = *(const uint4*)(Ql + (size_t)gr*Dn + j*8);
            }
            *(uint4*)(sm + r*AT_PITCH + j*16)         = vh;
            *(uint4*)(sm + 18432 + r*AT_PITCH + j*16) = vl;
        }
    }

    // ---- issue first two KV stages (disjoint smem region)
#define ISSUE_KV(t_, buf_) do{ \
    const int kv0 = (t_)*64; \
    const uint32_t bp = smb + 36864u + (uint32_t)(buf_)*KV_STAGE; \
    _Pragma("unroll") \
    for (int i_ = 0; i_ < 4; i_++){ \
        const int idx = tid + i_*256;            /* 0..1023 */ \
        const int ts  = idx >> 9;                /* 0:K 1:V */ \
        const int rem = idx & 511; \
        const int r_  = rem >> 3; \
        const int j_  = rem & 7; \
        const int gr  = kv0 + r_; \
        const __half* src = ts ? Vp : Kp; \
        const uint32_t n_ = (gr < Nn) ? 16u : 0u; \
        cpa(bp + (uint32_t)ts*AT_TILE + (uint32_t)(r_*AT_PITCH + j_*16), \
            src + (size_t)gr*Dn + j_*8, n_); \
    } \
    asm volatile("cp.async.commit_group;":::"memory"); \
}while(0)

    ISSUE_KV(0, 0);
    ISSUE_KV(1, 1);

    __syncthreads();
    uint32_t qfh[4][4], qfl[4][4];
    {
        const uint32_t qa = smb + (uint32_t)((wid*16 + (lane&15))*AT_PITCH + (lane>>4)*16);
#pragma unroll
        for (int kk = 0; kk < 4; kk++){
            ldsm4(qfh[kk], qa + kk*32);
            ldsm4(qfl[kk], qa + 18432 + kk*32);
        }
    }

    float m0r = -1e30f, m1r = -1e30f, l0r = 0.f, l1r = 0.f;
    float o[8][4];
#pragma unroll
    for (int j=0;j<8;j++)
#pragma unroll
        for (int q=0;q<4;q++) o[j][q] = 0.f;

    for (int t = 0; t < NTkv; t++){
        if (t < NTkv-1) asm volatile("cp.async.wait_group 1;":::"memory");
        else            asm volatile("cp.async.wait_group 0;":::"memory");
        __syncthreads();

        const uint32_t sb = smb + 36864u + (uint32_t)(t&1)*KV_STAGE;

        // ---- S = (Qh + Ql) K^T   (2 fp16 terms)
        float s[8][4];
#pragma unroll
        for (int j=0;j<8;j++)
#pragma unroll
            for (int q=0;q<4;q++) s[j][q] = 0.f;

#pragma unroll
        for (int kk = 0; kk < 4; kk++){
            uint32_t kh[4][4];
#pragma unroll
            for (int g = 0; g < 4; g++){
                const uint32_t ka = sb
                    + (uint32_t)((g*16 + (lane&7) + ((lane>>4)<<3))*AT_PITCH
                                 + ((lane>>3)&1)*16 + kk*32);
                ldsm4(kh[g], ka);
            }
#pragma unroll
            for (int j = 0; j < 8; j++)
                mma16816h(s[j], qfh[kk], kh[j>>1][(j&1)*2], kh[j>>1][(j&1)*2+1]);
#pragma unroll
            for (int j = 0; j < 8; j++)
                mma16816h(s[j], qfl[kk], kh[j>>1][(j&1)*2], kh[j>>1][(j&1)*2+1]);
        }

        // ---- mask + online softmax
        if (t == NTkv-1){
#pragma unroll
            for (int j = 0; j < 8; j++){
                const int c0 = t*64 + j*8 + (lane&3)*2;
                if (c0   >= Nn){ s[j][0] = -1e30f; s[j][2] = -1e30f; }
                if (c0+1 >= Nn){ s[j][1] = -1e30f; s[j][3] = -1e30f; }
            }
        }
        float mx0 = -1e30f, mx1 = -1e30f;
#pragma unroll
        for (int j = 0; j < 8; j++){
            mx0 = fmaxf(mx0, fmaxf(s[j][0], s[j][1]));
            mx1 = fmaxf(mx1, fmaxf(s[j][2], s[j][3]));
        }
        mx0 = fmaxf(mx0, __shfl_xor_sync(0xffffffffu, mx0, 1));
        mx0 = fmaxf(mx0, __shfl_xor_sync(0xffffffffu, mx0, 2));
        mx1 = fmaxf(mx1, __shfl_xor_sync(0xffffffffu, mx1, 1));
        mx1 = fmaxf(mx1, __shfl_xor_sync(0xffffffffu, mx1, 2));
        const float mn0 = fmaxf(m0r, mx0), mn1 = fmaxf(m1r, mx1);
        const float al0 = __expf(m0r - mn0), al1 = __expf(m1r - mn1);
        float rs0 = 0.f, rs1 = 0.f;
#pragma unroll
        for (int j = 0; j < 8; j++){
            s[j][0] = __expf(s[j][0]-mn0); s[j][1] = __expf(s[j][1]-mn0);
            s[j][2] = __expf(s[j][2]-mn1); s[j][3] = __expf(s[j][3]-mn1);
            rs0 += s[j][0] + s[j][1];
            rs1 += s[j][2] + s[j][3];
        }
        rs0 += __shfl_xor_sync(0xffffffffu, rs0, 1);
        rs0 += __shfl_xor_sync(0xffffffffu, rs0, 2);
        rs1 += __shfl_xor_sync(0xffffffffu, rs1, 1);
        rs1 += __shfl_xor_sync(0xffffffffu, rs1, 2);
        l0r = l0r*al0 + rs0;  m0r = mn0;
        l1r = l1r*al1 + rs1;  m1r = mn1;
#pragma unroll
        for (int j = 0; j < 8; j++){
            o[j][0] *= al0; o[j][1] *= al0;
            o[j][2] *= al1; o[j][3] *= al1;
        }

        // ---- O += (Ph + Pl) V   (2 fp16 terms), P repacked in registers
#pragma unroll
        for (int kk = 0; kk < 4; kk++){
            uint32_t pha[4], pla[4];
            {
                const int j0 = 2*kk, j1 = 2*kk+1;
                float h0, h1;
                h0 = __half2float(__float2half_rn(s[j0][0]));
                h1 = __half2float(__float2half_rn(s[j0][1]));
                pha[0] = packh(s[j0][0], s[j0][1]);
                pla[0] = packh(s[j0][0]-h0, s[j0][1]-h1);
                h0 = __half2float(__float2half_rn(s[j0][2]));
                h1 = __half2float(__float2half_rn(s[j0][3]));
                pha[1] = packh(s[j0][2], s[j0][3]);
                pla[1] = packh(s[j0][2]-h0, s[j0][3]-h1);
                h0 = __half2float(__float2half_rn(s[j1][0]));
                h1 = __half2float(__float2half_rn(s[j1][1]));
                pha[2] = packh(s[j1][0], s[j1][1]);
                pla[2] = packh(s[j1][0]-h0, s[j1][1]-h1);
                h0 = __half2float(__float2half_rn(s[j1][2]));
                h1 = __half2float(__float2half_rn(s[j1][3]));
                pha[3] = packh(s[j1][2], s[j1][3]);
                pla[3] = packh(s[j1][2]-h0, s[j1][3]-h1);
            }
            uint32_t vh[4][4];
#pragma unroll
            for (int g = 0; g < 4; g++){
                const uint32_t va = sb + AT_TILE
                    + (uint32_t)((kk*16 + (lane&7) + ((lane>>3)&1)*8)*AT_PITCH
                                 + ((lane>>4)*8 + g*16)*2);
                ldsm4t(vh[g], va);
            }
#pragma unroll
            for (int j = 0; j < 8; j++)
                mma16816h(o[j], pha, vh[j>>1][(j&1)*2], vh[j>>1][(j&1)*2+1]);
#pragma unroll
            for (int j = 0; j < 8; j++)
                mma16816h(o[j], pla, vh[j>>1][(j&1)*2], vh[j>>1][(j&1)*2+1]);
        }
        __syncthreads();
        if (t+2 < NTkv) ISSUE_KV(t+2, t&1);
    }
#undef ISSUE_KV

    // ---- normalize + store AO bf16 hi/lo ([B*N, C] at col h*64+d)
    const float inv0 = 1.f / l0r, inv1 = 1.f / l1r;
    const int r0 = qt*128 + wid*16 + (lane>>2);
    const int r1 = r0 + 8;
#pragma unroll
    for (int j = 0; j < 8; j++){
        const int col = h*Dn + j*8 + (lane&3)*2;
        if (r0 < Nn)
            store_pair(g_aoh, g_aol, (size_t)(bb*Nn + r0)*Cn + col,
                       o[j][0]*inv0, o[j][1]*inv0);
        if (r1 < Nn)
            store_pair(g_aoh, g_aol, (size_t)(bb*Nn + r1)*Cn + col,
                       o[j][2]*inv1, o[j][3]*inv1);
    }
}

// ---------------------------------------------------------------------------
extern "C" void kernel_launch(void* const* d_in, const int* in_sizes, int n_in,
                              void* d_out, int out_size)
{
    (void)in_sizes; (void)n_in; (void)out_size;
    const float* x      = (const float*)d_in[0];
    const float* w_qkv  = (const float*)d_in[1];
    const float* w_proj = (const float*)d_in[2];
    const float* b_proj = (const float*)d_in[3];
    const float* cosb   = (const float*)d_in[4];
    const float* sinb   = (const float*)d_in[5];
    float* out = (float*)d_out;

    cudaFuncSetAttribute(gemm_qkv,  cudaFuncAttributeMaxDynamicSharedMemorySize, SMEM_Q);
    cudaFuncSetAttribute(gemm_proj, cudaFuncAttributeMaxDynamicSharedMemorySize, SMEM_G);
    cudaFuncSetAttribute(attn_tc,   cudaFuncAttributeMaxDynamicSharedMemorySize, AT_SMEM);

    __half *xh, *xl, *wq;
    __nv_bfloat16 *wph, *wpl, *aoh, *aol;
    cudaGetSymbolAddress((void**)&xh,  g_xh);  cudaGetSymbolAddress((void**)&xl,  g_xl);
    cudaGetSymbolAddress((void**)&wq,  g_wq);
    cudaGetSymbolAddress((void**)&wph, g_wph); cudaGetSymbolAddress((void**)&wpl, g_wpl);
    cudaGetSymbolAddress((void**)&aoh, g_aoh); cudaGetSymbolAddress((void**)&aol, g_aol);

    const int nx = Mn*Cn, nwq = QKV_N*Cn, nwp = Cn*Cn;
    split_h<<<(nx/4 + 255)/256, 256>>>(x, xh, xl, nx);
    cvt_h<<<(nwq/4 + 255)/256, 256>>>(w_qkv, wq, nwq);
    split_bf<<<(nwp/4 + 255)/256, 256>>>(w_proj, wph, wpl, nwp);

    const int MT = (Mn + 127) / 128;   // 145
    gemm_qkv<<<dim3(QKV_N/128, MT), 256, SMEM_Q>>>(xh, xl, wq, cosb, sinb);
    attn_tc<<<dim3((Nn+127)/128, Bn*Hn), 256, AT_SMEM>>>();
    gemm_proj<<<dim3(Cn/128, MT), 256, SMEM_G>>>(aoh, aol, wph, wpl, b_proj, out);
}

// round 10
// speedup vs baseline: 1.9895x; 1.0608x over previous
#include <cuda_runtime.h>
#include <cuda_bf16.h>
#include <cuda_fp16.h>
#include <cstdint>

#define Bn 32
#define Nn 577
#define Cn 768
#define Hn 12
#define Dn 64
#define Mn (Bn*Nn)          // 18464
#define QKV_N (3*Cn)        // 2304
#define BHD ((size_t)Bn*Hn*Nn*Dn)   // 14,180,352

// Scratch (__device__ globals)
__device__ __align__(16) __half g_xh[(size_t)Mn*Cn], g_xl[(size_t)Mn*Cn];   // x split fp16
__device__ __align__(16) __half g_wq[(size_t)QKV_N*Cn];                      // w_qkv fp16
__device__ __align__(16) __half g_wp[(size_t)Cn*Cn];                         // w_proj fp16
__device__ __align__(16) __half g_qh[BHD], g_ql[BHD];                        // Q fp16 hi/lo
__device__ __align__(16) __half g_k[BHD], g_v[BHD];                          // K,V fp16
__device__ __align__(16) __half g_aoh[(size_t)Mn*Cn], g_aol[(size_t)Mn*Cn];  // AO fp16 hi/lo

// ---------------------------------------------------------------------------
// helpers
// ---------------------------------------------------------------------------
__device__ __forceinline__ uint32_t smem_u32(const void* p){
    uint32_t a;
    asm("{ .reg .u64 t; cvta.to.shared.u64 t, %1; cvt.u32.u64 %0, t; }"
        : "=r"(a) : "l"(p));
    return a;
}
__device__ __forceinline__ void ldsm4(uint32_t (&r)[4], uint32_t a){
    asm volatile("ldmatrix.sync.aligned.m8n8.x4.shared.b16 {%0,%1,%2,%3}, [%4];"
        : "=r"(r[0]),"=r"(r[1]),"=r"(r[2]),"=r"(r[3]) : "r"(a));
}
__device__ __forceinline__ void ldsm4t(uint32_t (&r)[4], uint32_t a){
    asm volatile("ldmatrix.sync.aligned.m8n8.x4.trans.shared.b16 {%0,%1,%2,%3}, [%4];"
        : "=r"(r[0]),"=r"(r[1]),"=r"(r[2]),"=r"(r[3]) : "r"(a));
}
__device__ __forceinline__ void mma16816h(float* c, const uint32_t* a,
                                          uint32_t b0, uint32_t b1){
    asm volatile("mma.sync.aligned.m16n8k16.row.col.f32.f16.f16.f32 "
        "{%0,%1,%2,%3}, {%4,%5,%6,%7}, {%8,%9}, {%0,%1,%2,%3};"
        : "+f"(c[0]),"+f"(c[1]),"+f"(c[2]),"+f"(c[3])
        : "r"(a[0]),"r"(a[1]),"r"(a[2]),"r"(a[3]), "r"(b0),"r"(b1));
}
__device__ __forceinline__ void cpa(uint32_t s, const void* g, uint32_t n){
    asm volatile("cp.async.cg.shared.global [%0], [%1], 16, %2;"
                 :: "r"(s), "l"(g), "r"(n) : "memory");
}
__device__ __forceinline__ uint32_t packh(float x, float y){
    __half2 t = __floats2half2_rn(x, y);
    return *reinterpret_cast<uint32_t*>(&t);
}
__device__ __forceinline__ void store_pairh(__half* dh, __half* dl,
                                            size_t idx, float v1, float v2){
    const __half h1 = __float2half_rn(v1), h2 = __float2half_rn(v2);
    uint32_t hp; { __half2 t; t.x=h1; t.y=h2; hp=*reinterpret_cast<uint32_t*>(&t); }
    *reinterpret_cast<uint32_t*>(dh + idx) = hp;
    *reinterpret_cast<uint32_t*>(dl + idx) =
        packh(v1 - __half2float(h1), v2 - __half2float(h2));
}

// ---------------------------------------------------------------------------
// conversion kernels
// ---------------------------------------------------------------------------
__global__ __launch_bounds__(256) void split_h(
    const float* __restrict__ s, __half* __restrict__ dh,
    __half* __restrict__ dl, int n)
{
    const int i = (blockIdx.x*256 + threadIdx.x)*4;
    if (i < n){
        float4 v = *(const float4*)(s + i);
        const float hx = __half2float(__float2half_rn(v.x));
        const float hy = __half2float(__float2half_rn(v.y));
        const float hz = __half2float(__float2half_rn(v.z));
        const float hw = __half2float(__float2half_rn(v.w));
        *(uint2*)(dh + i) = make_uint2(packh(v.x, v.y), packh(v.z, v.w));
        *(uint2*)(dl + i) = make_uint2(packh(v.x-hx, v.y-hy), packh(v.z-hz, v.w-hw));
    }
}
__global__ __launch_bounds__(256) void cvt_h(
    const float* __restrict__ s, __half* __restrict__ d, int n)
{
    const int i = (blockIdx.x*256 + threadIdx.x)*4;
    if (i < n){
        float4 v = *(const float4*)(s + i);
        *(uint2*)(d + i) = make_uint2(packh(v.x, v.y), packh(v.z, v.w));
    }
}

// swizzled byte offset within a 128x(32x2B) tile
#define SWZ(row_, grp_) ((uint32_t)(row_)*64u + ((((uint32_t)(grp_)) ^ (((uint32_t)(row_)>>1)&3u))<<4))

#define KS 32
#define NSTG (Cn/KS)         // 24
#define TILE8K 8192

// ---------------------------------------------------------------------------
// fp16 2-term GEMM (Ah·B + Al·B), 4-deep cp.async pipe, 2 CTAs/SM.
// EPI==0: RoPE + q-scale -> fp16 (q hi/lo; k,v single) in [B,H,N,D]
// EPI==1: +bias -> fp32 Out
// ---------------------------------------------------------------------------
#define QSTG_B (3*TILE8K)     // 24576 : Ah|Al|Bh
#define QNPIPE 4
#define SMEM_Q (QNPIPE*QSTG_B) // 98304

template<int EPI>
__global__ __launch_bounds__(256,2) void gemm_h2(
    const __half* __restrict__ Ah, const __half* __restrict__ Al,
    const __half* __restrict__ Bh,
    const float* __restrict__ cosb, const float* __restrict__ sinb,
    const float* __restrict__ bias, float* __restrict__ Out)
{
    extern __shared__ char sm[];
    const uint32_t smb = smem_u32(sm);

    const int tid  = threadIdx.x;
    const int wid  = tid >> 5;
    const int lane = tid & 31;
    const int m0 = blockIdx.y * 128;
    const int n0 = blockIdx.x * 128;
    const int wm = wid & 3;
    const int wn = wid >> 2;

    float acc[2][8][4];
#pragma unroll
    for (int im=0;im<2;im++)
#pragma unroll
        for (int j=0;j<8;j++)
#pragma unroll
            for (int q=0;q<4;q++) acc[im][j][q] = 0.f;

#define QISSUE(s_, b_) do{ \
    const uint32_t bb_ = smb + (uint32_t)(b_)*QSTG_B; \
    const int kt_ = (s_)*KS; \
    _Pragma("unroll") \
    for (int r_ = 0; r_ < 2; r_++){ \
        const int idx_ = tid + r_*256; \
        const uint32_t row_ = (uint32_t)(idx_ >> 2); \
        const uint32_t grp_ = (uint32_t)(idx_ & 3); \
        const uint32_t dst_ = bb_ + SWZ(row_, grp_); \
        const uint32_t an_  = ((int)(m0 + row_) < Mn) ? 16u : 0u; \
        const size_t aoff_ = (size_t)(m0 + row_)*Cn + kt_ + grp_*8; \
        const size_t boff_ = (size_t)(n0 + row_)*Cn + kt_ + grp_*8; \
        cpa(dst_,            Ah + aoff_, an_); \
        cpa(dst_ + TILE8K,   Al + aoff_, an_); \
        cpa(dst_ + 2*TILE8K, Bh + boff_, 16u); \
    } \
    asm volatile("cp.async.commit_group;":::"memory"); \
}while(0)

    QISSUE(0, 0);
    QISSUE(1, 1);
    QISSUE(2, 2);

    const uint32_t ar0 = (uint32_t)(wm*32 + (lane & 15));
    const uint32_t ar1 = ar0 + 16;
    const uint32_t brb = (uint32_t)(wn*64 + (lane & 7) + ((lane >> 4) << 3));

    for (int s = 0; s < NSTG; s++){
        asm volatile("cp.async.wait_group 2;":::"memory");
        __syncthreads();

        const uint32_t sb = smb + (uint32_t)(s % QNPIPE)*QSTG_B;
#pragma unroll
        for (int kk = 0; kk < 2; kk++){
            const uint32_t gA = (uint32_t)(kk*2 + (lane >> 4));
            const uint32_t gB = (uint32_t)(kk*2 + ((lane >> 3) & 1));
            uint32_t ah[2][4], al[2][4], bhf[4][4];
            ldsm4(ah[0], sb + SWZ(ar0, gA));
            ldsm4(ah[1], sb + SWZ(ar1, gA));
            ldsm4(al[0], sb + TILE8K + SWZ(ar0, gA));
            ldsm4(al[1], sb + TILE8K + SWZ(ar1, gA));
#pragma unroll
            for (int t2 = 0; t2 < 4; t2++){
                const uint32_t br = brb + (uint32_t)(t2*16);
                ldsm4(bhf[t2], sb + 2*TILE8K + SWZ(br, gB));
            }
#pragma unroll
            for (int im = 0; im < 2; im++)
#pragma unroll
                for (int j = 0; j < 8; j++)
                    mma16816h(acc[im][j], ah[im],
                              bhf[j>>1][(j&1)*2], bhf[j>>1][(j&1)*2+1]);
#pragma unroll
            for (int im = 0; im < 2; im++)
#pragma unroll
                for (int j = 0; j < 8; j++)
                    mma16816h(acc[im][j], al[im],
                              bhf[j>>1][(j&1)*2], bhf[j>>1][(j&1)*2+1]);
        }
        __syncthreads();
        if (s + 3 < NSTG) QISSUE(s + 3, (s + 3) % QNPIPE);
    }
#undef QISSUE

    if (EPI == 0){
        // epilogue: RoPE + q-scale -> fp16 q hi/lo, k/v single fp16, [B,H,N,D]
#pragma unroll
        for (int im = 0; im < 2; im++){
#pragma unroll
            for (int j = 0; j < 8; j++){
                const int cl = wn*64 + j*8 + (lane&3)*2;
#pragma unroll
                for (int rr = 0; rr < 2; rr++){
                    const int r = wm*32 + im*16 + (lane>>2) + rr*8;
                    const int m = m0 + r;
                    if (m >= Mn) continue;
                    float v1 = acc[im][j][rr*2+0];
                    float v2 = acc[im][j][rr*2+1];
                    const int gc  = n0 + cl;
                    const int sec = gc / Cn;
                    const int rem = gc - sec*Cn;
                    const int hh  = rem >> 6;
                    const int d   = rem & 63;
                    const int bb  = m / Nn;
                    const int n   = m - bb*Nn;
                    if (sec < 2 && n > 0){
                        const float cs = cosb[(n-1)*(Dn/2) + (d>>1)];
                        const float sn = sinb[(n-1)*(Dn/2) + (d>>1)];
                        const float r1 = v1*cs - v2*sn;
                        const float r2 = v1*sn + v2*cs;
                        v1 = r1; v2 = r2;
                    }
                    if (sec == 0){ v1 *= 0.125f; v2 *= 0.125f; }
                    const size_t idx = ((size_t)(bb*Hn + hh)*Nn + n)*Dn + d;
                    if (sec == 0)      store_pairh(g_qh, g_ql, idx, v1, v2);
                    else if (sec == 1) *reinterpret_cast<uint32_t*>(g_k + idx) = packh(v1, v2);
                    else               *reinterpret_cast<uint32_t*>(g_v + idx) = packh(v1, v2);
                }
            }
        }
    } else {
        // epilogue: +bias -> fp32 Out via smem staging
        float* Ds = (float*)sm;            // 128 x 132 = 67584 B <= 98304
#pragma unroll
        for (int im = 0; im < 2; im++){
#pragma unroll
            for (int j = 0; j < 8; j++){
                const int cl = wn*64 + j*8 + (lane&3)*2;
#pragma unroll
                for (int rr = 0; rr < 2; rr++){
                    const int r = wm*32 + im*16 + (lane>>2) + rr*8;
                    float v1 = acc[im][j][rr*2+0];
                    float v2 = acc[im][j][rr*2+1];
                    const int gc = n0 + cl;
                    v1 += bias[gc]; v2 += bias[gc+1];
                    Ds[r*132 + cl]   = v1;
                    Ds[r*132 + cl+1] = v2;
                }
            }
        }
        __syncthreads();
        const int row  = tid >> 1;
        const int half = tid & 1;
        const int m = m0 + row;
        if (m < Mn){
            float* dst = Out + (size_t)m*Cn + n0 + half*64;
            const float* src = &Ds[row*132 + half*64];
#pragma unroll
            for (int j = 0; j < 64; j += 4)
                *(float4*)&dst[j] = *(const float4*)&src[j];
        }
    }
}

// ---------------------------------------------------------------------------
// HMMA flash attention, fp16 2-term: S=(Qh+Ql)K, O+=(Ph+Pl)V.
// KV staged via cp.async double buffer; AO stored fp16 hi/lo.
// ---------------------------------------------------------------------------
#define AT_PITCH 144
#define AT_TILE  (64*AT_PITCH)       // 9216
#define KV_STAGE (2*AT_TILE)         // 18432 : K | V
#define AT_SMEM  (36864 + 2*KV_STAGE) // 73728
#define NTkv ((Nn+63)/64)            // 10

__global__ __launch_bounds__(256,2) void attn_tc()
{
    extern __shared__ char sm[];
    const uint32_t smb = smem_u32(sm);
    const int tid  = threadIdx.x;
    const int wid  = tid >> 5;
    const int lane = tid & 31;
    const int qt   = blockIdx.x;
    const int bh   = blockIdx.y;
    const int bb   = bh / Hn;
    const int h    = bh - bb*Hn;

    const __half* Qh = g_qh + (size_t)bh*Nn*Dn;
    const __half* Ql = g_ql + (size_t)bh*Nn*Dn;
    const __half* Kp = g_k  + (size_t)bh*Nn*Dn;
    const __half* Vp = g_v  + (size_t)bh*Nn*Dn;

    // ---- stage Q (128 rows x 64 fp16) hi at 0, lo at 18432
    {
#pragma unroll
        for (int i = 0; i < 4; i++){
            const int idx = tid + i*256;
            const int r   = idx >> 3;
            const int j   = idx & 7;
            const int gr  = qt*128 + r;
            uint4 vh = make_uint4(0,0,0,0), vl = vh;
            if (gr < Nn){
                vh = *(const uint4*)(Qh + (size_t)gr*Dn + j*8);
                vl = *(const uint4*)(Ql + (size_t)gr*Dn + j*8);
            }
            *(uint4*)(sm + r*AT_PITCH + j*16)         = vh;
            *(uint4*)(sm + 18432 + r*AT_PITCH + j*16) = vl;
        }
    }

#define ISSUE_KV(t_, buf_) do{ \
    const int kv0 = (t_)*64; \
    const uint32_t bp = smb + 36864u + (uint32_t)(buf_)*KV_STAGE; \
    _Pragma("unroll") \
    for (int i_ = 0; i_ < 4; i_++){ \
        const int idx = tid + i_*256; \
        const int ts  = idx >> 9; \
        const int rem = idx & 511; \
        const int r_  = rem >> 3; \
        const int j_  = rem & 7; \
        const int gr  = kv0 + r_; \
        const __half* src = ts ? Vp : Kp; \
        const uint32_t n_ = (gr < Nn) ? 16u : 0u; \
        cpa(bp + (uint32_t)ts*AT_TILE + (uint32_t)(r_*AT_PITCH + j_*16), \
            src + (size_t)gr*Dn + j_*8, n_); \
    } \
    asm volatile("cp.async.commit_group;":::"memory"); \
}while(0)

    ISSUE_KV(0, 0);
    ISSUE_KV(1, 1);

    __syncthreads();
    uint32_t qfh[4][4], qfl[4][4];
    {
        const uint32_t qa = smb + (uint32_t)((wid*16 + (lane&15))*AT_PITCH + (lane>>4)*16);
#pragma unroll
        for (int kk = 0; kk < 4; kk++){
            ldsm4(qfh[kk], qa + kk*32);
            ldsm4(qfl[kk], qa + 18432 + kk*32);
        }
    }

    float m0r = -1e30f, m1r = -1e30f, l0r = 0.f, l1r = 0.f;
    float o[8][4];
#pragma unroll
    for (int j=0;j<8;j++)
#pragma unroll
        for (int q=0;q<4;q++) o[j][q] = 0.f;

    for (int t = 0; t < NTkv; t++){
        if (t < NTkv-1) asm volatile("cp.async.wait_group 1;":::"memory");
        else            asm volatile("cp.async.wait_group 0;":::"memory");
        __syncthreads();

        const uint32_t sb = smb + 36864u + (uint32_t)(t&1)*KV_STAGE;

        float s[8][4];
#pragma unroll
        for (int j=0;j<8;j++)
#pragma unroll
            for (int q=0;q<4;q++) s[j][q] = 0.f;

#pragma unroll
        for (int kk = 0; kk < 4; kk++){
            uint32_t kh[4][4];
#pragma unroll
            for (int g = 0; g < 4; g++){
                const uint32_t ka = sb
                    + (uint32_t)((g*16 + (lane&7) + ((lane>>4)<<3))*AT_PITCH
                                 + ((lane>>3)&1)*16 + kk*32);
                ldsm4(kh[g], ka);
            }
#pragma unroll
            for (int j = 0; j < 8; j++)
                mma16816h(s[j], qfh[kk], kh[j>>1][(j&1)*2], kh[j>>1][(j&1)*2+1]);
#pragma unroll
            for (int j = 0; j < 8; j++)
                mma16816h(s[j], qfl[kk], kh[j>>1][(j&1)*2], kh[j>>1][(j&1)*2+1]);
        }

        if (t == NTkv-1){
#pragma unroll
            for (int j = 0; j < 8; j++){
                const int c0 = t*64 + j*8 + (lane&3)*2;
                if (c0   >= Nn){ s[j][0] = -1e30f; s[j][2] = -1e30f; }
                if (c0+1 >= Nn){ s[j][1] = -1e30f; s[j][3] = -1e30f; }
            }
        }
        float mx0 = -1e30f, mx1 = -1e30f;
#pragma unroll
        for (int j = 0; j < 8; j++){
            mx0 = fmaxf(mx0, fmaxf(s[j][0], s[j][1]));
            mx1 = fmaxf(mx1, fmaxf(s[j][2], s[j][3]));
        }
        mx0 = fmaxf(mx0, __shfl_xor_sync(0xffffffffu, mx0, 1));
        mx0 = fmaxf(mx0, __shfl_xor_sync(0xffffffffu, mx0, 2));
        mx1 = fmaxf(mx1, __shfl_xor_sync(0xffffffffu, mx1, 1));
        mx1 = fmaxf(mx1, __shfl_xor_sync(0xffffffffu, mx1, 2));
        const float mn0 = fmaxf(m0r, mx0), mn1 = fmaxf(m1r, mx1);
        const float al0 = __expf(m0r - mn0), al1 = __expf(m1r - mn1);
        float rs0 = 0.f, rs1 = 0.f;
#pragma unroll
        for (int j = 0; j < 8; j++){
            s[j][0] = __expf(s[j][0]-mn0); s[j][1] = __expf(s[j][1]-mn0);
            s[j][2] = __expf(s[j][2]-mn1); s[j][3] = __expf(s[j][3]-mn1);
            rs0 += s[j][0] + s[j][1];
            rs1 += s[j][2] + s[j][3];
        }
        rs0 += __shfl_xor_sync(0xffffffffu, rs0, 1);
        rs0 += __shfl_xor_sync(0xffffffffu, rs0, 2);
        rs1 += __shfl_xor_sync(0xffffffffu, rs1, 1);
        rs1 += __shfl_xor_sync(0xffffffffu, rs1, 2);
        l0r = l0r*al0 + rs0;  m0r = mn0;
        l1r = l1r*al1 + rs1;  m1r = mn1;
#pragma unroll
        for (int j = 0; j < 8; j++){
            o[j][0] *= al0; o[j][1] *= al0;
            o[j][2] *= al1; o[j][3] *= al1;
        }

#pragma unroll
        for (int kk = 0; kk < 4; kk++){
            uint32_t pha[4], pla[4];
            {
                const int j0 = 2*kk, j1 = 2*kk+1;
                float h0, h1;
                h0 = __half2float(__float2half_rn(s[j0][0]));
                h1 = __half2float(__float2half_rn(s[j0][1]));
                pha[0] = packh(s[j0][0], s[j0][1]);
                pla[0] = packh(s[j0][0]-h0, s[j0][1]-h1);
                h0 = __half2float(__float2half_rn(s[j0][2]));
                h1 = __half2float(__float2half_rn(s[j0][3]));
                pha[1] = packh(s[j0][2], s[j0][3]);
                pla[1] = packh(s[j0][2]-h0, s[j0][3]-h1);
                h0 = __half2float(__float2half_rn(s[j1][0]));
                h1 = __half2float(__float2half_rn(s[j1][1]));
                pha[2] = packh(s[j1][0], s[j1][1]);
                pla[2] = packh(s[j1][0]-h0, s[j1][1]-h1);
                h0 = __half2float(__float2half_rn(s[j1][2]));
                h1 = __half2float(__float2half_rn(s[j1][3]));
                pha[3] = packh(s[j1][2], s[j1][3]);
                pla[3] = packh(s[j1][2]-h0, s[j1][3]-h1);
            }
            uint32_t vh[4][4];
#pragma unroll
            for (int g = 0; g < 4; g++){
                const uint32_t va = sb + AT_TILE
                    + (uint32_t)((kk*16 + (lane&7) + ((lane>>3)&1)*8)*AT_PITCH
                                 + ((lane>>4)*8 + g*16)*2);
                ldsm4t(vh[g], va);
            }
#pragma unroll
            for (int j = 0; j < 8; j++)
                mma16816h(o[j], pha, vh[j>>1][(j&1)*2], vh[j>>1][(j&1)*2+1]);
#pragma unroll
            for (int j = 0; j < 8; j++)
                mma16816h(o[j], pla, vh[j>>1][(j&1)*2], vh[j>>1][(j&1)*2+1]);
        }
        __syncthreads();
        if (t+2 < NTkv) ISSUE_KV(t+2, t&1);
    }
#undef ISSUE_KV

    // ---- normalize + store AO fp16 hi/lo ([B*N, C] at col h*64+d)
    const float inv0 = 1.f / l0r, inv1 = 1.f / l1r;
    const int r0 = qt*128 + wid*16 + (lane>>2);
    const int r1 = r0 + 8;
#pragma unroll
    for (int j = 0; j < 8; j++){
        const int col = h*Dn + j*8 + (lane&3)*2;
        if (r0 < Nn)
            store_pairh(g_aoh, g_aol, (size_t)(bb*Nn + r0)*Cn + col,
                        o[j][0]*inv0, o[j][1]*inv0);
        if (r1 < Nn)
            store_pairh(g_aoh, g_aol, (size_t)(bb*Nn + r1)*Cn + col,
                        o[j][2]*inv1, o[j][3]*inv1);
    }
}

// ---------------------------------------------------------------------------
extern "C" void kernel_launch(void* const* d_in, const int* in_sizes, int n_in,
                              void* d_out, int out_size)
{
    (void)in_sizes; (void)n_in; (void)out_size;
    const float* x      = (const float*)d_in[0];
    const float* w_qkv  = (const float*)d_in[1];
    const float* w_proj = (const float*)d_in[2];
    const float* b_proj = (const float*)d_in[3];
    const float* cosb   = (const float*)d_in[4];
    const float* sinb   = (const float*)d_in[5];
    float* out = (float*)d_out;

    cudaFuncSetAttribute(gemm_h2<0>, cudaFuncAttributeMaxDynamicSharedMemorySize, SMEM_Q);
    cudaFuncSetAttribute(gemm_h2<1>, cudaFuncAttributeMaxDynamicSharedMemorySize, SMEM_Q);
    cudaFuncSetAttribute(attn_tc,    cudaFuncAttributeMaxDynamicSharedMemorySize, AT_SMEM);

    __half *xh, *xl, *wq, *wp, *aoh, *aol;
    cudaGetSymbolAddress((void**)&xh,  g_xh);  cudaGetSymbolAddress((void**)&xl,  g_xl);
    cudaGetSymbolAddress((void**)&wq,  g_wq);  cudaGetSymbolAddress((void**)&wp,  g_wp);
    cudaGetSymbolAddress((void**)&aoh, g_aoh); cudaGetSymbolAddress((void**)&aol, g_aol);

    const int nx = Mn*Cn, nwq = QKV_N*Cn, nwp = Cn*Cn;
    split_h<<<(nx/4 + 255)/256, 256>>>(x, xh, xl, nx);
    cvt_h<<<(nwq/4 + 255)/256, 256>>>(w_qkv, wq, nwq);
    cvt_h<<<(nwp/4 + 255)/256, 256>>>(w_proj, wp, nwp);

    const int MT = (Mn + 127) / 128;   // 145
    gemm_h2<0><<<dim3(QKV_N/128, MT), 256, SMEM_Q>>>(xh, xl, wq, cosb, sinb,
                                                     nullptr, nullptr);
    attn_tc<<<dim3((Nn+127)/128, Bn*Hn), 256, AT_SMEM>>>();
    gemm_h2<1><<<dim3(Cn/128, MT), 256, SMEM_Q>>>(aoh, aol, wp, nullptr, nullptr,
                                                  b_proj, out);
}

// round 11
// speedup vs baseline: 2.0890x; 1.0500x over previous
#include <cuda_runtime.h>
#include <cuda_bf16.h>
#include <cuda_fp16.h>
#include <cstdint>

#define Bn 32
#define Nn 577
#define Cn 768
#define Hn 12
#define Dn 64
#define Mn (Bn*Nn)          // 18464
#define QKV_N (3*Cn)        // 2304
#define BHD ((size_t)Bn*Hn*Nn*Dn)   // 14,180,352

// Scratch (__device__ globals)
__device__ __align__(16) __half g_xh[(size_t)Mn*Cn], g_xl[(size_t)Mn*Cn];   // x split fp16
__device__ __align__(16) __half g_wq[(size_t)QKV_N*Cn];                      // w_qkv fp16
__device__ __align__(16) __half g_wp[(size_t)Cn*Cn];                         // w_proj fp16
__device__ __align__(16) __half g_qh[BHD], g_ql[BHD];                        // Q fp16 hi/lo
__device__ __align__(16) __half g_k[BHD], g_v[BHD];                          // K,V fp16
__device__ __align__(16) __half g_aoh[(size_t)Mn*Cn], g_aol[(size_t)Mn*Cn];  // AO fp16 hi/lo

// ---------------------------------------------------------------------------
// helpers
// ---------------------------------------------------------------------------
__device__ __forceinline__ uint32_t smem_u32(const void* p){
    uint32_t a;
    asm("{ .reg .u64 t; cvta.to.shared.u64 t, %1; cvt.u32.u64 %0, t; }"
        : "=r"(a) : "l"(p));
    return a;
}
__device__ __forceinline__ void ldsm4(uint32_t (&r)[4], uint32_t a){
    asm volatile("ldmatrix.sync.aligned.m8n8.x4.shared.b16 {%0,%1,%2,%3}, [%4];"
        : "=r"(r[0]),"=r"(r[1]),"=r"(r[2]),"=r"(r[3]) : "r"(a));
}
__device__ __forceinline__ void ldsm4t(uint32_t (&r)[4], uint32_t a){
    asm volatile("ldmatrix.sync.aligned.m8n8.x4.trans.shared.b16 {%0,%1,%2,%3}, [%4];"
        : "=r"(r[0]),"=r"(r[1]),"=r"(r[2]),"=r"(r[3]) : "r"(a));
}
__device__ __forceinline__ void mma16816h(float* c, const uint32_t* a,
                                          uint32_t b0, uint32_t b1){
    asm volatile("mma.sync.aligned.m16n8k16.row.col.f32.f16.f16.f32 "
        "{%0,%1,%2,%3}, {%4,%5,%6,%7}, {%8,%9}, {%0,%1,%2,%3};"
        : "+f"(c[0]),"+f"(c[1]),"+f"(c[2]),"+f"(c[3])
        : "r"(a[0]),"r"(a[1]),"r"(a[2]),"r"(a[3]), "r"(b0),"r"(b1));
}
__device__ __forceinline__ void cpa(uint32_t s, const void* g, uint32_t n){
    asm volatile("cp.async.cg.shared.global [%0], [%1], 16, %2;"
                 :: "r"(s), "l"(g), "r"(n) : "memory");
}
__device__ __forceinline__ uint32_t packh(float x, float y){
    __half2 t = __floats2half2_rn(x, y);
    return *reinterpret_cast<uint32_t*>(&t);
}
__device__ __forceinline__ void store_pairh(__half* dh, __half* dl,
                                            size_t idx, float v1, float v2){
    const __half h1 = __float2half_rn(v1), h2 = __float2half_rn(v2);
    uint32_t hp; { __half2 t; t.x=h1; t.y=h2; hp=*reinterpret_cast<uint32_t*>(&t); }
    *reinterpret_cast<uint32_t*>(dh + idx) = hp;
    *reinterpret_cast<uint32_t*>(dl + idx) =
        packh(v1 - __half2float(h1), v2 - __half2float(h2));
}

// ---------------------------------------------------------------------------
// merged conversion kernel: x -> split fp16 hi/lo; w_qkv, w_proj -> fp16
// ---------------------------------------------------------------------------
#define NBX ((Mn*Cn)/1024)        // 13848
#define NBQ ((QKV_N*Cn)/1024)     // 1728
#define NBP ((Cn*Cn)/1024)        // 576

__global__ __launch_bounds__(256) void conv_all(
    const float* __restrict__ x, const float* __restrict__ wq,
    const float* __restrict__ wp,
    __half* __restrict__ xh, __half* __restrict__ xl,
    __half* __restrict__ wqd, __half* __restrict__ wpd)
{
    const int b = blockIdx.x;
    const int t4 = threadIdx.x * 4;
    if (b < NBX){
        const int i = b*1024 + t4;
        float4 v = *(const float4*)(x + i);
        const float hx = __half2float(__float2half_rn(v.x));
        const float hy = __half2float(__float2half_rn(v.y));
        const float hz = __half2float(__float2half_rn(v.z));
        const float hw = __half2float(__float2half_rn(v.w));
        *(uint2*)(xh + i) = make_uint2(packh(v.x, v.y), packh(v.z, v.w));
        *(uint2*)(xl + i) = make_uint2(packh(v.x-hx, v.y-hy), packh(v.z-hz, v.w-hw));
    } else if (b < NBX + NBQ){
        const int i = (b - NBX)*1024 + t4;
        float4 v = *(const float4*)(wq + i);
        *(uint2*)(wqd + i) = make_uint2(packh(v.x, v.y), packh(v.z, v.w));
    } else {
        const int i = (b - NBX - NBQ)*1024 + t4;
        float4 v = *(const float4*)(wp + i);
        *(uint2*)(wpd + i) = make_uint2(packh(v.x, v.y), packh(v.z, v.w));
    }
}

// ---------------------------------------------------------------------------
// fp16 2-term GEMM (Ah·B + Al·B), k-stage 64, 2-deep cp.async pipe, 2 CTAs/SM.
// Tiles: 128 rows x 64 fp16 = 128B rows, SW128 xor swizzle.
// EPI==0: RoPE + q-scale -> fp16 (q hi/lo; k,v single) in [B,H,N,D]
// EPI==1: +bias -> fp32 Out
// ---------------------------------------------------------------------------
#define KS2 64
#define NSTG2 (Cn/KS2)        // 12
#define TILE16K 16384
#define GSTG_B (3*TILE16K)    // 49152 : Ah|Al|B
#define SMEM_GM (2*GSTG_B)    // 98304

// swizzled byte offset within a 128x(64 fp16 = 128B) tile
#define SWZ128(row_, grp_) ((uint32_t)(row_)*128u + ((((uint32_t)(grp_)) ^ ((uint32_t)(row_)&7u))<<4))

template<int EPI>
__global__ __launch_bounds__(256,2) void gemm_h2(
    const __half* __restrict__ Ah, const __half* __restrict__ Al,
    const __half* __restrict__ Bh,
    const float* __restrict__ cosb, const float* __restrict__ sinb,
    const float* __restrict__ bias, float* __restrict__ Out)
{
    extern __shared__ char sm[];
    const uint32_t smb = smem_u32(sm);

    const int tid  = threadIdx.x;
    const int wid  = tid >> 5;
    const int lane = tid & 31;
    const int m0 = blockIdx.y * 128;
    const int n0 = blockIdx.x * 128;
    const int wm = wid & 3;
    const int wn = wid >> 2;

    float acc[2][8][4];
#pragma unroll
    for (int im=0;im<2;im++)
#pragma unroll
        for (int j=0;j<8;j++)
#pragma unroll
            for (int q=0;q<4;q++) acc[im][j][q] = 0.f;

#define GISSUE(s_, b_) do{ \
    const uint32_t bb_ = smb + (uint32_t)(b_)*GSTG_B; \
    const int kt_ = (s_)*KS2; \
    _Pragma("unroll") \
    for (int r_ = 0; r_ < 4; r_++){ \
        const int idx_ = tid + r_*256; \
        const uint32_t row_ = (uint32_t)(idx_ >> 3); \
        const uint32_t grp_ = (uint32_t)(idx_ & 7); \
        const uint32_t dst_ = bb_ + SWZ128(row_, grp_); \
        const uint32_t an_  = ((int)(m0 + row_) < Mn) ? 16u : 0u; \
        const size_t aoff_ = (size_t)(m0 + row_)*Cn + kt_ + grp_*8; \
        const size_t boff_ = (size_t)(n0 + row_)*Cn + kt_ + grp_*8; \
        cpa(dst_,             Ah + aoff_, an_); \
        cpa(dst_ + TILE16K,   Al + aoff_, an_); \
        cpa(dst_ + 2*TILE16K, Bh + boff_, 16u); \
    } \
    asm volatile("cp.async.commit_group;":::"memory"); \
}while(0)

    GISSUE(0, 0);
    GISSUE(1, 1);

    const uint32_t ar0 = (uint32_t)(wm*32 + (lane & 15));
    const uint32_t ar1 = ar0 + 16;
    const uint32_t brb = (uint32_t)(wn*64 + (lane & 7) + ((lane >> 4) << 3));

    for (int s = 0; s < NSTG2; s++){
        if (s < NSTG2-1) asm volatile("cp.async.wait_group 1;":::"memory");
        else             asm volatile("cp.async.wait_group 0;":::"memory");
        __syncthreads();

        const uint32_t sb = smb + (uint32_t)(s & 1)*GSTG_B;
#pragma unroll
        for (int kk = 0; kk < 4; kk++){
            const uint32_t gA = (uint32_t)(kk*2 + (lane >> 4));
            const uint32_t gB = (uint32_t)(kk*2 + ((lane >> 3) & 1));
            uint32_t ah[2][4], al[2][4], bhf[4][4];
            ldsm4(ah[0], sb + SWZ128(ar0, gA));
            ldsm4(ah[1], sb + SWZ128(ar1, gA));
            ldsm4(al[0], sb + TILE16K + SWZ128(ar0, gA));
            ldsm4(al[1], sb + TILE16K + SWZ128(ar1, gA));
#pragma unroll
            for (int t2 = 0; t2 < 4; t2++){
                const uint32_t br = brb + (uint32_t)(t2*16);
                ldsm4(bhf[t2], sb + 2*TILE16K + SWZ128(br, gB));
            }
#pragma unroll
            for (int im = 0; im < 2; im++)
#pragma unroll
                for (int j = 0; j < 8; j++)
                    mma16816h(acc[im][j], ah[im],
                              bhf[j>>1][(j&1)*2], bhf[j>>1][(j&1)*2+1]);
#pragma unroll
            for (int im = 0; im < 2; im++)
#pragma unroll
                for (int j = 0; j < 8; j++)
                    mma16816h(acc[im][j], al[im],
                              bhf[j>>1][(j&1)*2], bhf[j>>1][(j&1)*2+1]);
        }
        __syncthreads();
        if (s + 2 < NSTG2) GISSUE(s + 2, s & 1);
    }
#undef GISSUE

    if (EPI == 0){
        // epilogue: RoPE + q-scale -> fp16 q hi/lo, k/v single fp16, [B,H,N,D]
#pragma unroll
        for (int im = 0; im < 2; im++){
#pragma unroll
            for (int j = 0; j < 8; j++){
                const int cl = wn*64 + j*8 + (lane&3)*2;
#pragma unroll
                for (int rr = 0; rr < 2; rr++){
                    const int r = wm*32 + im*16 + (lane>>2) + rr*8;
                    const int m = m0 + r;
                    if (m >= Mn) continue;
                    float v1 = acc[im][j][rr*2+0];
                    float v2 = acc[im][j][rr*2+1];
                    const int gc  = n0 + cl;
                    const int sec = gc / Cn;
                    const int rem = gc - sec*Cn;
                    const int hh  = rem >> 6;
                    const int d   = rem & 63;
                    const int bb  = m / Nn;
                    const int n   = m - bb*Nn;
                    if (sec < 2 && n > 0){
                        const float cs = cosb[(n-1)*(Dn/2) + (d>>1)];
                        const float sn = sinb[(n-1)*(Dn/2) + (d>>1)];
                        const float r1 = v1*cs - v2*sn;
                        const float r2 = v1*sn + v2*cs;
                        v1 = r1; v2 = r2;
                    }
                    if (sec == 0){ v1 *= 0.125f; v2 *= 0.125f; }
                    const size_t idx = ((size_t)(bb*Hn + hh)*Nn + n)*Dn + d;
                    if (sec == 0)      store_pairh(g_qh, g_ql, idx, v1, v2);
                    else if (sec == 1) *reinterpret_cast<uint32_t*>(g_k + idx) = packh(v1, v2);
                    else               *reinterpret_cast<uint32_t*>(g_v + idx) = packh(v1, v2);
                }
            }
        }
    } else {
        // epilogue: +bias -> fp32 Out via smem staging
        float* Ds = (float*)sm;            // 128 x 132 = 67584 B <= 98304
#pragma unroll
        for (int im = 0; im < 2; im++){
#pragma unroll
            for (int j = 0; j < 8; j++){
                const int cl = wn*64 + j*8 + (lane&3)*2;
#pragma unroll
                for (int rr = 0; rr < 2; rr++){
                    const int r = wm*32 + im*16 + (lane>>2) + rr*8;
                    float v1 = acc[im][j][rr*2+0];
                    float v2 = acc[im][j][rr*2+1];
                    const int gc = n0 + cl;
                    v1 += bias[gc]; v2 += bias[gc+1];
                    Ds[r*132 + cl]   = v1;
                    Ds[r*132 + cl+1] = v2;
                }
            }
        }
        __syncthreads();
        const int row  = tid >> 1;
        const int half = tid & 1;
        const int m = m0 + row;
        if (m < Mn){
            float* dst = Out + (size_t)m*Cn + n0 + half*64;
            const float* src = &Ds[row*132 + half*64];
#pragma unroll
            for (int j = 0; j < 64; j += 4)
                *(float4*)&dst[j] = *(const float4*)&src[j];
        }
    }
}

// ---------------------------------------------------------------------------
// HMMA flash attention, fp16 2-term: S=(Qh+Ql)K, O+=(Ph+Pl)V. (unchanged)
// ---------------------------------------------------------------------------
#define AT_PITCH 144
#define AT_TILE  (64*AT_PITCH)       // 9216
#define KV_STAGE (2*AT_TILE)         // 18432 : K | V
#define AT_SMEM  (36864 + 2*KV_STAGE) // 73728
#define NTkv ((Nn+63)/64)            // 10

__global__ __launch_bounds__(256,2) void attn_tc()
{
    extern __shared__ char sm[];
    const uint32_t smb = smem_u32(sm);
    const int tid  = threadIdx.x;
    const int wid  = tid >> 5;
    const int lane = tid & 31;
    const int qt   = blockIdx.x;
    const int bh   = blockIdx.y;
    const int bb   = bh / Hn;
    const int h    = bh - bb*Hn;

    const __half* Qh = g_qh + (size_t)bh*Nn*Dn;
    const __half* Ql = g_ql + (size_t)bh*Nn*Dn;
    const __half* Kp = g_k  + (size_t)bh*Nn*Dn;
    const __half* Vp = g_v  + (size_t)bh*Nn*Dn;

    {
#pragma unroll
        for (int i = 0; i < 4; i++){
            const int idx = tid + i*256;
            const int r   = idx >> 3;
            const int j   = idx & 7;
            const int gr  = qt*128 + r;
            uint4 vh = make_uint4(0,0,0,0), vl = vh;
            if (gr < Nn){
                vh = *(const uint4*)(Qh + (size_t)gr*Dn + j*8);
                vl = *(const uint4*)(Ql + (size_t)gr*Dn + j*8);
            }
            *(uint4*)(sm + r*AT_PITCH + j*16)         = vh;
            *(uint4*)(sm + 18432 + r*AT_PITCH + j*16) = vl;
        }
    }

#define ISSUE_KV(t_, buf_) do{ \
    const int kv0 = (t_)*64; \
    const uint32_t bp = smb + 36864u + (uint32_t)(buf_)*KV_STAGE; \
    _Pragma("unroll") \
    for (int i_ = 0; i_ < 4; i_++){ \
        const int idx = tid + i_*256; \
        const int ts  = idx >> 9; \
        const int rem = idx & 511; \
        const int r_  = rem >> 3; \
        const int j_  = rem & 7; \
        const int gr  = kv0 + r_; \
        const __half* src = ts ? Vp : Kp; \
        const uint32_t n_ = (gr < Nn) ? 16u : 0u; \
        cpa(bp + (uint32_t)ts*AT_TILE + (uint32_t)(r_*AT_PITCH + j_*16), \
            src + (size_t)gr*Dn + j_*8, n_); \
    } \
    asm volatile("cp.async.commit_group;":::"memory"); \
}while(0)

    ISSUE_KV(0, 0);
    ISSUE_KV(1, 1);

    __syncthreads();
    uint32_t qfh[4][4], qfl[4][4];
    {
        const uint32_t qa = smb + (uint32_t)((wid*16 + (lane&15))*AT_PITCH + (lane>>4)*16);
#pragma unroll
        for (int kk = 0; kk < 4; kk++){
            ldsm4(qfh[kk], qa + kk*32);
            ldsm4(qfl[kk], qa + 18432 + kk*32);
        }
    }

    float m0r = -1e30f, m1r = -1e30f, l0r = 0.f, l1r = 0.f;
    float o[8][4];
#pragma unroll
    for (int j=0;j<8;j++)
#pragma unroll
        for (int q=0;q<4;q++) o[j][q] = 0.f;

    for (int t = 0; t < NTkv; t++){
        if (t < NTkv-1) asm volatile("cp.async.wait_group 1;":::"memory");
        else            asm volatile("cp.async.wait_group 0;":::"memory");
        __syncthreads();

        const uint32_t sb = smb + 36864u + (uint32_t)(t&1)*KV_STAGE;

        float s[8][4];
#pragma unroll
        for (int j=0;j<8;j++)
#pragma unroll
            for (int q=0;q<4;q++) s[j][q] = 0.f;

#pragma unroll
        for (int kk = 0; kk < 4; kk++){
            uint32_t kh[4][4];
#pragma unroll
            for (int g = 0; g < 4; g++){
                const uint32_t ka = sb
                    + (uint32_t)((g*16 + (lane&7) + ((lane>>4)<<3))*AT_PITCH
                                 + ((lane>>3)&1)*16 + kk*32);
                ldsm4(kh[g], ka);
            }
#pragma unroll
            for (int j = 0; j < 8; j++)
                mma16816h(s[j], qfh[kk], kh[j>>1][(j&1)*2], kh[j>>1][(j&1)*2+1]);
#pragma unroll
            for (int j = 0; j < 8; j++)
                mma16816h(s[j], qfl[kk], kh[j>>1][(j&1)*2], kh[j>>1][(j&1)*2+1]);
        }

        if (t == NTkv-1){
#pragma unroll
            for (int j = 0; j < 8; j++){
                const int c0 = t*64 + j*8 + (lane&3)*2;
                if (c0   >= Nn){ s[j][0] = -1e30f; s[j][2] = -1e30f; }
                if (c0+1 >= Nn){ s[j][1] = -1e30f; s[j][3] = -1e30f; }
            }
        }
        float mx0 = -1e30f, mx1 = -1e30f;
#pragma unroll
        for (int j = 0; j < 8; j++){
            mx0 = fmaxf(mx0, fmaxf(s[j][0], s[j][1]));
            mx1 = fmaxf(mx1, fmaxf(s[j][2], s[j][3]));
        }
        mx0 = fmaxf(mx0, __shfl_xor_sync(0xffffffffu, mx0, 1));
        mx0 = fmaxf(mx0, __shfl_xor_sync(0xffffffffu, mx0, 2));
        mx1 = fmaxf(mx1, __shfl_xor_sync(0xffffffffu, mx1, 1));
        mx1 = fmaxf(mx1, __shfl_xor_sync(0xffffffffu, mx1, 2));
        const float mn0 = fmaxf(m0r, mx0), mn1 = fmaxf(m1r, mx1);
        const float al0 = __expf(m0r - mn0), al1 = __expf(m1r - mn1);
        float rs0 = 0.f, rs1 = 0.f;
#pragma unroll
        for (int j = 0; j < 8; j++){
            s[j][0] = __expf(s[j][0]-mn0); s[j][1] = __expf(s[j][1]-mn0);
            s[j][2] = __expf(s[j][2]-mn1); s[j][3] = __expf(s[j][3]-mn1);
            rs0 += s[j][0] + s[j][1];
            rs1 += s[j][2] + s[j][3];
        }
        rs0 += __shfl_xor_sync(0xffffffffu, rs0, 1);
        rs0 += __shfl_xor_sync(0xffffffffu, rs0, 2);
        rs1 += __shfl_xor_sync(0xffffffffu, rs1, 1);
        rs1 += __shfl_xor_sync(0xffffffffu, rs1, 2);
        l0r = l0r*al0 + rs0;  m0r = mn0;
        l1r = l1r*al1 + rs1;  m1r = mn1;
#pragma unroll
        for (int j = 0; j < 8; j++){
            o[j][0] *= al0; o[j][1] *= al0;
            o[j][2] *= al1; o[j][3] *= al1;
        }

#pragma unroll
        for (int kk = 0; kk < 4; kk++){
            uint32_t pha[4], pla[4];
            {
                const int j0 = 2*kk, j1 = 2*kk+1;
                float h0, h1;
                h0 = __half2float(__float2half_rn(s[j0][0]));
                h1 = __half2float(__float2half_rn(s[j0][1]));
                pha[0] = packh(s[j0][0], s[j0][1]);
                pla[0] = packh(s[j0][0]-h0, s[j0][1]-h1);
                h0 = __half2float(__float2half_rn(s[j0][2]));
                h1 = __half2float(__float2half_rn(s[j0][3]));
                pha[1] = packh(s[j0][2], s[j0][3]);
                pla[1] = packh(s[j0][2]-h0, s[j0][3]-h1);
                h0 = __half2float(__float2half_rn(s[j1][0]));
                h1 = __half2float(__float2half_rn(s[j1][1]));
                pha[2] = packh(s[j1][0], s[j1][1]);
                pla[2] = packh(s[j1][0]-h0, s[j1][1]-h1);
                h0 = __half2float(__float2half_rn(s[j1][2]));
                h1 = __half2float(__float2half_rn(s[j1][3]));
                pha[3] = packh(s[j1][2], s[j1][3]);
                pla[3] = packh(s[j1][2]-h0, s[j1][3]-h1);
            }
            uint32_t vh[4][4];
#pragma unroll
            for (int g = 0; g < 4; g++){
                const uint32_t va = sb + AT_TILE
                    + (uint32_t)((kk*16 + (lane&7) + ((lane>>3)&1)*8)*AT_PITCH
                                 + ((lane>>4)*8 + g*16)*2);
                ldsm4t(vh[g], va);
            }
#pragma unroll
            for (int j = 0; j < 8; j++)
                mma16816h(o[j], pha, vh[j>>1][(j&1)*2], vh[j>>1][(j&1)*2+1]);
#pragma unroll
            for (int j = 0; j < 8; j++)
                mma16816h(o[j], pla, vh[j>>1][(j&1)*2], vh[j>>1][(j&1)*2+1]);
        }
        __syncthreads();
        if (t+2 < NTkv) ISSUE_KV(t+2, t&1);
    }
#undef ISSUE_KV

    const float inv0 = 1.f / l0r, inv1 = 1.f / l1r;
    const int r0 = qt*128 + wid*16 + (lane>>2);
    const int r1 = r0 + 8;
#pragma unroll
    for (int j = 0; j < 8; j++){
        const int col = h*Dn + j*8 + (lane&3)*2;
        if (r0 < Nn)
            store_pairh(g_aoh, g_aol, (size_t)(bb*Nn + r0)*Cn + col,
                        o[j][0]*inv0, o[j][1]*inv0);
        if (r1 < Nn)
            store_pairh(g_aoh, g_aol, (size_t)(bb*Nn + r1)*Cn + col,
                        o[j][2]*inv1, o[j][3]*inv1);
    }
}

// ---------------------------------------------------------------------------
extern "C" void kernel_launch(void* const* d_in, const int* in_sizes, int n_in,
                              void* d_out, int out_size)
{
    (void)in_sizes; (void)n_in; (void)out_size;
    const float* x      = (const float*)d_in[0];
    const float* w_qkv  = (const float*)d_in[1];
    const float* w_proj = (const float*)d_in[2];
    const float* b_proj = (const float*)d_in[3];
    const float* cosb   = (const float*)d_in[4];
    const float* sinb   = (const float*)d_in[5];
    float* out = (float*)d_out;

    cudaFuncSetAttribute(gemm_h2<0>, cudaFuncAttributeMaxDynamicSharedMemorySize, SMEM_GM);
    cudaFuncSetAttribute(gemm_h2<1>, cudaFuncAttributeMaxDynamicSharedMemorySize, SMEM_GM);
    cudaFuncSetAttribute(attn_tc,    cudaFuncAttributeMaxDynamicSharedMemorySize, AT_SMEM);

    __half *xh, *xl, *wq, *wp, *aoh, *aol;
    cudaGetSymbolAddress((void**)&xh,  g_xh);  cudaGetSymbolAddress((void**)&xl,  g_xl);
    cudaGetSymbolAddress((void**)&wq,  g_wq);  cudaGetSymbolAddress((void**)&wp,  g_wp);
    cudaGetSymbolAddress((void**)&aoh, g_aoh); cudaGetSymbolAddress((void**)&aol, g_aol);

    conv_all<<<NBX + NBQ + NBP, 256>>>(x, w_qkv, w_proj, xh, xl, wq, wp);

    const int MT = (Mn + 127) / 128;   // 145
    gemm_h2<0><<<dim3(QKV_N/128, MT), 256, SMEM_GM>>>(xh, xl, wq, cosb, sinb,
                                                      nullptr, nullptr);
    attn_tc<<<dim3((Nn+127)/128, Bn*Hn), 256, AT_SMEM>>>();
    gemm_h2<1><<<dim3(Cn/128, MT), 256, SMEM_GM>>>(aoh, aol, wp, nullptr, nullptr,
                                                   b_proj, out);
}

// round 12
// speedup vs baseline: 2.0897x; 1.0003x over previous
#include <cuda_runtime.h>
#include <cuda_bf16.h>
#include <cuda_fp16.h>
#include <cstdint>

#define Bn 32
#define Nn 577
#define Cn 768
#define Hn 12
#define Dn 64
#define Mn (Bn*Nn)          // 18464
#define QKV_N (3*Cn)        // 2304
#define BHD ((size_t)Bn*Hn*Nn*Dn)   // 14,180,352

// Scratch (__device__ globals)
__device__ __align__(16) __half g_xh[(size_t)Mn*Cn], g_xl[(size_t)Mn*Cn];   // x split fp16
__device__ __align__(16) __half g_wq[(size_t)QKV_N*Cn];                      // w_qkv fp16
__device__ __align__(16) __half g_wp[(size_t)Cn*Cn];                         // w_proj fp16
__device__ __align__(16) __half g_qh[BHD], g_ql[BHD];                        // Q fp16 hi/lo
__device__ __align__(16) __half g_k[BHD], g_v[BHD];                          // K,V fp16
__device__ __align__(16) __half g_aoh[(size_t)Mn*Cn], g_aol[(size_t)Mn*Cn];  // AO fp16 hi/lo

// ---------------------------------------------------------------------------
// helpers
// ---------------------------------------------------------------------------
__device__ __forceinline__ uint32_t smem_u32(const void* p){
    uint32_t a;
    asm("{ .reg .u64 t; cvta.to.shared.u64 t, %1; cvt.u32.u64 %0, t; }"
        : "=r"(a) : "l"(p));
    return a;
}
__device__ __forceinline__ void ldsm4(uint32_t (&r)[4], uint32_t a){
    asm volatile("ldmatrix.sync.aligned.m8n8.x4.shared.b16 {%0,%1,%2,%3}, [%4];"
        : "=r"(r[0]),"=r"(r[1]),"=r"(r[2]),"=r"(r[3]) : "r"(a));
}
__device__ __forceinline__ void ldsm4t(uint32_t (&r)[4], uint32_t a){
    asm volatile("ldmatrix.sync.aligned.m8n8.x4.trans.shared.b16 {%0,%1,%2,%3}, [%4];"
        : "=r"(r[0]),"=r"(r[1]),"=r"(r[2]),"=r"(r[3]) : "r"(a));
}
__device__ __forceinline__ void mma16816h(float* c, const uint32_t* a,
                                          uint32_t b0, uint32_t b1){
    asm volatile("mma.sync.aligned.m16n8k16.row.col.f32.f16.f16.f32 "
        "{%0,%1,%2,%3}, {%4,%5,%6,%7}, {%8,%9}, {%0,%1,%2,%3};"
        : "+f"(c[0]),"+f"(c[1]),"+f"(c[2]),"+f"(c[3])
        : "r"(a[0]),"r"(a[1]),"r"(a[2]),"r"(a[3]), "r"(b0),"r"(b1));
}
__device__ __forceinline__ void cpa(uint32_t s, const void* g, uint32_t n){
    asm volatile("cp.async.cg.shared.global [%0], [%1], 16, %2;"
                 :: "r"(s), "l"(g), "r"(n) : "memory");
}
__device__ __forceinline__ uint32_t packh(float x, float y){
    __half2 t = __floats2half2_rn(x, y);
    return *reinterpret_cast<uint32_t*>(&t);
}
__device__ __forceinline__ void store_pairh(__half* dh, __half* dl,
                                            size_t idx, float v1, float v2){
    const __half h1 = __float2half_rn(v1), h2 = __float2half_rn(v2);
    uint32_t hp; { __half2 t; t.x=h1; t.y=h2; hp=*reinterpret_cast<uint32_t*>(&t); }
    *reinterpret_cast<uint32_t*>(dh + idx) = hp;
    *reinterpret_cast<uint32_t*>(dl + idx) =
        packh(v1 - __half2float(h1), v2 - __half2float(h2));
}

// ---------------------------------------------------------------------------
// merged conversion kernel: x -> split fp16 hi/lo; w_qkv, w_proj -> fp16
// ---------------------------------------------------------------------------
#define NBX ((Mn*Cn)/1024)        // 13848
#define NBQ ((QKV_N*Cn)/1024)     // 1728
#define NBP ((Cn*Cn)/1024)        // 576

__global__ __launch_bounds__(256) void conv_all(
    const float* __restrict__ x, const float* __restrict__ wq,
    const float* __restrict__ wp,
    __half* __restrict__ xh, __half* __restrict__ xl,
    __half* __restrict__ wqd, __half* __restrict__ wpd)
{
    const int b = blockIdx.x;
    const int t4 = threadIdx.x * 4;
    if (b < NBX){
        const int i = b*1024 + t4;
        float4 v = *(const float4*)(x + i);
        const float hx = __half2float(__float2half_rn(v.x));
        const float hy = __half2float(__float2half_rn(v.y));
        const float hz = __half2float(__float2half_rn(v.z));
        const float hw = __half2float(__float2half_rn(v.w));
        *(uint2*)(xh + i) = make_uint2(packh(v.x, v.y), packh(v.z, v.w));
        *(uint2*)(xl + i) = make_uint2(packh(v.x-hx, v.y-hy), packh(v.z-hz, v.w-hw));
    } else if (b < NBX + NBQ){
        const int i = (b - NBX)*1024 + t4;
        float4 v = *(const float4*)(wq + i);
        *(uint2*)(wqd + i) = make_uint2(packh(v.x, v.y), packh(v.z, v.w));
    } else {
        const int i = (b - NBX - NBQ)*1024 + t4;
        float4 v = *(const float4*)(wp + i);
        *(uint2*)(wpd + i) = make_uint2(packh(v.x, v.y), packh(v.z, v.w));
    }
}

// ---------------------------------------------------------------------------
// fp16 2-term GEMM (Ah·B + Al·B), k-stage 64, 2-deep cp.async pipe, 2 CTAs/SM.
// EPI==0: RoPE + q-scale(incl. log2e) -> fp16 q hi/lo, k/v single, [B,H,N,D]
// EPI==1: +bias -> fp32 Out
// ---------------------------------------------------------------------------
#define KS2 64
#define NSTG2 (Cn/KS2)        // 12
#define TILE16K 16384
#define GSTG_B (3*TILE16K)    // 49152 : Ah|Al|B
#define SMEM_GM (2*GSTG_B)    // 98304

#define SWZ128(row_, grp_) ((uint32_t)(row_)*128u + ((((uint32_t)(grp_)) ^ ((uint32_t)(row_)&7u))<<4))

template<int EPI>
__global__ __launch_bounds__(256,2) void gemm_h2(
    const __half* __restrict__ Ah, const __half* __restrict__ Al,
    const __half* __restrict__ Bh,
    const float* __restrict__ cosb, const float* __restrict__ sinb,
    const float* __restrict__ bias, float* __restrict__ Out)
{
    extern __shared__ char sm[];
    const uint32_t smb = smem_u32(sm);

    const int tid  = threadIdx.x;
    const int wid  = tid >> 5;
    const int lane = tid & 31;
    const int m0 = blockIdx.y * 128;
    const int n0 = blockIdx.x * 128;
    const int wm = wid & 3;
    const int wn = wid >> 2;

    float acc[2][8][4];
#pragma unroll
    for (int im=0;im<2;im++)
#pragma unroll
        for (int j=0;j<8;j++)
#pragma unroll
            for (int q=0;q<4;q++) acc[im][j][q] = 0.f;

#define GISSUE(s_, b_) do{ \
    const uint32_t bb_ = smb + (uint32_t)(b_)*GSTG_B; \
    const int kt_ = (s_)*KS2; \
    _Pragma("unroll") \
    for (int r_ = 0; r_ < 4; r_++){ \
        const int idx_ = tid + r_*256; \
        const uint32_t row_ = (uint32_t)(idx_ >> 3); \
        const uint32_t grp_ = (uint32_t)(idx_ & 7); \
        const uint32_t dst_ = bb_ + SWZ128(row_, grp_); \
        const uint32_t an_  = ((int)(m0 + row_) < Mn) ? 16u : 0u; \
        const size_t aoff_ = (size_t)(m0 + row_)*Cn + kt_ + grp_*8; \
        const size_t boff_ = (size_t)(n0 + row_)*Cn + kt_ + grp_*8; \
        cpa(dst_,             Ah + aoff_, an_); \
        cpa(dst_ + TILE16K,   Al + aoff_, an_); \
        cpa(dst_ + 2*TILE16K, Bh + boff_, 16u); \
    } \
    asm volatile("cp.async.commit_group;":::"memory"); \
}while(0)

    GISSUE(0, 0);
    GISSUE(1, 1);

    const uint32_t ar0 = (uint32_t)(wm*32 + (lane & 15));
    const uint32_t ar1 = ar0 + 16;
    const uint32_t brb = (uint32_t)(wn*64 + (lane & 7) + ((lane >> 4) << 3));

    for (int s = 0; s < NSTG2; s++){
        if (s < NSTG2-1) asm volatile("cp.async.wait_group 1;":::"memory");
        else             asm volatile("cp.async.wait_group 0;":::"memory");
        __syncthreads();

        const uint32_t sb = smb + (uint32_t)(s & 1)*GSTG_B;
#pragma unroll
        for (int kk = 0; kk < 4; kk++){
            const uint32_t gA = (uint32_t)(kk*2 + (lane >> 4));
            const uint32_t gB = (uint32_t)(kk*2 + ((lane >> 3) & 1));
            uint32_t ah[2][4], al[2][4], bhf[4][4];
            ldsm4(ah[0], sb + SWZ128(ar0, gA));
            ldsm4(ah[1], sb + SWZ128(ar1, gA));
            ldsm4(al[0], sb + TILE16K + SWZ128(ar0, gA));
            ldsm4(al[1], sb + TILE16K + SWZ128(ar1, gA));
#pragma unroll
            for (int t2 = 0; t2 < 4; t2++){
                const uint32_t br = brb + (uint32_t)(t2*16);
                ldsm4(bhf[t2], sb + 2*TILE16K + SWZ128(br, gB));
            }
#pragma unroll
            for (int im = 0; im < 2; im++)
#pragma unroll
                for (int j = 0; j < 8; j++)
                    mma16816h(acc[im][j], ah[im],
                              bhf[j>>1][(j&1)*2], bhf[j>>1][(j&1)*2+1]);
#pragma unroll
            for (int im = 0; im < 2; im++)
#pragma unroll
                for (int j = 0; j < 8; j++)
                    mma16816h(acc[im][j], al[im],
                              bhf[j>>1][(j&1)*2], bhf[j>>1][(j&1)*2+1]);
        }
        __syncthreads();
        if (s + 2 < NSTG2) GISSUE(s + 2, s & 1);
    }
#undef GISSUE

    if (EPI == 0){
        // q scale folds HEAD_DIM^-0.5 and log2e (softmax runs in exp2 domain)
        const float QSCALE = 0.125f * 1.44269504088896f;
        // hoist per-row batch/token decode (4 distinct rows per thread)
        int bb4[2][2], n4[2][2];
#pragma unroll
        for (int im = 0; im < 2; im++)
#pragma unroll
            for (int rr = 0; rr < 2; rr++){
                const int m = m0 + wm*32 + im*16 + (lane>>2) + rr*8;
                const int bb = (m < Mn) ? (m / Nn) : 0;
                bb4[im][rr] = bb;
                n4[im][rr]  = m - bb*Nn;
            }
#pragma unroll
        for (int im = 0; im < 2; im++){
#pragma unroll
            for (int j = 0; j < 8; j++){
                const int cl = wn*64 + j*8 + (lane&3)*2;
                const int gc  = n0 + cl;
                const int sec = gc / Cn;
                const int rem = gc - sec*Cn;
                const int hh  = rem >> 6;
                const int d   = rem & 63;
#pragma unroll
                for (int rr = 0; rr < 2; rr++){
                    const int m = m0 + wm*32 + im*16 + (lane>>2) + rr*8;
                    if (m >= Mn) continue;
                    float v1 = acc[im][j][rr*2+0];
                    float v2 = acc[im][j][rr*2+1];
                    const int bb = bb4[im][rr];
                    const int n  = n4[im][rr];
                    if (sec < 2 && n > 0){
                        const float cs = cosb[(n-1)*(Dn/2) + (d>>1)];
                        const float sn = sinb[(n-1)*(Dn/2) + (d>>1)];
                        const float r1 = v1*cs - v2*sn;
                        const float r2 = v1*sn + v2*cs;
                        v1 = r1; v2 = r2;
                    }
                    if (sec == 0){ v1 *= QSCALE; v2 *= QSCALE; }
                    const size_t idx = ((size_t)(bb*Hn + hh)*Nn + n)*Dn + d;
                    if (sec == 0)      store_pairh(g_qh, g_ql, idx, v1, v2);
                    else if (sec == 1) *reinterpret_cast<uint32_t*>(g_k + idx) = packh(v1, v2);
                    else               *reinterpret_cast<uint32_t*>(g_v + idx) = packh(v1, v2);
                }
            }
        }
    } else {
        float* Ds = (float*)sm;
#pragma unroll
        for (int im = 0; im < 2; im++){
#pragma unroll
            for (int j = 0; j < 8; j++){
                const int cl = wn*64 + j*8 + (lane&3)*2;
#pragma unroll
                for (int rr = 0; rr < 2; rr++){
                    const int r = wm*32 + im*16 + (lane>>2) + rr*8;
                    float v1 = acc[im][j][rr*2+0];
                    float v2 = acc[im][j][rr*2+1];
                    const int gc = n0 + cl;
                    v1 += bias[gc]; v2 += bias[gc+1];
                    Ds[r*132 + cl]   = v1;
                    Ds[r*132 + cl+1] = v2;
                }
            }
        }
        __syncthreads();
        const int row  = tid >> 1;
        const int half = tid & 1;
        const int m = m0 + row;
        if (m < Mn){
            float* dst = Out + (size_t)m*Cn + n0 + half*64;
            const float* src = &Ds[row*132 + half*64];
#pragma unroll
            for (int j = 0; j < 64; j += 4)
                *(float4*)&dst[j] = *(const float4*)&src[j];
        }
    }
}

// ---------------------------------------------------------------------------
// HMMA flash attention, fp16 2-term, exp2 softmax (log2e pre-folded into Q).
// KV: 3-deep cp.async ring -> single __syncthreads per kv-tile.
// ---------------------------------------------------------------------------
#define AT_PITCH 144
#define AT_TILE  (64*AT_PITCH)        // 9216
#define KV_STAGE (2*AT_TILE)          // 18432 : K | V
#define AT_SMEM  (36864 + 3*KV_STAGE) // 92160
#define NTkv ((Nn+63)/64)             // 10

__global__ __launch_bounds__(256,2) void attn_tc()
{
    extern __shared__ char sm[];
    const uint32_t smb = smem_u32(sm);
    const int tid  = threadIdx.x;
    const int wid  = tid >> 5;
    const int lane = tid & 31;
    const int qt   = blockIdx.x;
    const int bh   = blockIdx.y;
    const int bb   = bh / Hn;
    const int h    = bh - bb*Hn;

    const __half* Qh = g_qh + (size_t)bh*Nn*Dn;
    const __half* Ql = g_ql + (size_t)bh*Nn*Dn;
    const __half* Kp = g_k  + (size_t)bh*Nn*Dn;
    const __half* Vp = g_v  + (size_t)bh*Nn*Dn;

    // ---- stage Q (128 rows x 64 fp16) hi at 0, lo at 18432
    {
#pragma unroll
        for (int i = 0; i < 4; i++){
            const int idx = tid + i*256;
            const int r   = idx >> 3;
            const int j   = idx & 7;
            const int gr  = qt*128 + r;
            uint4 vh = make_uint4(0,0,0,0), vl = vh;
            if (gr < Nn){
                vh = *(const uint4*)(Qh + (size_t)gr*Dn + j*8);
                vl = *(const uint4*)(Ql + (size_t)gr*Dn + j*8);
            }
            *(uint4*)(sm + r*AT_PITCH + j*16)         = vh;
            *(uint4*)(sm + 18432 + r*AT_PITCH + j*16) = vl;
        }
    }

#define ISSUE_KV(t_, buf_) do{ \
    const int kv0 = (t_)*64; \
    const uint32_t bp = smb + 36864u + (uint32_t)(buf_)*KV_STAGE; \
    _Pragma("unroll") \
    for (int i_ = 0; i_ < 4; i_++){ \
        const int idx = tid + i_*256; \
        const int ts  = idx >> 9; \
        const int rem = idx & 511; \
        const int r_  = rem >> 3; \
        const int j_  = rem & 7; \
        const int gr  = kv0 + r_; \
        const __half* src = ts ? Vp : Kp; \
        const uint32_t n_ = (gr < Nn) ? 16u : 0u; \
        cpa(bp + (uint32_t)ts*AT_TILE + (uint32_t)(r_*AT_PITCH + j_*16), \
            src + (size_t)gr*Dn + j_*8, n_); \
    } \
    asm volatile("cp.async.commit_group;":::"memory"); \
}while(0)

    ISSUE_KV(0, 0);
    ISSUE_KV(1, 1);

    __syncthreads();        // Q staged (plain STS) before ldsm
    uint32_t qfh[4][4], qfl[4][4];
    {
        const uint32_t qa = smb + (uint32_t)((wid*16 + (lane&15))*AT_PITCH + (lane>>4)*16);
#pragma unroll
        for (int kk = 0; kk < 4; kk++){
            ldsm4(qfh[kk], qa + kk*32);
            ldsm4(qfl[kk], qa + 18432 + kk*32);
        }
    }

    float m0r = -1e30f, m1r = -1e30f, l0r = 0.f, l1r = 0.f;
    float o[8][4];
#pragma unroll
    for (int j=0;j<8;j++)
#pragma unroll
        for (int q=0;q<4;q++) o[j][q] = 0.f;

    int buf = 0;    // t % 3
    for (int t = 0; t < NTkv; t++){
        if (t < NTkv-1) asm volatile("cp.async.wait_group 1;":::"memory");
        else            asm volatile("cp.async.wait_group 0;":::"memory");
        __syncthreads();   // single barrier per tile (3-deep ring makes the
                           // post-compute barrier unnecessary: ISSUE below
                           // writes the buffer last read at t-1)

        const uint32_t sb = smb + 36864u + (uint32_t)buf*KV_STAGE;

        // ---- S = (Qh + Ql) K^T   (scores already in log2 domain)
        float s[8][4];
#pragma unroll
        for (int j=0;j<8;j++)
#pragma unroll
            for (int q=0;q<4;q++) s[j][q] = 0.f;

#pragma unroll
        for (int kk = 0; kk < 4; kk++){
            uint32_t kh[4][4];
#pragma unroll
            for (int g = 0; g < 4; g++){
                const uint32_t ka = sb
                    + (uint32_t)((g*16 + (lane&7) + ((lane>>4)<<3))*AT_PITCH
                                 + ((lane>>3)&1)*16 + kk*32);
                ldsm4(kh[g], ka);
            }
#pragma unroll
            for (int j = 0; j < 8; j++)
                mma16816h(s[j], qfh[kk], kh[j>>1][(j&1)*2], kh[j>>1][(j&1)*2+1]);
#pragma unroll
            for (int j = 0; j < 8; j++)
                mma16816h(s[j], qfl[kk], kh[j>>1][(j&1)*2], kh[j>>1][(j&1)*2+1]);
        }

        // ---- mask + online softmax (exp2 domain)
        if (t == NTkv-1){
#pragma unroll
            for (int j = 0; j < 8; j++){
                const int c0 = t*64 + j*8 + (lane&3)*2;
                if (c0   >= Nn){ s[j][0] = -1e30f; s[j][2] = -1e30f; }
                if (c0+1 >= Nn){ s[j][1] = -1e30f; s[j][3] = -1e30f; }
            }
        }
        float mx0 = -1e30f, mx1 = -1e30f;
#pragma unroll
        for (int j = 0; j < 8; j++){
            mx0 = fmaxf(mx0, fmaxf(s[j][0], s[j][1]));
            mx1 = fmaxf(mx1, fmaxf(s[j][2], s[j][3]));
        }
        mx0 = fmaxf(mx0, __shfl_xor_sync(0xffffffffu, mx0, 1));
        mx0 = fmaxf(mx0, __shfl_xor_sync(0xffffffffu, mx0, 2));
        mx1 = fmaxf(mx1, __shfl_xor_sync(0xffffffffu, mx1, 1));
        mx1 = fmaxf(mx1, __shfl_xor_sync(0xffffffffu, mx1, 2));
        const float mn0 = fmaxf(m0r, mx0), mn1 = fmaxf(m1r, mx1);
        const float al0 = exp2f(m0r - mn0), al1 = exp2f(m1r - mn1);
        float rs0 = 0.f, rs1 = 0.f;
#pragma unroll
        for (int j = 0; j < 8; j++){
            s[j][0] = exp2f(s[j][0]-mn0); s[j][1] = exp2f(s[j][1]-mn0);
            s[j][2] = exp2f(s[j][2]-mn1); s[j][3] = exp2f(s[j][3]-mn1);
            rs0 += s[j][0] + s[j][1];
            rs1 += s[j][2] + s[j][3];
        }
        rs0 += __shfl_xor_sync(0xffffffffu, rs0, 1);
        rs0 += __shfl_xor_sync(0xffffffffu, rs0, 2);
        rs1 += __shfl_xor_sync(0xffffffffu, rs1, 1);
        rs1 += __shfl_xor_sync(0xffffffffu, rs1, 2);
        l0r = l0r*al0 + rs0;  m0r = mn0;
        l1r = l1r*al1 + rs1;  m1r = mn1;
#pragma unroll
        for (int j = 0; j < 8; j++){
            o[j][0] *= al0; o[j][1] *= al0;
            o[j][2] *= al1; o[j][3] *= al1;
        }

        // ---- O += (Ph + Pl) V
#pragma unroll
        for (int kk = 0; kk < 4; kk++){
            uint32_t pha[4], pla[4];
            {
                const int j0 = 2*kk, j1 = 2*kk+1;
                float h0, h1;
                h0 = __half2float(__float2half_rn(s[j0][0]));
                h1 = __half2float(__float2half_rn(s[j0][1]));
                pha[0] = packh(s[j0][0], s[j0][1]);
                pla[0] = packh(s[j0][0]-h0, s[j0][1]-h1);
                h0 = __half2float(__float2half_rn(s[j0][2]));
                h1 = __half2float(__float2half_rn(s[j0][3]));
                pha[1] = packh(s[j0][2], s[j0][3]);
                pla[1] = packh(s[j0][2]-h0, s[j0][3]-h1);
                h0 = __half2float(__float2half_rn(s[j1][0]));
                h1 = __half2float(__float2half_rn(s[j1][1]));
                pha[2] = packh(s[j1][0], s[j1][1]);
                pla[2] = packh(s[j1][0]-h0, s[j1][1]-h1);
                h0 = __half2float(__float2half_rn(s[j1][2]));
                h1 = __half2float(__float2half_rn(s[j1][3]));
                pha[3] = packh(s[j1][2], s[j1][3]);
                pla[3] = packh(s[j1][2]-h0, s[j1][3]-h1);
            }
            uint32_t vh[4][4];
#pragma unroll
            for (int g = 0; g < 4; g++){
                const uint32_t va = sb + AT_TILE
                    + (uint32_t)((kk*16 + (lane&7) + ((lane>>3)&1)*8)*AT_PITCH
                                 + ((lane>>4)*8 + g*16)*2);
                ldsm4t(vh[g], va);
            }
#pragma unroll
            for (int j = 0; j < 8; j++)
                mma16816h(o[j], pha, vh[j>>1][(j&1)*2], vh[j>>1][(j&1)*2+1]);
#pragma unroll
            for (int j = 0; j < 8; j++)
                mma16816h(o[j], pla, vh[j>>1][(j&1)*2], vh[j>>1][(j&1)*2+1]);
        }

        if (t+2 < NTkv){
            const int nb = (t+2) % 3;
            ISSUE_KV(t+2, nb);
        }
        buf = (buf + 1 == 3) ? 0 : buf + 1;
    }
#undef ISSUE_KV

    // ---- normalize + store AO fp16 hi/lo
    const float inv0 = 1.f / l0r, inv1 = 1.f / l1r;
    const int r0 = qt*128 + wid*16 + (lane>>2);
    const int r1 = r0 + 8;
#pragma unroll
    for (int j = 0; j < 8; j++){
        const int col = h*Dn + j*8 + (lane&3)*2;
        if (r0 < Nn)
            store_pairh(g_aoh, g_aol, (size_t)(bb*Nn + r0)*Cn + col,
                        o[j][0]*inv0, o[j][1]*inv0);
        if (r1 < Nn)
            store_pairh(g_aoh, g_aol, (size_t)(bb*Nn + r1)*Cn + col,
                        o[j][2]*inv1, o[j][3]*inv1);
    }
}

// ---------------------------------------------------------------------------
extern "C" void kernel_launch(void* const* d_in, const int* in_sizes, int n_in,
                              void* d_out, int out_size)
{
    (void)in_sizes; (void)n_in; (void)out_size;
    const float* x      = (const float*)d_in[0];
    const float* w_qkv  = (const float*)d_in[1];
    const float* w_proj = (const float*)d_in[2];
    const float* b_proj = (const float*)d_in[3];
    const float* cosb   = (const float*)d_in[4];
    const float* sinb   = (const float*)d_in[5];
    float* out = (float*)d_out;

    cudaFuncSetAttribute(gemm_h2<0>, cudaFuncAttributeMaxDynamicSharedMemorySize, SMEM_GM);
    cudaFuncSetAttribute(gemm_h2<1>, cudaFuncAttributeMaxDynamicSharedMemorySize, SMEM_GM);
    cudaFuncSetAttribute(attn_tc,    cudaFuncAttributeMaxDynamicSharedMemorySize, AT_SMEM);

    __half *xh, *xl, *wq, *wp, *aoh, *aol;
    cudaGetSymbolAddress((void**)&xh,  g_xh);  cudaGetSymbolAddress((void**)&xl,  g_xl);
    cudaGetSymbolAddress((void**)&wq,  g_wq);  cudaGetSymbolAddress((void**)&wp,  g_wp);
    cudaGetSymbolAddress((void**)&aoh, g_aoh); cudaGetSymbolAddress((void**)&aol, g_aol);

    conv_all<<<NBX + NBQ + NBP, 256>>>(x, w_qkv, w_proj, xh, xl, wq, wp);

    const int MT = (Mn + 127) / 128;   // 145
    gemm_h2<0><<<dim3(QKV_N/128, MT), 256, SMEM_GM>>>(xh, xl, wq, cosb, sinb,
                                                      nullptr, nullptr);
    attn_tc<<<dim3((Nn+127)/128, Bn*Hn), 256, AT_SMEM>>>();
    gemm_h2<1><<<dim3(Cn/128, MT), 256, SMEM_GM>>>(aoh, aol, wp, nullptr, nullptr,
                                                   b_proj, out);
}

// round 13
// speedup vs baseline: 2.2654x; 1.0841x over previous
#include <cuda_runtime.h>
#include <cuda_bf16.h>
#include <cuda_fp16.h>
#include <cstdint>

#define Bn 32
#define Nn 577
#define Cn 768
#define Hn 12
#define Dn 64
#define Mn (Bn*Nn)          // 18464
#define QKV_N (3*Cn)        // 2304
#define BHD ((size_t)Bn*Hn*Nn*Dn)   // 14,180,352

// Scratch (__device__ globals)
__device__ __align__(16) __half g_xh[(size_t)Mn*Cn], g_xl[(size_t)Mn*Cn];   // x split fp16
__device__ __align__(16) __half g_wq[(size_t)QKV_N*Cn];                      // w_qkv fp16
__device__ __align__(16) __half g_wp[(size_t)Cn*Cn];                         // w_proj fp16
__device__ __align__(16) __half g_qh[BHD], g_ql[BHD];                        // Q fp16 hi/lo
__device__ __align__(16) __half g_k[BHD], g_v[BHD];                          // K,V fp16
__device__ __align__(16) __half g_aoh[(size_t)Mn*Cn], g_aol[(size_t)Mn*Cn];  // AO fp16 hi/lo

// ---------------------------------------------------------------------------
// helpers
// ---------------------------------------------------------------------------
__device__ __forceinline__ uint32_t smem_u32(const void* p){
    uint32_t a;
    asm("{ .reg .u64 t; cvta.to.shared.u64 t, %1; cvt.u32.u64 %0, t; }"
        : "=r"(a) : "l"(p));
    return a;
}
__device__ __forceinline__ void ldsm4(uint32_t (&r)[4], uint32_t a){
    asm volatile("ldmatrix.sync.aligned.m8n8.x4.shared.b16 {%0,%1,%2,%3}, [%4];"
        : "=r"(r[0]),"=r"(r[1]),"=r"(r[2]),"=r"(r[3]) : "r"(a));
}
__device__ __forceinline__ void ldsm4t(uint32_t (&r)[4], uint32_t a){
    asm volatile("ldmatrix.sync.aligned.m8n8.x4.trans.shared.b16 {%0,%1,%2,%3}, [%4];"
        : "=r"(r[0]),"=r"(r[1]),"=r"(r[2]),"=r"(r[3]) : "r"(a));
}
__device__ __forceinline__ void mma16816h(float* c, const uint32_t* a,
                                          uint32_t b0, uint32_t b1){
    asm volatile("mma.sync.aligned.m16n8k16.row.col.f32.f16.f16.f32 "
        "{%0,%1,%2,%3}, {%4,%5,%6,%7}, {%8,%9}, {%0,%1,%2,%3};"
        : "+f"(c[0]),"+f"(c[1]),"+f"(c[2]),"+f"(c[3])
        : "r"(a[0]),"r"(a[1]),"r"(a[2]),"r"(a[3]), "r"(b0),"r"(b1));
}
__device__ __forceinline__ void cpa(uint32_t s, const void* g, uint32_t n){
    asm volatile("cp.async.cg.shared.global [%0], [%1], 16, %2;"
                 :: "r"(s), "l"(g), "r"(n) : "memory");
}
__device__ __forceinline__ uint32_t packh(float x, float y){
    __half2 t = __floats2half2_rn(x, y);
    return *reinterpret_cast<uint32_t*>(&t);
}
__device__ __forceinline__ void store_pairh(__half* dh, __half* dl,
                                            size_t idx, float v1, float v2){
    const __half h1 = __float2half_rn(v1), h2 = __float2half_rn(v2);
    uint32_t hp; { __half2 t; t.x=h1; t.y=h2; hp=*reinterpret_cast<uint32_t*>(&t); }
    *reinterpret_cast<uint32_t*>(dh + idx) = hp;
    *reinterpret_cast<uint32_t*>(dl + idx) =
        packh(v1 - __half2float(h1), v2 - __half2float(h2));
}

// ---------------------------------------------------------------------------
// merged conversion kernel: x -> split fp16 hi/lo; w_qkv, w_proj -> fp16
// ---------------------------------------------------------------------------
#define NBX ((Mn*Cn)/1024)        // 13848
#define NBQ ((QKV_N*Cn)/1024)     // 1728
#define NBP ((Cn*Cn)/1024)        // 576

__global__ __launch_bounds__(256) void conv_all(
    const float* __restrict__ x, const float* __restrict__ wq,
    const float* __restrict__ wp,
    __half* __restrict__ xh, __half* __restrict__ xl,
    __half* __restrict__ wqd, __half* __restrict__ wpd)
{
    const int b = blockIdx.x;
    const int t4 = threadIdx.x * 4;
    if (b < NBX){
        const int i = b*1024 + t4;
        float4 v = *(const float4*)(x + i);
        const float hx = __half2float(__float2half_rn(v.x));
        const float hy = __half2float(__float2half_rn(v.y));
        const float hz = __half2float(__float2half_rn(v.z));
        const float hw = __half2float(__float2half_rn(v.w));
        *(uint2*)(xh + i) = make_uint2(packh(v.x, v.y), packh(v.z, v.w));
        *(uint2*)(xl + i) = make_uint2(packh(v.x-hx, v.y-hy), packh(v.z-hz, v.w-hw));
    } else if (b < NBX + NBQ){
        const int i = (b - NBX)*1024 + t4;
        float4 v = *(const float4*)(wq + i);
        *(uint2*)(wqd + i) = make_uint2(packh(v.x, v.y), packh(v.z, v.w));
    } else {
        const int i = (b - NBX - NBQ)*1024 + t4;
        float4 v = *(const float4*)(wp + i);
        *(uint2*)(wpd + i) = make_uint2(packh(v.x, v.y), packh(v.z, v.w));
    }
}

// ---------------------------------------------------------------------------
// fp16 2-term GEMM (Ah·B + Al·B), k-stage 64, 2-deep cp.async pipe, 2 CTAs/SM.
// EPI==0: RoPE + q-scale(incl. log2e) -> fp16 q hi/lo, k/v single, [B,H,N,D]
// EPI==1: +bias -> fp32 Out
// ---------------------------------------------------------------------------
#define KS2 64
#define NSTG2 (Cn/KS2)        // 12
#define TILE16K 16384
#define GSTG_B (3*TILE16K)    // 49152 : Ah|Al|B
#define SMEM_GM (2*GSTG_B)    // 98304

#define SWZ128(row_, grp_) ((uint32_t)(row_)*128u + ((((uint32_t)(grp_)) ^ ((uint32_t)(row_)&7u))<<4))

template<int EPI>
__global__ __launch_bounds__(256,2) void gemm_h2(
    const __half* __restrict__ Ah, const __half* __restrict__ Al,
    const __half* __restrict__ Bh,
    const float* __restrict__ cosb, const float* __restrict__ sinb,
    const float* __restrict__ bias, float* __restrict__ Out)
{
    extern __shared__ char sm[];
    const uint32_t smb = smem_u32(sm);

    const int tid  = threadIdx.x;
    const int wid  = tid >> 5;
    const int lane = tid & 31;
    const int m0 = blockIdx.y * 128;
    const int n0 = blockIdx.x * 128;
    const int wm = wid & 3;
    const int wn = wid >> 2;

    float acc[2][8][4];
#pragma unroll
    for (int im=0;im<2;im++)
#pragma unroll
        for (int j=0;j<8;j++)
#pragma unroll
            for (int q=0;q<4;q++) acc[im][j][q] = 0.f;

#define GISSUE(s_, b_) do{ \
    const uint32_t bb_ = smb + (uint32_t)(b_)*GSTG_B; \
    const int kt_ = (s_)*KS2; \
    _Pragma("unroll") \
    for (int r_ = 0; r_ < 4; r_++){ \
        const int idx_ = tid + r_*256; \
        const uint32_t row_ = (uint32_t)(idx_ >> 3); \
        const uint32_t grp_ = (uint32_t)(idx_ & 7); \
        const uint32_t dst_ = bb_ + SWZ128(row_, grp_); \
        const uint32_t an_  = ((int)(m0 + row_) < Mn) ? 16u : 0u; \
        const size_t aoff_ = (size_t)(m0 + row_)*Cn + kt_ + grp_*8; \
        const size_t boff_ = (size_t)(n0 + row_)*Cn + kt_ + grp_*8; \
        cpa(dst_,             Ah + aoff_, an_); \
        cpa(dst_ + TILE16K,   Al + aoff_, an_); \
        cpa(dst_ + 2*TILE16K, Bh + boff_, 16u); \
    } \
    asm volatile("cp.async.commit_group;":::"memory"); \
}while(0)

    GISSUE(0, 0);
    GISSUE(1, 1);

    const uint32_t ar0 = (uint32_t)(wm*32 + (lane & 15));
    const uint32_t ar1 = ar0 + 16;
    const uint32_t brb = (uint32_t)(wn*64 + (lane & 7) + ((lane >> 4) << 3));

    for (int s = 0; s < NSTG2; s++){
        if (s < NSTG2-1) asm volatile("cp.async.wait_group 1;":::"memory");
        else             asm volatile("cp.async.wait_group 0;":::"memory");
        __syncthreads();

        const uint32_t sb = smb + (uint32_t)(s & 1)*GSTG_B;
#pragma unroll
        for (int kk = 0; kk < 4; kk++){
            const uint32_t gA = (uint32_t)(kk*2 + (lane >> 4));
            const uint32_t gB = (uint32_t)(kk*2 + ((lane >> 3) & 1));
            uint32_t ah[2][4], al[2][4], bhf[4][4];
            ldsm4(ah[0], sb + SWZ128(ar0, gA));
            ldsm4(ah[1], sb + SWZ128(ar1, gA));
            ldsm4(al[0], sb + TILE16K + SWZ128(ar0, gA));
            ldsm4(al[1], sb + TILE16K + SWZ128(ar1, gA));
#pragma unroll
            for (int t2 = 0; t2 < 4; t2++){
                const uint32_t br = brb + (uint32_t)(t2*16);
                ldsm4(bhf[t2], sb + 2*TILE16K + SWZ128(br, gB));
            }
#pragma unroll
            for (int im = 0; im < 2; im++)
#pragma unroll
                for (int j = 0; j < 8; j++)
                    mma16816h(acc[im][j], ah[im],
                              bhf[j>>1][(j&1)*2], bhf[j>>1][(j&1)*2+1]);
#pragma unroll
            for (int im = 0; im < 2; im++)
#pragma unroll
                for (int j = 0; j < 8; j++)
                    mma16816h(acc[im][j], al[im],
                              bhf[j>>1][(j&1)*2], bhf[j>>1][(j&1)*2+1]);
        }
        __syncthreads();
        if (s + 2 < NSTG2) GISSUE(s + 2, s & 1);
    }
#undef GISSUE

    if (EPI == 0){
        const float QSCALE = 0.125f * 1.44269504088896f;
        int bb4[2][2], n4[2][2];
#pragma unroll
        for (int im = 0; im < 2; im++)
#pragma unroll
            for (int rr = 0; rr < 2; rr++){
                const int m = m0 + wm*32 + im*16 + (lane>>2) + rr*8;
                const int bb = (m < Mn) ? (m / Nn) : 0;
                bb4[im][rr] = bb;
                n4[im][rr]  = m - bb*Nn;
            }
#pragma unroll
        for (int im = 0; im < 2; im++){
#pragma unroll
            for (int j = 0; j < 8; j++){
                const int cl = wn*64 + j*8 + (lane&3)*2;
                const int gc  = n0 + cl;
                const int sec = gc / Cn;
                const int rem = gc - sec*Cn;
                const int hh  = rem >> 6;
                const int d   = rem & 63;
#pragma unroll
                for (int rr = 0; rr < 2; rr++){
                    const int m = m0 + wm*32 + im*16 + (lane>>2) + rr*8;
                    if (m >= Mn) continue;
                    float v1 = acc[im][j][rr*2+0];
                    float v2 = acc[im][j][rr*2+1];
                    const int bb = bb4[im][rr];
                    const int n  = n4[im][rr];
                    if (sec < 2 && n > 0){
                        const float cs = cosb[(n-1)*(Dn/2) + (d>>1)];
                        const float sn = sinb[(n-1)*(Dn/2) + (d>>1)];
                        const float r1 = v1*cs - v2*sn;
                        const float r2 = v1*sn + v2*cs;
                        v1 = r1; v2 = r2;
                    }
                    if (sec == 0){ v1 *= QSCALE; v2 *= QSCALE; }
                    const size_t idx = ((size_t)(bb*Hn + hh)*Nn + n)*Dn + d;
                    if (sec == 0)      store_pairh(g_qh, g_ql, idx, v1, v2);
                    else if (sec == 1) *reinterpret_cast<uint32_t*>(g_k + idx) = packh(v1, v2);
                    else               *reinterpret_cast<uint32_t*>(g_v + idx) = packh(v1, v2);
                }
            }
        }
    } else {
        float* Ds = (float*)sm;
#pragma unroll
        for (int im = 0; im < 2; im++){
#pragma unroll
            for (int j = 0; j < 8; j++){
                const int cl = wn*64 + j*8 + (lane&3)*2;
#pragma unroll
                for (int rr = 0; rr < 2; rr++){
                    const int r = wm*32 + im*16 + (lane>>2) + rr*8;
                    float v1 = acc[im][j][rr*2+0];
                    float v2 = acc[im][j][rr*2+1];
                    const int gc = n0 + cl;
                    v1 += bias[gc]; v2 += bias[gc+1];
                    Ds[r*132 + cl]   = v1;
                    Ds[r*132 + cl+1] = v2;
                }
            }
        }
        __syncthreads();
        const int row  = tid >> 1;
        const int half = tid & 1;
        const int m = m0 + row;
        if (m < Mn){
            float* dst = Out + (size_t)m*Cn + n0 + half*64;
            const float* src = &Ds[row*132 + half*64];
#pragma unroll
            for (int j = 0; j < 64; j += 4)
                *(float4*)&dst[j] = *(const float4*)&src[j];
        }
    }
}

// ---------------------------------------------------------------------------
// HMMA flash attention, fp16: S=(Qh+Ql)K (2 terms), O += P·V (P single fp16).
// exp2 softmax (log2e folded into Q). 3-deep cp.async KV ring.
// ---------------------------------------------------------------------------
#define AT_PITCH 144
#define AT_TILE  (64*AT_PITCH)        // 9216
#define KV_STAGE (2*AT_TILE)          // 18432 : K | V
#define AT_SMEM  (36864 + 3*KV_STAGE) // 92160
#define NTkv ((Nn+63)/64)             // 10

__global__ __launch_bounds__(256,2) void attn_tc()
{
    extern __shared__ char sm[];
    const uint32_t smb = smem_u32(sm);
    const int tid  = threadIdx.x;
    const int wid  = tid >> 5;
    const int lane = tid & 31;
    const int qt   = blockIdx.x;
    const int bh   = blockIdx.y;
    const int bb   = bh / Hn;
    const int h    = bh - bb*Hn;

    const __half* Qh = g_qh + (size_t)bh*Nn*Dn;
    const __half* Ql = g_ql + (size_t)bh*Nn*Dn;
    const __half* Kp = g_k  + (size_t)bh*Nn*Dn;
    const __half* Vp = g_v  + (size_t)bh*Nn*Dn;

    {
#pragma unroll
        for (int i = 0; i < 4; i++){
            const int idx = tid + i*256;
            const int r   = idx >> 3;
            const int j   = idx & 7;
            const int gr  = qt*128 + r;
            uint4 vh = make_uint4(0,0,0,0), vl = vh;
            if (gr < Nn){
                vh = *(const uint4*)(Qh + (size_t)gr*Dn + j*8);
                vl = *(const uint4*)(Ql + (size_t)gr*Dn + j*8);
            }
            *(uint4*)(sm + r*AT_PITCH + j*16)         = vh;
            *(uint4*)(sm + 18432 + r*AT_PITCH + j*16) = vl;
        }
    }

#define ISSUE_KV(t_, buf_) do{ \
    const int kv0 = (t_)*64; \
    const uint32_t bp = smb + 36864u + (uint32_t)(buf_)*KV_STAGE; \
    _Pragma("unroll") \
    for (int i_ = 0; i_ < 4; i_++){ \
        const int idx = tid + i_*256; \
        const int ts  = idx >> 9; \
        const int rem = idx & 511; \
        const int r_  = rem >> 3; \
        const int j_  = rem & 7; \
        const int gr  = kv0 + r_; \
        const __half* src = ts ? Vp : Kp; \
        const uint32_t n_ = (gr < Nn) ? 16u : 0u; \
        cpa(bp + (uint32_t)ts*AT_TILE + (uint32_t)(r_*AT_PITCH + j_*16), \
            src + (size_t)gr*Dn + j_*8, n_); \
    } \
    asm volatile("cp.async.commit_group;":::"memory"); \
}while(0)

    ISSUE_KV(0, 0);
    ISSUE_KV(1, 1);

    __syncthreads();
    uint32_t qfh[4][4], qfl[4][4];
    {
        const uint32_t qa = smb + (uint32_t)((wid*16 + (lane&15))*AT_PITCH + (lane>>4)*16);
#pragma unroll
        for (int kk = 0; kk < 4; kk++){
            ldsm4(qfh[kk], qa + kk*32);
            ldsm4(qfl[kk], qa + 18432 + kk*32);
        }
    }

    float m0r = -1e30f, m1r = -1e30f, l0r = 0.f, l1r = 0.f;
    float o[8][4];
#pragma unroll
    for (int j=0;j<8;j++)
#pragma unroll
        for (int q=0;q<4;q++) o[j][q] = 0.f;

    int buf = 0;
    for (int t = 0; t < NTkv; t++){
        if (t < NTkv-1) asm volatile("cp.async.wait_group 1;":::"memory");
        else            asm volatile("cp.async.wait_group 0;":::"memory");
        __syncthreads();

        const uint32_t sb = smb + 36864u + (uint32_t)buf*KV_STAGE;

        // ---- S = (Qh + Ql) K^T
        float s[8][4];
#pragma unroll
        for (int j=0;j<8;j++)
#pragma unroll
            for (int q=0;q<4;q++) s[j][q] = 0.f;

#pragma unroll
        for (int kk = 0; kk < 4; kk++){
            uint32_t kh[4][4];
#pragma unroll
            for (int g = 0; g < 4; g++){
                const uint32_t ka = sb
                    + (uint32_t)((g*16 + (lane&7) + ((lane>>4)<<3))*AT_PITCH
                                 + ((lane>>3)&1)*16 + kk*32);
                ldsm4(kh[g], ka);
            }
#pragma unroll
            for (int j = 0; j < 8; j++)
                mma16816h(s[j], qfh[kk], kh[j>>1][(j&1)*2], kh[j>>1][(j&1)*2+1]);
#pragma unroll
            for (int j = 0; j < 8; j++)
                mma16816h(s[j], qfl[kk], kh[j>>1][(j&1)*2], kh[j>>1][(j&1)*2+1]);
        }

        // ---- mask + online softmax (exp2 domain)
        if (t == NTkv-1){
#pragma unroll
            for (int j = 0; j < 8; j++){
                const int c0 = t*64 + j*8 + (lane&3)*2;
                if (c0   >= Nn){ s[j][0] = -1e30f; s[j][2] = -1e30f; }
                if (c0+1 >= Nn){ s[j][1] = -1e30f; s[j][3] = -1e30f; }
            }
        }
        float mx0 = -1e30f, mx1 = -1e30f;
#pragma unroll
        for (int j = 0; j < 8; j++){
            mx0 = fmaxf(mx0, fmaxf(s[j][0], s[j][1]));
            mx1 = fmaxf(mx1, fmaxf(s[j][2], s[j][3]));
        }
        mx0 = fmaxf(mx0, __shfl_xor_sync(0xffffffffu, mx0, 1));
        mx0 = fmaxf(mx0, __shfl_xor_sync(0xffffffffu, mx0, 2));
        mx1 = fmaxf(mx1, __shfl_xor_sync(0xffffffffu, mx1, 1));
        mx1 = fmaxf(mx1, __shfl_xor_sync(0xffffffffu, mx1, 2));
        const float mn0 = fmaxf(m0r, mx0), mn1 = fmaxf(m1r, mx1);
        const float al0 = exp2f(m0r - mn0), al1 = exp2f(m1r - mn1);
        float rs0 = 0.f, rs1 = 0.f;
#pragma unroll
        for (int j = 0; j < 8; j++){
            s[j][0] = exp2f(s[j][0]-mn0); s[j][1] = exp2f(s[j][1]-mn0);
            s[j][2] = exp2f(s[j][2]-mn1); s[j][3] = exp2f(s[j][3]-mn1);
            rs0 += s[j][0] + s[j][1];
            rs1 += s[j][2] + s[j][3];
        }
        rs0 += __shfl_xor_sync(0xffffffffu, rs0, 1);
        rs0 += __shfl_xor_sync(0xffffffffu, rs0, 2);
        rs1 += __shfl_xor_sync(0xffffffffu, rs1, 1);
        rs1 += __shfl_xor_sync(0xffffffffu, rs1, 2);
        l0r = l0r*al0 + rs0;  m0r = mn0;
        l1r = l1r*al1 + rs1;  m1r = mn1;
#pragma unroll
        for (int j = 0; j < 8; j++){
            o[j][0] *= al0; o[j][1] *= al0;
            o[j][2] *= al1; o[j][3] *= al1;
        }

        // ---- O += P V   (P single fp16; error ~2^-12, P normalized)
#pragma unroll
        for (int kk = 0; kk < 4; kk++){
            uint32_t pha[4];
            {
                const int j0 = 2*kk, j1 = 2*kk+1;
                pha[0] = packh(s[j0][0], s[j0][1]);
                pha[1] = packh(s[j0][2], s[j0][3]);
                pha[2] = packh(s[j1][0], s[j1][1]);
                pha[3] = packh(s[j1][2], s[j1][3]);
            }
            uint32_t vh[4][4];
#pragma unroll
            for (int g = 0; g < 4; g++){
                const uint32_t va = sb + AT_TILE
                    + (uint32_t)((kk*16 + (lane&7) + ((lane>>3)&1)*8)*AT_PITCH
                                 + ((lane>>4)*8 + g*16)*2);
                ldsm4t(vh[g], va);
            }
#pragma unroll
            for (int j = 0; j < 8; j++)
                mma16816h(o[j], pha, vh[j>>1][(j&1)*2], vh[j>>1][(j&1)*2+1]);
        }

        if (t+2 < NTkv){
            const int nb = (t+2) % 3;
            ISSUE_KV(t+2, nb);
        }
        buf = (buf + 1 == 3) ? 0 : buf + 1;
    }
#undef ISSUE_KV

    // ---- normalize + store AO fp16 hi/lo
    const float inv0 = 1.f / l0r, inv1 = 1.f / l1r;
    const int r0 = qt*128 + wid*16 + (lane>>2);
    const int r1 = r0 + 8;
#pragma unroll
    for (int j = 0; j < 8; j++){
        const int col = h*Dn + j*8 + (lane&3)*2;
        if (r0 < Nn)
            store_pairh(g_aoh, g_aol, (size_t)(bb*Nn + r0)*Cn + col,
                        o[j][0]*inv0, o[j][1]*inv0);
        if (r1 < Nn)
            store_pairh(g_aoh, g_aol, (size_t)(bb*Nn + r1)*Cn + col,
                        o[j][2]*inv1, o[j][3]*inv1);
    }
}

// ---------------------------------------------------------------------------
extern "C" void kernel_launch(void* const* d_in, const int* in_sizes, int n_in,
                              void* d_out, int out_size)
{
    (void)in_sizes; (void)n_in; (void)out_size;
    const float* x      = (const float*)d_in[0];
    const float* w_qkv  = (const float*)d_in[1];
    const float* w_proj = (const float*)d_in[2];
    const float* b_proj = (const float*)d_in[3];
    const float* cosb   = (const float*)d_in[4];
    const float* sinb   = (const float*)d_in[5];
    float* out = (float*)d_out;

    cudaFuncSetAttribute(gemm_h2<0>, cudaFuncAttributeMaxDynamicSharedMemorySize, SMEM_GM);
    cudaFuncSetAttribute(gemm_h2<1>, cudaFuncAttributeMaxDynamicSharedMemorySize, SMEM_GM);
    cudaFuncSetAttribute(attn_tc,    cudaFuncAttributeMaxDynamicSharedMemorySize, AT_SMEM);

    __half *xh, *xl, *wq, *wp, *aoh, *aol;
    cudaGetSymbolAddress((void**)&xh,  g_xh);  cudaGetSymbolAddress((void**)&xl,  g_xl);
    cudaGetSymbolAddress((void**)&wq,  g_wq);  cudaGetSymbolAddress((void**)&wp,  g_wp);
    cudaGetSymbolAddress((void**)&aoh, g_aoh); cudaGetSymbolAddress((void**)&aol, g_aol);

    conv_all<<<NBX + NBQ + NBP, 256>>>(x, w_qkv, w_proj, xh, xl, wq, wp);

    const int MT = (Mn + 127) / 128;   // 145
    gemm_h2<0><<<dim3(QKV_N/128, MT), 256, SMEM_GM>>>(xh, xl, wq, cosb, sinb,
                                                      nullptr, nullptr);
    attn_tc<<<dim3((Nn+127)/128, Bn*Hn), 256, AT_SMEM>>>();
    gemm_h2<1><<<dim3(Cn/128, MT), 256, SMEM_GM>>>(aoh, aol, wp, nullptr, nullptr,
                                                   b_proj, out);
}

// round 14
// speedup vs baseline: 2.7999x; 1.2359x over previous
#include <cuda_runtime.h>
#include <cuda_bf16.h>
#include <cuda_fp16.h>
#include <cstdint>

#define Bn 32
#define Nn 577
#define Cn 768
#define Hn 12
#define Dn 64
#define Mn (Bn*Nn)          // 18464
#define QKV_N (3*Cn)        // 2304
#define BHD ((size_t)Bn*Hn*Nn*Dn)   // 14,180,352

// Scratch (__device__ globals)
__device__ __align__(16) __half g_xh[(size_t)Mn*Cn];                         // x fp16 (single)
__device__ __align__(16) __half g_wq[(size_t)QKV_N*Cn];                      // w_qkv fp16
__device__ __align__(16) __half g_wp[(size_t)Cn*Cn];                         // w_proj fp16
__device__ __align__(16) __half g_qh[BHD], g_ql[BHD];                        // Q fp16 hi/lo
__device__ __align__(16) __half g_k[BHD], g_v[BHD];                          // K,V fp16
__device__ __align__(16) __half g_aoh[(size_t)Mn*Cn], g_aol[(size_t)Mn*Cn];  // AO fp16 hi/lo

// ---------------------------------------------------------------------------
// helpers
// ---------------------------------------------------------------------------
__device__ __forceinline__ uint32_t smem_u32(const void* p){
    uint32_t a;
    asm("{ .reg .u64 t; cvta.to.shared.u64 t, %1; cvt.u32.u64 %0, t; }"
        : "=r"(a) : "l"(p));
    return a;
}
__device__ __forceinline__ void ldsm4(uint32_t (&r)[4], uint32_t a){
    asm volatile("ldmatrix.sync.aligned.m8n8.x4.shared.b16 {%0,%1,%2,%3}, [%4];"
        : "=r"(r[0]),"=r"(r[1]),"=r"(r[2]),"=r"(r[3]) : "r"(a));
}
__device__ __forceinline__ void ldsm4t(uint32_t (&r)[4], uint32_t a){
    asm volatile("ldmatrix.sync.aligned.m8n8.x4.trans.shared.b16 {%0,%1,%2,%3}, [%4];"
        : "=r"(r[0]),"=r"(r[1]),"=r"(r[2]),"=r"(r[3]) : "r"(a));
}
__device__ __forceinline__ void mma16816h(float* c, const uint32_t* a,
                                          uint32_t b0, uint32_t b1){
    asm volatile("mma.sync.aligned.m16n8k16.row.col.f32.f16.f16.f32 "
        "{%0,%1,%2,%3}, {%4,%5,%6,%7}, {%8,%9}, {%0,%1,%2,%3};"
        : "+f"(c[0]),"+f"(c[1]),"+f"(c[2]),"+f"(c[3])
        : "r"(a[0]),"r"(a[1]),"r"(a[2]),"r"(a[3]), "r"(b0),"r"(b1));
}
__device__ __forceinline__ void cpa(uint32_t s, const void* g, uint32_t n){
    asm volatile("cp.async.cg.shared.global [%0], [%1], 16, %2;"
                 :: "r"(s), "l"(g), "r"(n) : "memory");
}
__device__ __forceinline__ uint32_t packh(float x, float y){
    __half2 t = __floats2half2_rn(x, y);
    return *reinterpret_cast<uint32_t*>(&t);
}
__device__ __forceinline__ void store_pairh(__half* dh, __half* dl,
                                            size_t idx, float v1, float v2){
    const __half h1 = __float2half_rn(v1), h2 = __float2half_rn(v2);
    uint32_t hp; { __half2 t; t.x=h1; t.y=h2; hp=*reinterpret_cast<uint32_t*>(&t); }
    *reinterpret_cast<uint32_t*>(dh + idx) = hp;
    *reinterpret_cast<uint32_t*>(dl + idx) =
        packh(v1 - __half2float(h1), v2 - __half2float(h2));
}

// ---------------------------------------------------------------------------
// merged conversion kernel: x, w_qkv, w_proj -> fp16
// ---------------------------------------------------------------------------
#define NBX ((Mn*Cn)/1024)        // 13848
#define NBQ ((QKV_N*Cn)/1024)     // 1728
#define NBP ((Cn*Cn)/1024)        // 576

__global__ __launch_bounds__(256) void conv_all(
    const float* __restrict__ x, const float* __restrict__ wq,
    const float* __restrict__ wp,
    __half* __restrict__ xh,
    __half* __restrict__ wqd, __half* __restrict__ wpd)
{
    const int b = blockIdx.x;
    const int t4 = threadIdx.x * 4;
    const float* src; __half* dst; int i;
    if (b < NBX){       src = x;  dst = xh;  i = b*1024 + t4; }
    else if (b < NBX+NBQ){ src = wq; dst = wqd; i = (b-NBX)*1024 + t4; }
    else {              src = wp; dst = wpd; i = (b-NBX-NBQ)*1024 + t4; }
    float4 v = *(const float4*)(src + i);
    *(uint2*)(dst + i) = make_uint2(packh(v.x, v.y), packh(v.z, v.w));
}

// ---------------------------------------------------------------------------
// fp16 GEMM template: NT A-terms (1 or 2) x single-fp16 B.
// NT==1: 2 tiles/stage (32KB), 3-deep pipe.  NT==2: 3 tiles/stage, 2-deep.
// EPI==0: RoPE + q-scale(incl. log2e) -> fp16 q hi/lo, k/v single, [B,H,N,D]
// EPI==1: +bias -> fp32 Out
// ---------------------------------------------------------------------------
#define KS2 64
#define NSTG2 (Cn/KS2)        // 12
#define TILE16K 16384
#define SMEM_GM 98304         // both configs use 96KB -> 2 CTAs/SM

#define SWZ128(row_, grp_) ((uint32_t)(row_)*128u + ((((uint32_t)(grp_)) ^ ((uint32_t)(row_)&7u))<<4))

template<int EPI, int NT>
__global__ __launch_bounds__(256,2) void gemm_h2(
    const __half* __restrict__ Ah, const __half* __restrict__ Al,
    const __half* __restrict__ Bh,
    const float* __restrict__ cosb, const float* __restrict__ sinb,
    const float* __restrict__ bias, float* __restrict__ Out)
{
    extern __shared__ char sm[];
    const uint32_t smb = smem_u32(sm);
    constexpr int STG_B  = (NT+1)*TILE16K;     // 32KB or 48KB
    constexpr int DEPTH  = (NT==1) ? 3 : 2;
    constexpr uint32_t BOFF = (uint32_t)NT*TILE16K;

    const int tid  = threadIdx.x;
    const int wid  = tid >> 5;
    const int lane = tid & 31;
    const int m0 = blockIdx.y * 128;
    const int n0 = blockIdx.x * 128;
    const int wm = wid & 3;
    const int wn = wid >> 2;

    float acc[2][8][4];
#pragma unroll
    for (int im=0;im<2;im++)
#pragma unroll
        for (int j=0;j<8;j++)
#pragma unroll
            for (int q=0;q<4;q++) acc[im][j][q] = 0.f;

#define GISSUE(s_, b_) do{ \
    const uint32_t bb_ = smb + (uint32_t)(b_)*STG_B; \
    const int kt_ = (s_)*KS2; \
    _Pragma("unroll") \
    for (int r_ = 0; r_ < 4; r_++){ \
        const int idx_ = tid + r_*256; \
        const uint32_t row_ = (uint32_t)(idx_ >> 3); \
        const uint32_t grp_ = (uint32_t)(idx_ & 7); \
        const uint32_t dst_ = bb_ + SWZ128(row_, grp_); \
        const uint32_t an_  = ((int)(m0 + row_) < Mn) ? 16u : 0u; \
        const size_t aoff_ = (size_t)(m0 + row_)*Cn + kt_ + grp_*8; \
        const size_t boff_ = (size_t)(n0 + row_)*Cn + kt_ + grp_*8; \
        cpa(dst_, Ah + aoff_, an_); \
        if (NT == 2) cpa(dst_ + TILE16K, Al + aoff_, an_); \
        cpa(dst_ + BOFF, Bh + boff_, 16u); \
    } \
    asm volatile("cp.async.commit_group;":::"memory"); \
}while(0)

    GISSUE(0, 0);
    GISSUE(1, 1);
    if (DEPTH == 3) GISSUE(2, 2);

    const uint32_t ar0 = (uint32_t)(wm*32 + (lane & 15));
    const uint32_t ar1 = ar0 + 16;
    const uint32_t brb = (uint32_t)(wn*64 + (lane & 7) + ((lane >> 4) << 3));

    for (int s = 0; s < NSTG2; s++){
        if (s + 2 < NSTG2 && DEPTH == 3)
            asm volatile("cp.async.wait_group 2;":::"memory");
        else if (s + 1 < NSTG2)
            asm volatile("cp.async.wait_group 1;":::"memory");
        else
            asm volatile("cp.async.wait_group 0;":::"memory");
        __syncthreads();

        const uint32_t sb = smb + (uint32_t)(s % DEPTH)*STG_B;
#pragma unroll
        for (int kk = 0; kk < 4; kk++){
            const uint32_t gA = (uint32_t)(kk*2 + (lane >> 4));
            const uint32_t gB = (uint32_t)(kk*2 + ((lane >> 3) & 1));
            uint32_t ah[2][4], al[2][4], bhf[4][4];
            ldsm4(ah[0], sb + SWZ128(ar0, gA));
            ldsm4(ah[1], sb + SWZ128(ar1, gA));
            if (NT == 2){
                ldsm4(al[0], sb + TILE16K + SWZ128(ar0, gA));
                ldsm4(al[1], sb + TILE16K + SWZ128(ar1, gA));
            }
#pragma unroll
            for (int t2 = 0; t2 < 4; t2++){
                const uint32_t br = brb + (uint32_t)(t2*16);
                ldsm4(bhf[t2], sb + BOFF + SWZ128(br, gB));
            }
#pragma unroll
            for (int im = 0; im < 2; im++)
#pragma unroll
                for (int j = 0; j < 8; j++)
                    mma16816h(acc[im][j], ah[im],
                              bhf[j>>1][(j&1)*2], bhf[j>>1][(j&1)*2+1]);
            if (NT == 2){
#pragma unroll
                for (int im = 0; im < 2; im++)
#pragma unroll
                    for (int j = 0; j < 8; j++)
                        mma16816h(acc[im][j], al[im],
                                  bhf[j>>1][(j&1)*2], bhf[j>>1][(j&1)*2+1]);
            }
        }
        __syncthreads();
        if (s + DEPTH < NSTG2) GISSUE(s + DEPTH, s % DEPTH);
    }
#undef GISSUE

    if (EPI == 0){
        const float QSCALE = 0.125f * 1.44269504088896f;
        int bb4[2][2], n4[2][2];
#pragma unroll
        for (int im = 0; im < 2; im++)
#pragma unroll
            for (int rr = 0; rr < 2; rr++){
                const int m = m0 + wm*32 + im*16 + (lane>>2) + rr*8;
                const int bb = (m < Mn) ? (m / Nn) : 0;
                bb4[im][rr] = bb;
                n4[im][rr]  = m - bb*Nn;
            }
#pragma unroll
        for (int im = 0; im < 2; im++){
#pragma unroll
            for (int j = 0; j < 8; j++){
                const int cl = wn*64 + j*8 + (lane&3)*2;
                const int gc  = n0 + cl;
                const int sec = gc / Cn;
                const int rem = gc - sec*Cn;
                const int hh  = rem >> 6;
                const int d   = rem & 63;
#pragma unroll
                for (int rr = 0; rr < 2; rr++){
                    const int m = m0 + wm*32 + im*16 + (lane>>2) + rr*8;
                    if (m >= Mn) continue;
                    float v1 = acc[im][j][rr*2+0];
                    float v2 = acc[im][j][rr*2+1];
                    const int bb = bb4[im][rr];
                    const int n  = n4[im][rr];
                    if (sec < 2 && n > 0){
                        const float cs = cosb[(n-1)*(Dn/2) + (d>>1)];
                        const float sn = sinb[(n-1)*(Dn/2) + (d>>1)];
                        const float r1 = v1*cs - v2*sn;
                        const float r2 = v1*sn + v2*cs;
                        v1 = r1; v2 = r2;
                    }
                    if (sec == 0){ v1 *= QSCALE; v2 *= QSCALE; }
                    const size_t idx = ((size_t)(bb*Hn + hh)*Nn + n)*Dn + d;
                    if (sec == 0)      store_pairh(g_qh, g_ql, idx, v1, v2);
                    else if (sec == 1) *reinterpret_cast<uint32_t*>(g_k + idx) = packh(v1, v2);
                    else               *reinterpret_cast<uint32_t*>(g_v + idx) = packh(v1, v2);
                }
            }
        }
    } else {
        float* Ds = (float*)sm;
#pragma unroll
        for (int im = 0; im < 2; im++){
#pragma unroll
            for (int j = 0; j < 8; j++){
                const int cl = wn*64 + j*8 + (lane&3)*2;
#pragma unroll
                for (int rr = 0; rr < 2; rr++){
                    const int r = wm*32 + im*16 + (lane>>2) + rr*8;
                    float v1 = acc[im][j][rr*2+0];
                    float v2 = acc[im][j][rr*2+1];
                    const int gc = n0 + cl;
                    v1 += bias[gc]; v2 += bias[gc+1];
                    Ds[r*132 + cl]   = v1;
                    Ds[r*132 + cl+1] = v2;
                }
            }
        }
        __syncthreads();
        const int row  = tid >> 1;
        const int half = tid & 1;
        const int m = m0 + row;
        if (m < Mn){
            float* dst = Out + (size_t)m*Cn + n0 + half*64;
            const float* src = &Ds[row*132 + half*64];
#pragma unroll
            for (int j = 0; j < 64; j += 4)
                *(float4*)&dst[j] = *(const float4*)&src[j];
        }
    }
}

// ---------------------------------------------------------------------------
// HMMA flash attention (unchanged from round 13)
// ---------------------------------------------------------------------------
#define AT_PITCH 144
#define AT_TILE  (64*AT_PITCH)        // 9216
#define KV_STAGE (2*AT_TILE)          // 18432 : K | V
#define AT_SMEM  (36864 + 3*KV_STAGE) // 92160
#define NTkv ((Nn+63)/64)             // 10

__global__ __launch_bounds__(256,2) void attn_tc()
{
    extern __shared__ char sm[];
    const uint32_t smb = smem_u32(sm);
    const int tid  = threadIdx.x;
    const int wid  = tid >> 5;
    const int lane = tid & 31;
    const int qt   = blockIdx.x;
    const int bh   = blockIdx.y;
    const int bb   = bh / Hn;
    const int h    = bh - bb*Hn;

    const __half* Qh = g_qh + (size_t)bh*Nn*Dn;
    const __half* Ql = g_ql + (size_t)bh*Nn*Dn;
    const __half* Kp = g_k  + (size_t)bh*Nn*Dn;
    const __half* Vp = g_v  + (size_t)bh*Nn*Dn;

    {
#pragma unroll
        for (int i = 0; i < 4; i++){
            const int idx = tid + i*256;
            const int r   = idx >> 3;
            const int j   = idx & 7;
            const int gr  = qt*128 + r;
            uint4 vh = make_uint4(0,0,0,0), vl = vh;
            if (gr < Nn){
                vh = *(const uint4*)(Qh + (size_t)gr*Dn + j*8);
                vl = *(const uint4*)(Ql + (size_t)gr*Dn + j*8);
            }
            *(uint4*)(sm + r*AT_PITCH + j*16)         = vh;
            *(uint4*)(sm + 18432 + r*AT_PITCH + j*16) = vl;
        }
    }

#define ISSUE_KV(t_, buf_) do{ \
    const int kv0 = (t_)*64; \
    const uint32_t bp = smb + 36864u + (uint32_t)(buf_)*KV_STAGE; \
    _Pragma("unroll") \
    for (int i_ = 0; i_ < 4; i_++){ \
        const int idx = tid + i_*256; \
        const int ts  = idx >> 9; \
        const int rem = idx & 511; \
        const int r_  = rem >> 3; \
        const int j_  = rem & 7; \
        const int gr  = kv0 + r_; \
        const __half* src = ts ? Vp : Kp; \
        const uint32_t n_ = (gr < Nn) ? 16u : 0u; \
        cpa(bp + (uint32_t)ts*AT_TILE + (uint32_t)(r_*AT_PITCH + j_*16), \
            src + (size_t)gr*Dn + j_*8, n_); \
    } \
    asm volatile("cp.async.commit_group;":::"memory"); \
}while(0)

    ISSUE_KV(0, 0);
    ISSUE_KV(1, 1);

    __syncthreads();
    uint32_t qfh[4][4], qfl[4][4];
    {
        const uint32_t qa = smb + (uint32_t)((wid*16 + (lane&15))*AT_PITCH + (lane>>4)*16);
#pragma unroll
        for (int kk = 0; kk < 4; kk++){
            ldsm4(qfh[kk], qa + kk*32);
            ldsm4(qfl[kk], qa + 18432 + kk*32);
        }
    }

    float m0r = -1e30f, m1r = -1e30f, l0r = 0.f, l1r = 0.f;
    float o[8][4];
#pragma unroll
    for (int j=0;j<8;j++)
#pragma unroll
        for (int q=0;q<4;q++) o[j][q] = 0.f;

    int buf = 0;
    for (int t = 0; t < NTkv; t++){
        if (t < NTkv-1) asm volatile("cp.async.wait_group 1;":::"memory");
        else            asm volatile("cp.async.wait_group 0;":::"memory");
        __syncthreads();

        const uint32_t sb = smb + 36864u + (uint32_t)buf*KV_STAGE;

        float s[8][4];
#pragma unroll
        for (int j=0;j<8;j++)
#pragma unroll
            for (int q=0;q<4;q++) s[j][q] = 0.f;

#pragma unroll
        for (int kk = 0; kk < 4; kk++){
            uint32_t kh[4][4];
#pragma unroll
            for (int g = 0; g < 4; g++){
                const uint32_t ka = sb
                    + (uint32_t)((g*16 + (lane&7) + ((lane>>4)<<3))*AT_PITCH
                                 + ((lane>>3)&1)*16 + kk*32);
                ldsm4(kh[g], ka);
            }
#pragma unroll
            for (int j = 0; j < 8; j++)
                mma16816h(s[j], qfh[kk], kh[j>>1][(j&1)*2], kh[j>>1][(j&1)*2+1]);
#pragma unroll
            for (int j = 0; j < 8; j++)
                mma16816h(s[j], qfl[kk], kh[j>>1][(j&1)*2], kh[j>>1][(j&1)*2+1]);
        }

        if (t == NTkv-1){
#pragma unroll
            for (int j = 0; j < 8; j++){
                const int c0 = t*64 + j*8 + (lane&3)*2;
                if (c0   >= Nn){ s[j][0] = -1e30f; s[j][2] = -1e30f; }
                if (c0+1 >= Nn){ s[j][1] = -1e30f; s[j][3] = -1e30f; }
            }
        }
        float mx0 = -1e30f, mx1 = -1e30f;
#pragma unroll
        for (int j = 0; j < 8; j++){
            mx0 = fmaxf(mx0, fmaxf(s[j][0], s[j][1]));
            mx1 = fmaxf(mx1, fmaxf(s[j][2], s[j][3]));
        }
        mx0 = fmaxf(mx0, __shfl_xor_sync(0xffffffffu, mx0, 1));
        mx0 = fmaxf(mx0, __shfl_xor_sync(0xffffffffu, mx0, 2));
        mx1 = fmaxf(mx1, __shfl_xor_sync(0xffffffffu, mx1, 1));
        mx1 = fmaxf(mx1, __shfl_xor_sync(0xffffffffu, mx1, 2));
        const float mn0 = fmaxf(m0r, mx0), mn1 = fmaxf(m1r, mx1);
        const float al0 = exp2f(m0r - mn0), al1 = exp2f(m1r - mn1);
        float rs0 = 0.f, rs1 = 0.f;
#pragma unroll
        for (int j = 0; j < 8; j++){
            s[j][0] = exp2f(s[j][0]-mn0); s[j][1] = exp2f(s[j][1]-mn0);
            s[j][2] = exp2f(s[j][2]-mn1); s[j][3] = exp2f(s[j][3]-mn1);
            rs0 += s[j][0] + s[j][1];
            rs1 += s[j][2] + s[j][3];
        }
        rs0 += __shfl_xor_sync(0xffffffffu, rs0, 1);
        rs0 += __shfl_xor_sync(0xffffffffu, rs0, 2);
        rs1 += __shfl_xor_sync(0xffffffffu, rs1, 1);
        rs1 += __shfl_xor_sync(0xffffffffu, rs1, 2);
        l0r = l0r*al0 + rs0;  m0r = mn0;
        l1r = l1r*al1 + rs1;  m1r = mn1;
#pragma unroll
        for (int j = 0; j < 8; j++){
            o[j][0] *= al0; o[j][1] *= al0;
            o[j][2] *= al1; o[j][3] *= al1;
        }

#pragma unroll
        for (int kk = 0; kk < 4; kk++){
            uint32_t pha[4];
            {
                const int j0 = 2*kk, j1 = 2*kk+1;
                pha[0] = packh(s[j0][0], s[j0][1]);
                pha[1] = packh(s[j0][2], s[j0][3]);
                pha[2] = packh(s[j1][0], s[j1][1]);
                pha[3] = packh(s[j1][2], s[j1][3]);
            }
            uint32_t vh[4][4];
#pragma unroll
            for (int g = 0; g < 4; g++){
                const uint32_t va = sb + AT_TILE
                    + (uint32_t)((kk*16 + (lane&7) + ((lane>>3)&1)*8)*AT_PITCH
                                 + ((lane>>4)*8 + g*16)*2);
                ldsm4t(vh[g], va);
            }
#pragma unroll
            for (int j = 0; j < 8; j++)
                mma16816h(o[j], pha, vh[j>>1][(j&1)*2], vh[j>>1][(j&1)*2+1]);
        }

        if (t+2 < NTkv){
            const int nb = (t+2) % 3;
            ISSUE_KV(t+2, nb);
        }
        buf = (buf + 1 == 3) ? 0 : buf + 1;
    }
#undef ISSUE_KV

    const float inv0 = 1.f / l0r, inv1 = 1.f / l1r;
    const int r0 = qt*128 + wid*16 + (lane>>2);
    const int r1 = r0 + 8;
#pragma unroll
    for (int j = 0; j < 8; j++){
        const int col = h*Dn + j*8 + (lane&3)*2;
        if (r0 < Nn)
            store_pairh(g_aoh, g_aol, (size_t)(bb*Nn + r0)*Cn + col,
                        o[j][0]*inv0, o[j][1]*inv0);
        if (r1 < Nn)
            store_pairh(g_aoh, g_aol, (size_t)(bb*Nn + r1)*Cn + col,
                        o[j][2]*inv1, o[j][3]*inv1);
    }
}

// ---------------------------------------------------------------------------
extern "C" void kernel_launch(void* const* d_in, const int* in_sizes, int n_in,
                              void* d_out, int out_size)
{
    (void)in_sizes; (void)n_in; (void)out_size;
    const float* x      = (const float*)d_in[0];
    const float* w_qkv  = (const float*)d_in[1];
    const float* w_proj = (const float*)d_in[2];
    const float* b_proj = (const float*)d_in[3];
    const float* cosb   = (const float*)d_in[4];
    const float* sinb   = (const float*)d_in[5];
    float* out = (float*)d_out;

    cudaFuncSetAttribute((const void*)gemm_h2<0,1>,
                         cudaFuncAttributeMaxDynamicSharedMemorySize, SMEM_GM);
    cudaFuncSetAttribute((const void*)gemm_h2<1,2>,
                         cudaFuncAttributeMaxDynamicSharedMemorySize, SMEM_GM);
    cudaFuncSetAttribute(attn_tc, cudaFuncAttributeMaxDynamicSharedMemorySize, AT_SMEM);

    __half *xh, *wq, *wp, *aoh, *aol;
    cudaGetSymbolAddress((void**)&xh,  g_xh);
    cudaGetSymbolAddress((void**)&wq,  g_wq);  cudaGetSymbolAddress((void**)&wp,  g_wp);
    cudaGetSymbolAddress((void**)&aoh, g_aoh); cudaGetSymbolAddress((void**)&aol, g_aol);

    conv_all<<<NBX + NBQ + NBP, 256>>>(x, w_qkv, w_proj, xh, wq, wp);

    const int MT = (Mn + 127) / 128;   // 145
    gemm_h2<0,1><<<dim3(QKV_N/128, MT), 256, SMEM_GM>>>(xh, nullptr, wq,
                                                        cosb, sinb, nullptr, nullptr);
    attn_tc<<<dim3((Nn+127)/128, Bn*Hn), 256, AT_SMEM>>>();
    gemm_h2<1,2><<<dim3(Cn/128, MT), 256, SMEM_GM>>>(aoh, aol, wp,
                                                     nullptr, nullptr, b_proj, out);
}

// round 15
// speedup vs baseline: 3.1068x; 1.1096x over previous
#include <cuda_runtime.h>
#include <cuda_bf16.h>
#include <cuda_fp16.h>
#include <cstdint>

#define Bn 32
#define Nn 577
#define Cn 768
#define Hn 12
#define Dn 64
#define Mn (Bn*Nn)          // 18464
#define QKV_N (3*Cn)        // 2304
#define BHD ((size_t)Bn*Hn*Nn*Dn)   // 14,180,352

// Scratch (__device__ globals)
__device__ __align__(16) __half g_xh[(size_t)Mn*Cn];                         // x fp16
__device__ __align__(16) __half g_wq[(size_t)QKV_N*Cn];                      // w_qkv fp16
__device__ __align__(16) __half g_wp[(size_t)Cn*Cn];                         // w_proj fp16
__device__ __align__(16) __half g_qh[BHD], g_ql[BHD];                        // Q fp16 hi/lo
__device__ __align__(16) __half g_k[BHD], g_v[BHD];                          // K,V fp16
__device__ __align__(16) __half g_aoh[(size_t)Mn*Cn];                        // AO fp16

// ---------------------------------------------------------------------------
// helpers
// ---------------------------------------------------------------------------
__device__ __forceinline__ uint32_t smem_u32(const void* p){
    uint32_t a;
    asm("{ .reg .u64 t; cvta.to.shared.u64 t, %1; cvt.u32.u64 %0, t; }"
        : "=r"(a) : "l"(p));
    return a;
}
__device__ __forceinline__ void ldsm4(uint32_t (&r)[4], uint32_t a){
    asm volatile("ldmatrix.sync.aligned.m8n8.x4.shared.b16 {%0,%1,%2,%3}, [%4];"
        : "=r"(r[0]),"=r"(r[1]),"=r"(r[2]),"=r"(r[3]) : "r"(a));
}
__device__ __forceinline__ void ldsm4t(uint32_t (&r)[4], uint32_t a){
    asm volatile("ldmatrix.sync.aligned.m8n8.x4.trans.shared.b16 {%0,%1,%2,%3}, [%4];"
        : "=r"(r[0]),"=r"(r[1]),"=r"(r[2]),"=r"(r[3]) : "r"(a));
}
__device__ __forceinline__ void mma16816h(float* c, const uint32_t* a,
                                          uint32_t b0, uint32_t b1){
    asm volatile("mma.sync.aligned.m16n8k16.row.col.f32.f16.f16.f32 "
        "{%0,%1,%2,%3}, {%4,%5,%6,%7}, {%8,%9}, {%0,%1,%2,%3};"
        : "+f"(c[0]),"+f"(c[1]),"+f"(c[2]),"+f"(c[3])
        : "r"(a[0]),"r"(a[1]),"r"(a[2]),"r"(a[3]), "r"(b0),"r"(b1));
}
__device__ __forceinline__ void cpa(uint32_t s, const void* g, uint32_t n){
    asm volatile("cp.async.cg.shared.global [%0], [%1], 16, %2;"
                 :: "r"(s), "l"(g), "r"(n) : "memory");
}
__device__ __forceinline__ uint32_t packh(float x, float y){
    __half2 t = __floats2half2_rn(x, y);
    return *reinterpret_cast<uint32_t*>(&t);
}
__device__ __forceinline__ void store_pairh(__half* dh, __half* dl,
                                            size_t idx, float v1, float v2){
    const __half h1 = __float2half_rn(v1), h2 = __float2half_rn(v2);
    uint32_t hp; { __half2 t; t.x=h1; t.y=h2; hp=*reinterpret_cast<uint32_t*>(&t); }
    *reinterpret_cast<uint32_t*>(dh + idx) = hp;
    *reinterpret_cast<uint32_t*>(dl + idx) =
        packh(v1 - __half2float(h1), v2 - __half2float(h2));
}

// ---------------------------------------------------------------------------
// merged conversion kernel: x, w_qkv, w_proj -> fp16
// ---------------------------------------------------------------------------
#define NBX ((Mn*Cn)/1024)        // 13848
#define NBQ ((QKV_N*Cn)/1024)     // 1728
#define NBP ((Cn*Cn)/1024)        // 576

__global__ __launch_bounds__(256) void conv_all(
    const float* __restrict__ x, const float* __restrict__ wq,
    const float* __restrict__ wp,
    __half* __restrict__ xh,
    __half* __restrict__ wqd, __half* __restrict__ wpd)
{
    const int b = blockIdx.x;
    const int t4 = threadIdx.x * 4;
    const float* src; __half* dst; int i;
    if (b < NBX){       src = x;  dst = xh;  i = b*1024 + t4; }
    else if (b < NBX+NBQ){ src = wq; dst = wqd; i = (b-NBX)*1024 + t4; }
    else {              src = wp; dst = wpd; i = (b-NBX-NBQ)*1024 + t4; }
    float4 v = *(const float4*)(src + i);
    *(uint2*)(dst + i) = make_uint2(packh(v.x, v.y), packh(v.z, v.w));
}

// ---------------------------------------------------------------------------
// fp16 GEMM template: NT A-terms (1 or 2) x single-fp16 B.
// NT==1: 2 tiles/stage (32KB), 3-deep pipe.  NT==2: 3 tiles/stage, 2-deep.
// EPI==0: RoPE + q-scale(incl. log2e) -> fp16 q hi/lo, k/v single, [B,H,N,D]
// EPI==1: +bias -> fp32 Out
// ---------------------------------------------------------------------------
#define KS2 64
#define NSTG2 (Cn/KS2)        // 12
#define TILE16K 16384
#define SMEM_GM 98304         // 96KB -> 2 CTAs/SM

#define SWZ128(row_, grp_) ((uint32_t)(row_)*128u + ((((uint32_t)(grp_)) ^ ((uint32_t)(row_)&7u))<<4))

template<int EPI, int NT>
__global__ __launch_bounds__(256,2) void gemm_h2(
    const __half* __restrict__ Ah, const __half* __restrict__ Al,
    const __half* __restrict__ Bh,
    const float* __restrict__ cosb, const float* __restrict__ sinb,
    const float* __restrict__ bias, float* __restrict__ Out)
{
    extern __shared__ char sm[];
    const uint32_t smb = smem_u32(sm);
    constexpr int STG_B  = (NT+1)*TILE16K;     // 32KB or 48KB
    constexpr int DEPTH  = (NT==1) ? 3 : 2;
    constexpr uint32_t BOFF = (uint32_t)NT*TILE16K;

    const int tid  = threadIdx.x;
    const int wid  = tid >> 5;
    const int lane = tid & 31;
    const int m0 = blockIdx.y * 128;
    const int n0 = blockIdx.x * 128;
    const int wm = wid & 3;
    const int wn = wid >> 2;

    float acc[2][8][4];
#pragma unroll
    for (int im=0;im<2;im++)
#pragma unroll
        for (int j=0;j<8;j++)
#pragma unroll
            for (int q=0;q<4;q++) acc[im][j][q] = 0.f;

#define GISSUE(s_, b_) do{ \
    const uint32_t bb_ = smb + (uint32_t)(b_)*STG_B; \
    const int kt_ = (s_)*KS2; \
    _Pragma("unroll") \
    for (int r_ = 0; r_ < 4; r_++){ \
        const int idx_ = tid + r_*256; \
        const uint32_t row_ = (uint32_t)(idx_ >> 3); \
        const uint32_t grp_ = (uint32_t)(idx_ & 7); \
        const uint32_t dst_ = bb_ + SWZ128(row_, grp_); \
        const uint32_t an_  = ((int)(m0 + row_) < Mn) ? 16u : 0u; \
        const size_t aoff_ = (size_t)(m0 + row_)*Cn + kt_ + grp_*8; \
        const size_t boff_ = (size_t)(n0 + row_)*Cn + kt_ + grp_*8; \
        cpa(dst_, Ah + aoff_, an_); \
        if (NT == 2) cpa(dst_ + TILE16K, Al + aoff_, an_); \
        cpa(dst_ + BOFF, Bh + boff_, 16u); \
    } \
    asm volatile("cp.async.commit_group;":::"memory"); \
}while(0)

    GISSUE(0, 0);
    GISSUE(1, 1);
    if (DEPTH == 3) GISSUE(2, 2);

    const uint32_t ar0 = (uint32_t)(wm*32 + (lane & 15));
    const uint32_t ar1 = ar0 + 16;
    const uint32_t brb = (uint32_t)(wn*64 + (lane & 7) + ((lane >> 4) << 3));

    for (int s = 0; s < NSTG2; s++){
        if (s + 2 < NSTG2 && DEPTH == 3)
            asm volatile("cp.async.wait_group 2;":::"memory");
        else if (s + 1 < NSTG2)
            asm volatile("cp.async.wait_group 1;":::"memory");
        else
            asm volatile("cp.async.wait_group 0;":::"memory");
        __syncthreads();

        const uint32_t sb = smb + (uint32_t)(s % DEPTH)*STG_B;
#pragma unroll
        for (int kk = 0; kk < 4; kk++){
            const uint32_t gA = (uint32_t)(kk*2 + (lane >> 4));
            const uint32_t gB = (uint32_t)(kk*2 + ((lane >> 3) & 1));
            uint32_t ah[2][4], al[2][4], bhf[4][4];
            ldsm4(ah[0], sb + SWZ128(ar0, gA));
            ldsm4(ah[1], sb + SWZ128(ar1, gA));
            if (NT == 2){
                ldsm4(al[0], sb + TILE16K + SWZ128(ar0, gA));
                ldsm4(al[1], sb + TILE16K + SWZ128(ar1, gA));
            }
#pragma unroll
            for (int t2 = 0; t2 < 4; t2++){
                const uint32_t br = brb + (uint32_t)(t2*16);
                ldsm4(bhf[t2], sb + BOFF + SWZ128(br, gB));
            }
#pragma unroll
            for (int im = 0; im < 2; im++)
#pragma unroll
                for (int j = 0; j < 8; j++)
                    mma16816h(acc[im][j], ah[im],
                              bhf[j>>1][(j&1)*2], bhf[j>>1][(j&1)*2+1]);
            if (NT == 2){
#pragma unroll
                for (int im = 0; im < 2; im++)
#pragma unroll
                    for (int j = 0; j < 8; j++)
                        mma16816h(acc[im][j], al[im],
                                  bhf[j>>1][(j&1)*2], bhf[j>>1][(j&1)*2+1]);
            }
        }
        __syncthreads();
        if (s + DEPTH < NSTG2) GISSUE(s + DEPTH, s % DEPTH);
    }
#undef GISSUE

    if (EPI == 0){
        const float QSCALE = 0.125f * 1.44269504088896f;
        int bb4[2][2], n4[2][2];
#pragma unroll
        for (int im = 0; im < 2; im++)
#pragma unroll
            for (int rr = 0; rr < 2; rr++){
                const int m = m0 + wm*32 + im*16 + (lane>>2) + rr*8;
                const int bb = (m < Mn) ? (m / Nn) : 0;
                bb4[im][rr] = bb;
                n4[im][rr]  = m - bb*Nn;
            }
#pragma unroll
        for (int im = 0; im < 2; im++){
#pragma unroll
            for (int j = 0; j < 8; j++){
                const int cl = wn*64 + j*8 + (lane&3)*2;
                const int gc  = n0 + cl;
                const int sec = gc / Cn;
                const int rem = gc - sec*Cn;
                const int hh  = rem >> 6;
                const int d   = rem & 63;
#pragma unroll
                for (int rr = 0; rr < 2; rr++){
                    const int m = m0 + wm*32 + im*16 + (lane>>2) + rr*8;
                    if (m >= Mn) continue;
                    float v1 = acc[im][j][rr*2+0];
                    float v2 = acc[im][j][rr*2+1];
                    const int bb = bb4[im][rr];
                    const int n  = n4[im][rr];
                    if (sec < 2 && n > 0){
                        const float cs = cosb[(n-1)*(Dn/2) + (d>>1)];
                        const float sn = sinb[(n-1)*(Dn/2) + (d>>1)];
                        const float r1 = v1*cs - v2*sn;
                        const float r2 = v1*sn + v2*cs;
                        v1 = r1; v2 = r2;
                    }
                    if (sec == 0){ v1 *= QSCALE; v2 *= QSCALE; }
                    const size_t idx = ((size_t)(bb*Hn + hh)*Nn + n)*Dn + d;
                    if (sec == 0)      store_pairh(g_qh, g_ql, idx, v1, v2);
                    else if (sec == 1) *reinterpret_cast<uint32_t*>(g_k + idx) = packh(v1, v2);
                    else               *reinterpret_cast<uint32_t*>(g_v + idx) = packh(v1, v2);
                }
            }
        }
    } else {
        float* Ds = (float*)sm;
#pragma unroll
        for (int im = 0; im < 2; im++){
#pragma unroll
            for (int j = 0; j < 8; j++){
                const int cl = wn*64 + j*8 + (lane&3)*2;
#pragma unroll
                for (int rr = 0; rr < 2; rr++){
                    const int r = wm*32 + im*16 + (lane>>2) + rr*8;
                    float v1 = acc[im][j][rr*2+0];
                    float v2 = acc[im][j][rr*2+1];
                    const int gc = n0 + cl;
                    v1 += bias[gc]; v2 += bias[gc+1];
                    Ds[r*132 + cl]   = v1;
                    Ds[r*132 + cl+1] = v2;
                }
            }
        }
        __syncthreads();
        const int row  = tid >> 1;
        const int half = tid & 1;
        const int m = m0 + row;
        if (m < Mn){
            float* dst = Out + (size_t)m*Cn + n0 + half*64;
            const float* src = &Ds[row*132 + half*64];
#pragma unroll
            for (int j = 0; j < 64; j += 4)
                *(float4*)&dst[j] = *(const float4*)&src[j];
        }
    }
}

// ---------------------------------------------------------------------------
// HMMA flash attention (AO stored single fp16; otherwise unchanged from R14)
// ---------------------------------------------------------------------------
#define AT_PITCH 144
#define AT_TILE  (64*AT_PITCH)        // 9216
#define KV_STAGE (2*AT_TILE)          // 18432 : K | V
#define AT_SMEM  (36864 + 3*KV_STAGE) // 92160
#define NTkv ((Nn+63)/64)             // 10

__global__ __launch_bounds__(256,2) void attn_tc()
{
    extern __shared__ char sm[];
    const uint32_t smb = smem_u32(sm);
    const int tid  = threadIdx.x;
    const int wid  = tid >> 5;
    const int lane = tid & 31;
    const int qt   = blockIdx.x;
    const int bh   = blockIdx.y;
    const int bb   = bh / Hn;
    const int h    = bh - bb*Hn;

    const __half* Qh = g_qh + (size_t)bh*Nn*Dn;
    const __half* Ql = g_ql + (size_t)bh*Nn*Dn;
    const __half* Kp = g_k  + (size_t)bh*Nn*Dn;
    const __half* Vp = g_v  + (size_t)bh*Nn*Dn;

    {
#pragma unroll
        for (int i = 0; i < 4; i++){
            const int idx = tid + i*256;
            const int r   = idx >> 3;
            const int j   = idx & 7;
            const int gr  = qt*128 + r;
            uint4 vh = make_uint4(0,0,0,0), vl = vh;
            if (gr < Nn){
                vh = *(const uint4*)(Qh + (size_t)gr*Dn + j*8);
                vl = *(const uint4*)(Ql + (size_t)gr*Dn + j*8);
            }
            *(uint4*)(sm + r*AT_PITCH + j*16)         = vh;
            *(uint4*)(sm + 18432 + r*AT_PITCH + j*16) = vl;
        }
    }

#define ISSUE_KV(t_, buf_) do{ \
    const int kv0 = (t_)*64; \
    const uint32_t bp = smb + 36864u + (uint32_t)(buf_)*KV_STAGE; \
    _Pragma("unroll") \
    for (int i_ = 0; i_ < 4; i_++){ \
        const int idx = tid + i_*256; \
        const int ts  = idx >> 9; \
        const int rem = idx & 511; \
        const int r_  = rem >> 3; \
        const int j_  = rem & 7; \
        const int gr  = kv0 + r_; \
        const __half* src = ts ? Vp : Kp; \
        const uint32_t n_ = (gr < Nn) ? 16u : 0u; \
        cpa(bp + (uint32_t)ts*AT_TILE + (uint32_t)(r_*AT_PITCH + j_*16), \
            src + (size_t)gr*Dn + j_*8, n_); \
    } \
    asm volatile("cp.async.commit_group;":::"memory"); \
}while(0)

    ISSUE_KV(0, 0);
    ISSUE_KV(1, 1);

    __syncthreads();
    uint32_t qfh[4][4], qfl[4][4];
    {
        const uint32_t qa = smb + (uint32_t)((wid*16 + (lane&15))*AT_PITCH + (lane>>4)*16);
#pragma unroll
        for (int kk = 0; kk < 4; kk++){
            ldsm4(qfh[kk], qa + kk*32);
            ldsm4(qfl[kk], qa + 18432 + kk*32);
        }
    }

    float m0r = -1e30f, m1r = -1e30f, l0r = 0.f, l1r = 0.f;
    float o[8][4];
#pragma unroll
    for (int j=0;j<8;j++)
#pragma unroll
        for (int q=0;q<4;q++) o[j][q] = 0.f;

    int buf = 0;
    for (int t = 0; t < NTkv; t++){
        if (t < NTkv-1) asm volatile("cp.async.wait_group 1;":::"memory");
        else            asm volatile("cp.async.wait_group 0;":::"memory");
        __syncthreads();

        const uint32_t sb = smb + 36864u + (uint32_t)buf*KV_STAGE;

        float s[8][4];
#pragma unroll
        for (int j=0;j<8;j++)
#pragma unroll
            for (int q=0;q<4;q++) s[j][q] = 0.f;

#pragma unroll
        for (int kk = 0; kk < 4; kk++){
            uint32_t kh[4][4];
#pragma unroll
            for (int g = 0; g < 4; g++){
                const uint32_t ka = sb
                    + (uint32_t)((g*16 + (lane&7) + ((lane>>4)<<3))*AT_PITCH
                                 + ((lane>>3)&1)*16 + kk*32);
                ldsm4(kh[g], ka);
            }
#pragma unroll
            for (int j = 0; j < 8; j++)
                mma16816h(s[j], qfh[kk], kh[j>>1][(j&1)*2], kh[j>>1][(j&1)*2+1]);
#pragma unroll
            for (int j = 0; j < 8; j++)
                mma16816h(s[j], qfl[kk], kh[j>>1][(j&1)*2], kh[j>>1][(j&1)*2+1]);
        }

        if (t == NTkv-1){
#pragma unroll
            for (int j = 0; j < 8; j++){
                const int c0 = t*64 + j*8 + (lane&3)*2;
                if (c0   >= Nn){ s[j][0] = -1e30f; s[j][2] = -1e30f; }
                if (c0+1 >= Nn){ s[j][1] = -1e30f; s[j][3] = -1e30f; }
            }
        }
        float mx0 = -1e30f, mx1 = -1e30f;
#pragma unroll
        for (int j = 0; j < 8; j++){
            mx0 = fmaxf(mx0, fmaxf(s[j][0], s[j][1]));
            mx1 = fmaxf(mx1, fmaxf(s[j][2], s[j][3]));
        }
        mx0 = fmaxf(mx0, __shfl_xor_sync(0xffffffffu, mx0, 1));
        mx0 = fmaxf(mx0, __shfl_xor_sync(0xffffffffu, mx0, 2));
        mx1 = fmaxf(mx1, __shfl_xor_sync(0xffffffffu, mx1, 1));
        mx1 = fmaxf(mx1, __shfl_xor_sync(0xffffffffu, mx1, 2));
        const float mn0 = fmaxf(m0r, mx0), mn1 = fmaxf(m1r, mx1);
        const float al0 = exp2f(m0r - mn0), al1 = exp2f(m1r - mn1);
        float rs0 = 0.f, rs1 = 0.f;
#pragma unroll
        for (int j = 0; j < 8; j++){
            s[j][0] = exp2f(s[j][0]-mn0); s[j][1] = exp2f(s[j][1]-mn0);
            s[j][2] = exp2f(s[j][2]-mn1); s[j][3] = exp2f(s[j][3]-mn1);
            rs0 += s[j][0] + s[j][1];
            rs1 += s[j][2] + s[j][3];
        }
        rs0 += __shfl_xor_sync(0xffffffffu, rs0, 1);
        rs0 += __shfl_xor_sync(0xffffffffu, rs0, 2);
        rs1 += __shfl_xor_sync(0xffffffffu, rs1, 1);
        rs1 += __shfl_xor_sync(0xffffffffu, rs1, 2);
        l0r = l0r*al0 + rs0;  m0r = mn0;
        l1r = l1r*al1 + rs1;  m1r = mn1;
#pragma unroll
        for (int j = 0; j < 8; j++){
            o[j][0] *= al0; o[j][1] *= al0;
            o[j][2] *= al1; o[j][3] *= al1;
        }

#pragma unroll
        for (int kk = 0; kk < 4; kk++){
            uint32_t pha[4];
            {
                const int j0 = 2*kk, j1 = 2*kk+1;
                pha[0] = packh(s[j0][0], s[j0][1]);
                pha[1] = packh(s[j0][2], s[j0][3]);
                pha[2] = packh(s[j1][0], s[j1][1]);
                pha[3] = packh(s[j1][2], s[j1][3]);
            }
            uint32_t vh[4][4];
#pragma unroll
            for (int g = 0; g < 4; g++){
                const uint32_t va = sb + AT_TILE
                    + (uint32_t)((kk*16 + (lane&7) + ((lane>>3)&1)*8)*AT_PITCH
                                 + ((lane>>4)*8 + g*16)*2);
                ldsm4t(vh[g], va);
            }
#pragma unroll
            for (int j = 0; j < 8; j++)
                mma16816h(o[j], pha, vh[j>>1][(j&1)*2], vh[j>>1][(j&1)*2+1]);
        }

        if (t+2 < NTkv){
            const int nb = (t+2) % 3;
            ISSUE_KV(t+2, nb);
        }
        buf = (buf + 1 == 3) ? 0 : buf + 1;
    }
#undef ISSUE_KV

    // ---- normalize + store AO single fp16 ([B*N, C] at col h*64+d)
    const float inv0 = 1.f / l0r, inv1 = 1.f / l1r;
    const int r0 = qt*128 + wid*16 + (lane>>2);
    const int r1 = r0 + 8;
#pragma unroll
    for (int j = 0; j < 8; j++){
        const int col = h*Dn + j*8 + (lane&3)*2;
        if (r0 < Nn)
            *reinterpret_cast<uint32_t*>(g_aoh + (size_t)(bb*Nn + r0)*Cn + col)
                = packh(o[j][0]*inv0, o[j][1]*inv0);
        if (r1 < Nn)
            *reinterpret_cast<uint32_t*>(g_aoh + (size_t)(bb*Nn + r1)*Cn + col)
                = packh(o[j][2]*inv1, o[j][3]*inv1);
    }
}

// ---------------------------------------------------------------------------
extern "C" void kernel_launch(void* const* d_in, const int* in_sizes, int n_in,
                              void* d_out, int out_size)
{
    (void)in_sizes; (void)n_in; (void)out_size;
    const float* x      = (const float*)d_in[0];
    const float* w_qkv  = (const float*)d_in[1];
    const float* w_proj = (const float*)d_in[2];
    const float* b_proj = (const float*)d_in[3];
    const float* cosb   = (const float*)d_in[4];
    const float* sinb   = (const float*)d_in[5];
    float* out = (float*)d_out;

    cudaFuncSetAttribute((const void*)gemm_h2<0,1>,
                         cudaFuncAttributeMaxDynamicSharedMemorySize, SMEM_GM);
    cudaFuncSetAttribute((const void*)gemm_h2<1,1>,
                         cudaFuncAttributeMaxDynamicSharedMemorySize, SMEM_GM);
    cudaFuncSetAttribute(attn_tc, cudaFuncAttributeMaxDynamicSharedMemorySize, AT_SMEM);

    __half *xh, *wq, *wp, *aoh;
    cudaGetSymbolAddress((void**)&xh,  g_xh);
    cudaGetSymbolAddress((void**)&wq,  g_wq);  cudaGetSymbolAddress((void**)&wp,  g_wp);
    cudaGetSymbolAddress((void**)&aoh, g_aoh);

    conv_all<<<NBX + NBQ + NBP, 256>>>(x, w_qkv, w_proj, xh, wq, wp);

    const int MT = (Mn + 127) / 128;   // 145
    gemm_h2<0,1><<<dim3(QKV_N/128, MT), 256, SMEM_GM>>>(xh, nullptr, wq,
                                                        cosb, sinb, nullptr, nullptr);
    attn_tc<<<dim3((Nn+127)/128, Bn*Hn), 256, AT_SMEM>>>();
    gemm_h2<1,1><<<dim3(Cn/128, MT), 256, SMEM_GM>>>(aoh, nullptr, wp,
                                                     nullptr, nullptr, b_proj, out);
}